// round 1
// baseline (speedup 1.0000x reference)
#include <cuda_runtime.h>
#include <math.h>

#define EPS 1e-5f
#define QK_SCALE 0.17677669529663687f   // 32^-0.5

// dynamic position bias table, written by dpb_kernel, read by attn_kernel
__device__ float g_table[289];

// -------------------------------------------------------------------------
// DPB MLP: 289 relative positions -> scalar bias table
// grid: 289 blocks x 64 threads (one block per grid row, one thread per feature)
// -------------------------------------------------------------------------
__device__ __forceinline__ float blockreduce64(float v, float* red) {
    #pragma unroll
    for (int o = 16; o > 0; o >>= 1) v += __shfl_xor_sync(0xffffffffu, v, o);
    int t = threadIdx.x;
    if ((t & 31) == 0) red[t >> 5] = v;
    __syncthreads();
    float r = red[0] + red[1];
    __syncthreads();
    return r;
}

__global__ void dpb_kernel(
    const float* __restrict__ w1, const float* __restrict__ b1,
    const float* __restrict__ g1, const float* __restrict__ bb1,
    const float* __restrict__ w2, const float* __restrict__ b2,
    const float* __restrict__ g2, const float* __restrict__ bb2,
    const float* __restrict__ w3, const float* __restrict__ b3,
    const float* __restrict__ g3, const float* __restrict__ bb3,
    const float* __restrict__ w4, const float* __restrict__ b4)
{
    __shared__ float hs[64];
    __shared__ float red[2];
    int r = blockIdx.x, j = threadIdx.x;
    float r0 = (float)(r / 17 - 8);
    float r1 = (float)(r % 17 - 8);

    // layer 1: rel(2) @ w1(2,64) + b1 -> LN -> relu
    float v = r0 * w1[j] + r1 * w1[64 + j] + b1[j];
    float m = blockreduce64(v, red) * (1.f / 64.f);
    float d = v - m;
    float var = blockreduce64(d * d, red) * (1.f / 64.f);
    v = fmaxf(d * rsqrtf(var + EPS) * g1[j] + bb1[j], 0.f);
    hs[j] = v;
    __syncthreads();

    // layer 2
    float a = b2[j];
    #pragma unroll 8
    for (int k = 0; k < 64; k++) a += hs[k] * w2[k * 64 + j];
    m = blockreduce64(a, red) * (1.f / 64.f);
    d = a - m;
    var = blockreduce64(d * d, red) * (1.f / 64.f);
    a = fmaxf(d * rsqrtf(var + EPS) * g2[j] + bb2[j], 0.f);
    hs[j] = a;
    __syncthreads();

    // layer 3
    a = b3[j];
    #pragma unroll 8
    for (int k = 0; k < 64; k++) a += hs[k] * w3[k * 64 + j];
    m = blockreduce64(a, red) * (1.f / 64.f);
    d = a - m;
    var = blockreduce64(d * d, red) * (1.f / 64.f);
    a = fmaxf(d * rsqrtf(var + EPS) * g3[j] + bb3[j], 0.f);
    hs[j] = a;
    __syncthreads();

    // layer 4: (64) @ w4(64,1) + b4
    float c = blockreduce64(hs[j] * w4[j], red);
    if (j == 0) g_table[r] = c + b4[0];
}

// -------------------------------------------------------------------------
// Fused window kernel: one CTA per 8x8 window.
// LN (channel-wise per pixel) -> QKV (per head) -> attention+bias+softmax
// -> AV -> output projection -> scatter to (B, D, H, W).
// SMEM layout (floats):
//   xs   [0     .. 16383]  x window, [d][pix], normalized in place
//   att  [16384 .. 32767]  attention output [inner_ch][pix]
//   work [32768 .. 43071]  (10304 floats) multi-use:
//        wt  [0..3103]   staged w_qkv tile [dd][96] (pitch 97)
//        sim [0..4159]   attention matrix [64][65]
//        red [0..511]    LN stat partials
//        w3t [0..8447]   staged w_out tile [o][32] (pitch 33)
//        qs  [4160..6207], ks [6208..8255], vs [8256..10303]  [dh][pix]
//   tbl  [43072..43360]  DPB table (289)
//   meanp[43361..43424], rstdp[43425..43488]
// Total 43489 floats = 173956 B dynamic smem.
// -------------------------------------------------------------------------
#define SMEM_FLOATS 43489

__global__ __launch_bounds__(256, 1) void attn_kernel(
    const float* __restrict__ x, const float* __restrict__ gw, const float* __restrict__ gb,
    const float* __restrict__ w_qkv, const float* __restrict__ w_out,
    const float* __restrict__ b_out, float* __restrict__ out)
{
    extern __shared__ float smf[];
    float* xs    = smf;
    float* att   = smf + 16384;
    float* work  = smf + 32768;
    float* wt    = work;
    float* sim   = work;
    float* w3t   = work;
    float* qs    = work + 4160;
    float* ks    = work + 6208;
    float* vs    = work + 8256;
    float* tbl   = smf + 43072;
    float* meanp = smf + 43361;
    float* rstdp = smf + 43425;

    const int t  = threadIdx.x;
    const int wid = blockIdx.x;
    const int bb = wid >> 10;
    const int wh = (wid >> 5) & 31;
    const int ww = wid & 31;
    const float* xb = x + ((size_t)bb << 24) + (size_t)(wh * 8) * 256 + ww * 8;

    // DPB table into smem
    for (int i = t; i < 289; i += 256) tbl[i] = g_table[i];

    // ---- load window: xs[d*64 + pix] ----
    #pragma unroll 4
    for (int m2 = 0; m2 < 64; m2++) {
        int idx = m2 * 256 + t;
        int d = idx >> 6, pix = idx & 63;
        xs[idx] = xb[((size_t)d << 16) + ((pix >> 3) << 8) + (pix & 7)];
    }
    __syncthreads();

    // ---- per-pixel LN stats over 256 channels ----
    {
        int pix = t & 63, q4 = t >> 6;
        float s = 0.f, ss = 0.f;
        #pragma unroll 8
        for (int d = q4 * 64; d < q4 * 64 + 64; d++) {
            float v = xs[d * 64 + pix];
            s += v; ss += v * v;
        }
        work[t] = s; work[256 + t] = ss;
        __syncthreads();
        if (t < 64) {
            float s0 = work[t] + work[64 + t] + work[128 + t] + work[192 + t];
            float s1 = work[256 + t] + work[320 + t] + work[384 + t] + work[448 + t];
            float mn = s0 * (1.f / 256.f);
            float vr = s1 * (1.f / 256.f) - mn * mn;
            meanp[t] = mn;
            rstdp[t] = rsqrtf(vr + EPS);
        }
        __syncthreads();
    }

    // ---- normalize in place ----
    #pragma unroll 4
    for (int m2 = 0; m2 < 64; m2++) {
        int idx = m2 * 256 + t;
        int d = idx >> 6, pix = idx & 63;
        xs[idx] = (xs[idx] - meanp[pix]) * rstdp[pix] * gw[d] + gb[d];
    }
    // (first syncthreads of head loop orders this)

    const int rg = t >> 4;   // 0..15
    const int pg = t & 15;   // 0..15

    // ---- per-head: QKV -> sim(+bias) -> softmax -> AV ----
    for (int head = 0; head < 8; head++) {
        // QKV GEMM: C[96 x 64] = Wslice[96 x 256] * xs[256 x 64]
        float acc[6][4];
        #pragma unroll
        for (int mr = 0; mr < 6; mr++)
            #pragma unroll
            for (int mp = 0; mp < 4; mp++) acc[mr][mp] = 0.f;

        for (int dc = 0; dc < 256; dc += 32) {
            __syncthreads();   // protect wt (aliases sim of previous head)
            #pragma unroll
            for (int i2 = t; i2 < 3072; i2 += 256) {
                int rr = i2 >> 5, dd = i2 & 31;
                int row = ((rr >> 5) << 8) + head * 32 + (rr & 31);
                wt[dd * 97 + rr] = w_qkv[(row << 8) + dc + dd];
            }
            __syncthreads();
            #pragma unroll
            for (int dd = 0; dd < 32; dd++) {
                float4 xv = *(const float4*)&xs[(dc + dd) * 64 + pg * 4];
                const float* wr = &wt[dd * 97 + rg * 6];
                #pragma unroll
                for (int mr = 0; mr < 6; mr++) {
                    float wv = wr[mr];
                    acc[mr][0] = fmaf(wv, xv.x, acc[mr][0]);
                    acc[mr][1] = fmaf(wv, xv.y, acc[mr][1]);
                    acc[mr][2] = fmaf(wv, xv.z, acc[mr][2]);
                    acc[mr][3] = fmaf(wv, xv.w, acc[mr][3]);
                }
            }
        }
        // scatter to qs/ks/vs  [dh][pix]
        #pragma unroll
        for (int mr = 0; mr < 6; mr++) {
            int o = rg * 6 + mr;
            int grp = o >> 5, dh = o & 31;
            float* dst = (grp == 0) ? qs : ((grp == 1) ? ks : vs);
            float sc = (grp == 0) ? QK_SCALE : 1.f;
            #pragma unroll
            for (int mp = 0; mp < 4; mp++)
                dst[dh * 64 + pg * 4 + mp] = acc[mr][mp] * sc;
        }
        __syncthreads();

        // sim[i][j] = bias(i,j) + sum_d q[d][i]*k[d][j]
        float s2[4][4];
        #pragma unroll
        for (int mi = 0; mi < 4; mi++) {
            int i = rg * 4 + mi, yi = i >> 3, xi = i & 7;
            #pragma unroll
            for (int mj = 0; mj < 4; mj++) {
                int j = pg * 4 + mj, yj = j >> 3, xj = j & 7;
                s2[mi][mj] = tbl[(yi - yj + 7) * 15 + (xi - xj + 7)];
            }
        }
        #pragma unroll
        for (int dd = 0; dd < 32; dd++) {
            float4 qv = *(const float4*)&qs[dd * 64 + rg * 4];
            float4 kv = *(const float4*)&ks[dd * 64 + pg * 4];
            float qa[4] = {qv.x, qv.y, qv.z, qv.w};
            float ka[4] = {kv.x, kv.y, kv.z, kv.w};
            #pragma unroll
            for (int mi = 0; mi < 4; mi++)
                #pragma unroll
                for (int mj = 0; mj < 4; mj++)
                    s2[mi][mj] = fmaf(qa[mi], ka[mj], s2[mi][mj]);
        }
        #pragma unroll
        for (int mi = 0; mi < 4; mi++)
            #pragma unroll
            for (int mj = 0; mj < 4; mj++)
                sim[(rg * 4 + mi) * 65 + pg * 4 + mj] = s2[mi][mj];
        __syncthreads();

        // softmax: warp per row, 8 rows per warp
        {
            int lane = t & 31, wrp = t >> 5;
            #pragma unroll
            for (int it = 0; it < 8; it++) {
                int r = wrp * 8 + it;
                float v0 = sim[r * 65 + lane];
                float v1 = sim[r * 65 + 32 + lane];
                float mx = fmaxf(v0, v1);
                #pragma unroll
                for (int o = 16; o > 0; o >>= 1)
                    mx = fmaxf(mx, __shfl_xor_sync(0xffffffffu, mx, o));
                float e0 = __expf(v0 - mx);
                float e1 = __expf(v1 - mx);
                float sum = e0 + e1;
                #pragma unroll
                for (int o = 16; o > 0; o >>= 1)
                    sum += __shfl_xor_sync(0xffffffffu, sum, o);
                float inv = 1.f / sum;
                sim[r * 65 + lane] = e0 * inv;
                sim[r * 65 + 32 + lane] = e1 * inv;
            }
        }
        __syncthreads();

        // AV: att[head*32+dh][i] = sum_j P[i][j] * v[dh][j]
        {
            int dg = t >> 4, igr = t & 15;
            float a0[4] = {0.f, 0.f, 0.f, 0.f};
            float a1[4] = {0.f, 0.f, 0.f, 0.f};
            #pragma unroll 4
            for (int j = 0; j < 64; j++) {
                float vv0 = vs[(dg * 2) * 64 + j];
                float vv1 = vs[(dg * 2 + 1) * 64 + j];
                #pragma unroll
                for (int mi = 0; mi < 4; mi++) {
                    float p = sim[(igr * 4 + mi) * 65 + j];
                    a0[mi] = fmaf(p, vv0, a0[mi]);
                    a1[mi] = fmaf(p, vv1, a1[mi]);
                }
            }
            #pragma unroll
            for (int mi = 0; mi < 4; mi++) {
                att[(head * 32 + dg * 2) * 64 + igr * 4 + mi]     = a0[mi];
                att[(head * 32 + dg * 2 + 1) * 64 + igr * 4 + mi] = a1[mi];
            }
        }
        // next head's first __syncthreads orders sim/vs reuse
    }
    __syncthreads();

    // ---- output projection: out[o][pix] = sum_i w_out[o][i]*att[i][pix] + b_out[o]
    {
        int rg3 = t >> 3;   // 0..31 -> rows o = rg3*8 + mr
        int pg3 = t & 7;    // 0..7  -> pix = pg3*8 + mp (one window row, contiguous)
        float a4[8][8];
        #pragma unroll
        for (int mr = 0; mr < 8; mr++)
            #pragma unroll
            for (int mp = 0; mp < 8; mp++) a4[mr][mp] = 0.f;

        for (int ic = 0; ic < 256; ic += 32) {
            __syncthreads();
            #pragma unroll
            for (int i2 = t; i2 < 8192; i2 += 256) {
                int o = i2 >> 5, ii = i2 & 31;
                w3t[o * 33 + ii] = w_out[(o << 8) + ic + ii];
            }
            __syncthreads();
            #pragma unroll
            for (int ii = 0; ii < 32; ii++) {
                float4 av0 = *(const float4*)&att[(ic + ii) * 64 + pg3 * 8];
                float4 av1 = *(const float4*)&att[(ic + ii) * 64 + pg3 * 8 + 4];
                float ab[8] = {av0.x, av0.y, av0.z, av0.w, av1.x, av1.y, av1.z, av1.w};
                #pragma unroll
                for (int mr = 0; mr < 8; mr++) {
                    float wv = w3t[(rg3 * 8 + mr) * 33 + ii];
                    #pragma unroll
                    for (int mp = 0; mp < 8; mp++)
                        a4[mr][mp] = fmaf(wv, ab[mp], a4[mr][mp]);
                }
            }
        }

        // scatter to (B, D, H, W); each (o) writes one contiguous 8-float row
        float* ob = out + ((size_t)bb << 24) + (size_t)(wh * 8 + pg3) * 256 + ww * 8;
        #pragma unroll
        for (int mr = 0; mr < 8; mr++) {
            int o = rg3 * 8 + mr;
            float bo = b_out[o];
            float4 v0 = make_float4(a4[mr][0] + bo, a4[mr][1] + bo,
                                    a4[mr][2] + bo, a4[mr][3] + bo);
            float4 v1 = make_float4(a4[mr][4] + bo, a4[mr][5] + bo,
                                    a4[mr][6] + bo, a4[mr][7] + bo);
            *(float4*)&ob[(size_t)o << 16]       = v0;
            *(float4*)&ob[((size_t)o << 16) + 4] = v1;
        }
    }
}

// -------------------------------------------------------------------------
extern "C" void kernel_launch(void* const* d_in, const int* in_sizes, int n_in,
                              void* d_out, int out_size)
{
    (void)in_sizes; (void)n_in; (void)out_size;
    const float* x     = (const float*)d_in[0];
    const float* g     = (const float*)d_in[1];
    const float* b     = (const float*)d_in[2];
    const float* w_qkv = (const float*)d_in[3];
    const float* w_out = (const float*)d_in[4];
    const float* b_out = (const float*)d_in[5];

    cudaFuncSetAttribute(attn_kernel, cudaFuncAttributeMaxDynamicSharedMemorySize,
                         SMEM_FLOATS * (int)sizeof(float));

    dpb_kernel<<<289, 64>>>(
        (const float*)d_in[6],  (const float*)d_in[7],
        (const float*)d_in[8],  (const float*)d_in[9],
        (const float*)d_in[10], (const float*)d_in[11],
        (const float*)d_in[12], (const float*)d_in[13],
        (const float*)d_in[14], (const float*)d_in[15],
        (const float*)d_in[16], (const float*)d_in[17],
        (const float*)d_in[18], (const float*)d_in[19]);

    attn_kernel<<<4096, 256, SMEM_FLOATS * (int)sizeof(float)>>>(
        x, g, b, w_qkv, w_out, b_out, (float*)d_out);
}

// round 2
// speedup vs baseline: 1.0016x; 1.0016x over previous
#include <cuda_runtime.h>
#include <math.h>

#define EPS 1e-5f
#define QK_SCALE 0.17677669529663687f   // 32^-0.5

// dynamic position bias table, written by dpb_kernel, read by attn_kernel
__device__ float g_table[289];

// -------------------------------------------------------------------------
// DPB MLP: 289 relative positions -> scalar bias table
// grid: 289 blocks x 64 threads (one block per grid row, one thread per feature)
// -------------------------------------------------------------------------
__device__ __forceinline__ float blockreduce64(float v, float* red) {
    #pragma unroll
    for (int o = 16; o > 0; o >>= 1) v += __shfl_xor_sync(0xffffffffu, v, o);
    int t = threadIdx.x;
    if ((t & 31) == 0) red[t >> 5] = v;
    __syncthreads();
    float r = red[0] + red[1];
    __syncthreads();
    return r;
}

__global__ void dpb_kernel(
    const float* __restrict__ w1, const float* __restrict__ b1,
    const float* __restrict__ g1, const float* __restrict__ bb1,
    const float* __restrict__ w2, const float* __restrict__ b2,
    const float* __restrict__ g2, const float* __restrict__ bb2,
    const float* __restrict__ w3, const float* __restrict__ b3,
    const float* __restrict__ g3, const float* __restrict__ bb3,
    const float* __restrict__ w4, const float* __restrict__ b4)
{
    __shared__ float hs[64];
    __shared__ float red[2];
    int r = blockIdx.x, j = threadIdx.x;
    float r0 = (float)(r / 17 - 8);
    float r1 = (float)(r % 17 - 8);

    // layer 1: rel(2) @ w1(2,64) + b1 -> LN -> relu
    float v = r0 * w1[j] + r1 * w1[64 + j] + b1[j];
    float m = blockreduce64(v, red) * (1.f / 64.f);
    float d = v - m;
    float var = blockreduce64(d * d, red) * (1.f / 64.f);
    v = fmaxf(d * rsqrtf(var + EPS) * g1[j] + bb1[j], 0.f);
    hs[j] = v;
    __syncthreads();

    // layer 2
    float a = b2[j];
    #pragma unroll 8
    for (int k = 0; k < 64; k++) a += hs[k] * w2[k * 64 + j];
    m = blockreduce64(a, red) * (1.f / 64.f);
    d = a - m;
    var = blockreduce64(d * d, red) * (1.f / 64.f);
    a = fmaxf(d * rsqrtf(var + EPS) * g2[j] + bb2[j], 0.f);
    hs[j] = a;
    __syncthreads();

    // layer 3
    a = b3[j];
    #pragma unroll 8
    for (int k = 0; k < 64; k++) a += hs[k] * w3[k * 64 + j];
    m = blockreduce64(a, red) * (1.f / 64.f);
    d = a - m;
    var = blockreduce64(d * d, red) * (1.f / 64.f);
    a = fmaxf(d * rsqrtf(var + EPS) * g3[j] + bb3[j], 0.f);
    hs[j] = a;
    __syncthreads();

    // layer 4: (64) @ w4(64,1) + b4
    float c = blockreduce64(hs[j] * w4[j], red);
    if (j == 0) g_table[r] = c + b4[0];
}

// -------------------------------------------------------------------------
// Fused window kernel: one CTA per 8x8 window.
// LN (channel-wise per pixel) -> QKV (per head) -> attention+bias+softmax
// -> AV -> output projection -> scatter to (B, D, H, W).
// SMEM layout (floats):
//   xs   [0     .. 16383]  x window, [d][pix], normalized in place
//   att  [16384 .. 32767]  attention output [inner_ch][pix]
//   work [32768 .. 43071]  (10304 floats) multi-use:
//        wt  [0..3103]   staged w_qkv tile [dd][96] (pitch 97)
//        sim [0..4159]   attention matrix [64][65]
//        red [0..511]    LN stat partials
//        w3t [0..8447]   staged w_out tile [o][32] (pitch 33)
//        qs  [4160..6207], ks [6208..8255], vs [8256..10303]  [dh][pix]
//   tbl  [43072..43360]  DPB table (289)
//   meanp[43361..43424], rstdp[43425..43488]
// Total 43489 floats = 173956 B dynamic smem.
// -------------------------------------------------------------------------
#define SMEM_FLOATS 43489

__global__ __launch_bounds__(256, 1) void attn_kernel(
    const float* __restrict__ x, const float* __restrict__ gw, const float* __restrict__ gb,
    const float* __restrict__ w_qkv, const float* __restrict__ w_out,
    const float* __restrict__ b_out, float* __restrict__ out)
{
    extern __shared__ float smf[];
    float* xs    = smf;
    float* att   = smf + 16384;
    float* work  = smf + 32768;
    float* wt    = work;
    float* sim   = work;
    float* w3t   = work;
    float* qs    = work + 4160;
    float* ks    = work + 6208;
    float* vs    = work + 8256;
    float* tbl   = smf + 43072;
    float* meanp = smf + 43361;
    float* rstdp = smf + 43425;

    const int t  = threadIdx.x;
    const int wid = blockIdx.x;
    const int bb = wid >> 10;
    const int wh = (wid >> 5) & 31;
    const int ww = wid & 31;
    const float* xb = x + ((size_t)bb << 24) + (size_t)(wh * 8) * 256 + ww * 8;

    // DPB table into smem
    for (int i = t; i < 289; i += 256) tbl[i] = g_table[i];

    // ---- load window: xs[d*64 + pix] ----
    #pragma unroll 4
    for (int m2 = 0; m2 < 64; m2++) {
        int idx = m2 * 256 + t;
        int d = idx >> 6, pix = idx & 63;
        xs[idx] = xb[((size_t)d << 16) + ((pix >> 3) << 8) + (pix & 7)];
    }
    __syncthreads();

    // ---- per-pixel LN stats over 256 channels ----
    {
        int pix = t & 63, q4 = t >> 6;
        float s = 0.f, ss = 0.f;
        #pragma unroll 8
        for (int d = q4 * 64; d < q4 * 64 + 64; d++) {
            float v = xs[d * 64 + pix];
            s += v; ss += v * v;
        }
        work[t] = s; work[256 + t] = ss;
        __syncthreads();
        if (t < 64) {
            float s0 = work[t] + work[64 + t] + work[128 + t] + work[192 + t];
            float s1 = work[256 + t] + work[320 + t] + work[384 + t] + work[448 + t];
            float mn = s0 * (1.f / 256.f);
            float vr = s1 * (1.f / 256.f) - mn * mn;
            meanp[t] = mn;
            rstdp[t] = rsqrtf(vr + EPS);
        }
        __syncthreads();
    }

    // ---- normalize in place ----
    #pragma unroll 4
    for (int m2 = 0; m2 < 64; m2++) {
        int idx = m2 * 256 + t;
        int d = idx >> 6, pix = idx & 63;
        xs[idx] = (xs[idx] - meanp[pix]) * rstdp[pix] * gw[d] + gb[d];
    }
    // (first syncthreads of head loop orders this)

    const int rg = t >> 4;   // 0..15
    const int pg = t & 15;   // 0..15

    // ---- per-head: QKV -> sim(+bias) -> softmax -> AV ----
    for (int head = 0; head < 8; head++) {
        // QKV GEMM: C[96 x 64] = Wslice[96 x 256] * xs[256 x 64]
        float acc[6][4];
        #pragma unroll
        for (int mr = 0; mr < 6; mr++)
            #pragma unroll
            for (int mp = 0; mp < 4; mp++) acc[mr][mp] = 0.f;

        for (int dc = 0; dc < 256; dc += 32) {
            __syncthreads();   // protect wt (aliases sim of previous head)
            #pragma unroll
            for (int i2 = t; i2 < 3072; i2 += 256) {
                int rr = i2 >> 5, dd = i2 & 31;
                int row = ((rr >> 5) << 8) + head * 32 + (rr & 31);
                wt[dd * 97 + rr] = w_qkv[(row << 8) + dc + dd];
            }
            __syncthreads();
            #pragma unroll
            for (int dd = 0; dd < 32; dd++) {
                float4 xv = *(const float4*)&xs[(dc + dd) * 64 + pg * 4];
                const float* wr = &wt[dd * 97 + rg * 6];
                #pragma unroll
                for (int mr = 0; mr < 6; mr++) {
                    float wv = wr[mr];
                    acc[mr][0] = fmaf(wv, xv.x, acc[mr][0]);
                    acc[mr][1] = fmaf(wv, xv.y, acc[mr][1]);
                    acc[mr][2] = fmaf(wv, xv.z, acc[mr][2]);
                    acc[mr][3] = fmaf(wv, xv.w, acc[mr][3]);
                }
            }
        }
        // scatter to qs/ks/vs  [dh][pix]
        #pragma unroll
        for (int mr = 0; mr < 6; mr++) {
            int o = rg * 6 + mr;
            int grp = o >> 5, dh = o & 31;
            float* dst = (grp == 0) ? qs : ((grp == 1) ? ks : vs);
            float sc = (grp == 0) ? QK_SCALE : 1.f;
            #pragma unroll
            for (int mp = 0; mp < 4; mp++)
                dst[dh * 64 + pg * 4 + mp] = acc[mr][mp] * sc;
        }
        __syncthreads();

        // sim[i][j] = bias(i,j) + sum_d q[d][i]*k[d][j]
        float s2[4][4];
        #pragma unroll
        for (int mi = 0; mi < 4; mi++) {
            int i = rg * 4 + mi, yi = i >> 3, xi = i & 7;
            #pragma unroll
            for (int mj = 0; mj < 4; mj++) {
                int j = pg * 4 + mj, yj = j >> 3, xj = j & 7;
                s2[mi][mj] = tbl[(yi - yj + 7) * 15 + (xi - xj + 7)];
            }
        }
        #pragma unroll
        for (int dd = 0; dd < 32; dd++) {
            float4 qv = *(const float4*)&qs[dd * 64 + rg * 4];
            float4 kv = *(const float4*)&ks[dd * 64 + pg * 4];
            float qa[4] = {qv.x, qv.y, qv.z, qv.w};
            float ka[4] = {kv.x, kv.y, kv.z, kv.w};
            #pragma unroll
            for (int mi = 0; mi < 4; mi++)
                #pragma unroll
                for (int mj = 0; mj < 4; mj++)
                    s2[mi][mj] = fmaf(qa[mi], ka[mj], s2[mi][mj]);
        }
        #pragma unroll
        for (int mi = 0; mi < 4; mi++)
            #pragma unroll
            for (int mj = 0; mj < 4; mj++)
                sim[(rg * 4 + mi) * 65 + pg * 4 + mj] = s2[mi][mj];
        __syncthreads();

        // softmax: warp per row, 8 rows per warp
        {
            int lane = t & 31, wrp = t >> 5;
            #pragma unroll
            for (int it = 0; it < 8; it++) {
                int r = wrp * 8 + it;
                float v0 = sim[r * 65 + lane];
                float v1 = sim[r * 65 + 32 + lane];
                float mx = fmaxf(v0, v1);
                #pragma unroll
                for (int o = 16; o > 0; o >>= 1)
                    mx = fmaxf(mx, __shfl_xor_sync(0xffffffffu, mx, o));
                float e0 = __expf(v0 - mx);
                float e1 = __expf(v1 - mx);
                float sum = e0 + e1;
                #pragma unroll
                for (int o = 16; o > 0; o >>= 1)
                    sum += __shfl_xor_sync(0xffffffffu, sum, o);
                float inv = 1.f / sum;
                sim[r * 65 + lane] = e0 * inv;
                sim[r * 65 + 32 + lane] = e1 * inv;
            }
        }
        __syncthreads();

        // AV: att[head*32+dh][i] = sum_j P[i][j] * v[dh][j]
        {
            int dg = t >> 4, igr = t & 15;
            float a0[4] = {0.f, 0.f, 0.f, 0.f};
            float a1[4] = {0.f, 0.f, 0.f, 0.f};
            #pragma unroll 4
            for (int j = 0; j < 64; j++) {
                float vv0 = vs[(dg * 2) * 64 + j];
                float vv1 = vs[(dg * 2 + 1) * 64 + j];
                #pragma unroll
                for (int mi = 0; mi < 4; mi++) {
                    float p = sim[(igr * 4 + mi) * 65 + j];
                    a0[mi] = fmaf(p, vv0, a0[mi]);
                    a1[mi] = fmaf(p, vv1, a1[mi]);
                }
            }
            #pragma unroll
            for (int mi = 0; mi < 4; mi++) {
                att[(head * 32 + dg * 2) * 64 + igr * 4 + mi]     = a0[mi];
                att[(head * 32 + dg * 2 + 1) * 64 + igr * 4 + mi] = a1[mi];
            }
        }
        // next head's first __syncthreads orders sim/vs reuse
    }
    __syncthreads();

    // ---- output projection: out[o][pix] = sum_i w_out[o][i]*att[i][pix] + b_out[o]
    {
        int rg3 = t >> 3;   // 0..31 -> rows o = rg3*8 + mr
        int pg3 = t & 7;    // 0..7  -> pix = pg3*8 + mp (one window row, contiguous)
        float a4[8][8];
        #pragma unroll
        for (int mr = 0; mr < 8; mr++)
            #pragma unroll
            for (int mp = 0; mp < 8; mp++) a4[mr][mp] = 0.f;

        for (int ic = 0; ic < 256; ic += 32) {
            __syncthreads();
            #pragma unroll
            for (int i2 = t; i2 < 8192; i2 += 256) {
                int o = i2 >> 5, ii = i2 & 31;
                w3t[o * 33 + ii] = w_out[(o << 8) + ic + ii];
            }
            __syncthreads();
            #pragma unroll
            for (int ii = 0; ii < 32; ii++) {
                float4 av0 = *(const float4*)&att[(ic + ii) * 64 + pg3 * 8];
                float4 av1 = *(const float4*)&att[(ic + ii) * 64 + pg3 * 8 + 4];
                float ab[8] = {av0.x, av0.y, av0.z, av0.w, av1.x, av1.y, av1.z, av1.w};
                #pragma unroll
                for (int mr = 0; mr < 8; mr++) {
                    float wv = w3t[(rg3 * 8 + mr) * 33 + ii];
                    #pragma unroll
                    for (int mp = 0; mp < 8; mp++)
                        a4[mr][mp] = fmaf(wv, ab[mp], a4[mr][mp]);
                }
            }
        }

        // scatter to (B, D, H, W); each (o) writes one contiguous 8-float row
        float* ob = out + ((size_t)bb << 24) + (size_t)(wh * 8 + pg3) * 256 + ww * 8;
        #pragma unroll
        for (int mr = 0; mr < 8; mr++) {
            int o = rg3 * 8 + mr;
            float bo = b_out[o];
            float4 v0 = make_float4(a4[mr][0] + bo, a4[mr][1] + bo,
                                    a4[mr][2] + bo, a4[mr][3] + bo);
            float4 v1 = make_float4(a4[mr][4] + bo, a4[mr][5] + bo,
                                    a4[mr][6] + bo, a4[mr][7] + bo);
            *(float4*)&ob[(size_t)o << 16]       = v0;
            *(float4*)&ob[((size_t)o << 16) + 4] = v1;
        }
    }
}

// -------------------------------------------------------------------------
extern "C" void kernel_launch(void* const* d_in, const int* in_sizes, int n_in,
                              void* d_out, int out_size)
{
    (void)in_sizes; (void)n_in; (void)out_size;
    const float* x     = (const float*)d_in[0];
    const float* g     = (const float*)d_in[1];
    const float* b     = (const float*)d_in[2];
    const float* w_qkv = (const float*)d_in[3];
    const float* w_out = (const float*)d_in[4];
    const float* b_out = (const float*)d_in[5];

    cudaFuncSetAttribute(attn_kernel, cudaFuncAttributeMaxDynamicSharedMemorySize,
                         SMEM_FLOATS * (int)sizeof(float));

    dpb_kernel<<<289, 64>>>(
        (const float*)d_in[6],  (const float*)d_in[7],
        (const float*)d_in[8],  (const float*)d_in[9],
        (const float*)d_in[10], (const float*)d_in[11],
        (const float*)d_in[12], (const float*)d_in[13],
        (const float*)d_in[14], (const float*)d_in[15],
        (const float*)d_in[16], (const float*)d_in[17],
        (const float*)d_in[18], (const float*)d_in[19]);

    attn_kernel<<<4096, 256, SMEM_FLOATS * (int)sizeof(float)>>>(
        x, g, b, w_qkv, w_out, b_out, (float*)d_out);
}

// round 3
// speedup vs baseline: 1.4706x; 1.4683x over previous
#include <cuda_runtime.h>
#include <math.h>

#define EPS 1e-5f
#define QK_SCALE 0.17677669529663687f
typedef unsigned int u32;

__device__ float g_table[289];
__device__ u32 WqkvHi[98304], WqkvLo[98304];   // [8 heads][96 rows(q32|k32|v32)][128 pairs]
__device__ u32 WoutHi[32768],  WoutLo[32768];  // [256 rows][128 pairs]

// ---------------- smem layout (u32 offsets) ----------------
#define P_X   132
#define O_XH  0
#define O_XL  8448
#define O_AH  16896
#define O_AL  25344
#define O_ST  33792
#define O_QKH 33792
#define O_QKL 36096
#define O_VH  38400
#define O_VL  39552
#define O_PH  40704
#define O_PL  43008
#define O_XF  16896      /* fp32 x temp, overlays ATT+stage head */
#define O_TBL 47616
#define O_BOUT 47936
#define O_GW  48192
#define O_GB  48448
#define O_RED 48704
#define O_MEAN 49216
#define O_RSTD 49280
#define SMEM_U32 49344
#define SMEM_BYTES (SMEM_U32*4)

// ---------------- helpers ----------------
__device__ __forceinline__ u32 pk2(float lo, float hi){
    u32 r; asm("cvt.rn.bf16x2.f32 %0, %1, %2;" : "=r"(r) : "f"(hi), "f"(lo)); return r;
}
__device__ __forceinline__ void sp2(float x0, float x1, u32& h, u32& l){
    h = pk2(x0, x1);
    float h0 = __uint_as_float(h << 16);
    float h1 = __uint_as_float(h & 0xffff0000u);
    l = pk2(x0 - h0, x1 - h1);
}
__device__ __forceinline__ void mma16(float* c, const u32* a, const u32* b){
    asm volatile("mma.sync.aligned.m16n8k16.row.col.f32.bf16.bf16.f32 "
        "{%0,%1,%2,%3},{%4,%5,%6,%7},{%8,%9},{%0,%1,%2,%3};"
        : "+f"(c[0]),"+f"(c[1]),"+f"(c[2]),"+f"(c[3])
        : "r"(a[0]),"r"(a[1]),"r"(a[2]),"r"(a[3]),"r"(b[0]),"r"(b[1]));
}
__device__ __forceinline__ void mma3(float* c, const u32* ah, const u32* al,
                                     const u32* bh, const u32* bl){
    mma16(c, ah, bh); mma16(c, al, bh); mma16(c, ah, bl);
}
__device__ __forceinline__ void ldA(u32* a, const u32* s, int r0, int cp_, int pitch, int g, int tg){
    a[0]=s[(r0+g)*pitch+cp_+tg];   a[1]=s[(r0+g+8)*pitch+cp_+tg];
    a[2]=s[(r0+g)*pitch+cp_+tg+4]; a[3]=s[(r0+g+8)*pitch+cp_+tg+4];
}
__device__ __forceinline__ void ldBf(u32* b, const u32* s, int n0, int cp_, int pitch, int g, int tg){
    b[0]=s[(n0+g)*pitch+cp_+tg];   b[1]=s[(n0+g)*pitch+cp_+tg+4];
}
__device__ __forceinline__ void cp16(void* s, const void* gm){
    u32 sa = (u32)__cvta_generic_to_shared(s);
    asm volatile("cp.async.cg.shared.global [%0], [%1], 16;" :: "r"(sa), "l"(gm));
}
__device__ __forceinline__ void cp_commit(){ asm volatile("cp.async.commit_group;"); }
__device__ __forceinline__ void cp_wait0(){ asm volatile("cp.async.wait_group 0;"); }
__device__ __forceinline__ void cp_wait1(){ asm volatile("cp.async.wait_group 1;"); }

// ---------------- weight precompute ----------------
__global__ void conv_qkv(const float* __restrict__ w){
    int h = blockIdx.x / 96, r = blockIdx.x % 96, p = threadIdx.x;
    int grow = (r >> 5) * 256 + h * 32 + (r & 31);
    u32 hh, ll;
    sp2(w[grow*256 + 2*p], w[grow*256 + 2*p + 1], hh, ll);
    WqkvHi[(h*96 + r)*128 + p] = hh;
    WqkvLo[(h*96 + r)*128 + p] = ll;
}
__global__ void conv_out(const float* __restrict__ w){
    int r = blockIdx.x, p = threadIdx.x;
    u32 hh, ll;
    sp2(w[r*256 + 2*p], w[r*256 + 2*p + 1], hh, ll);
    WoutHi[r*128 + p] = hh;
    WoutLo[r*128 + p] = ll;
}

// ---------------- DPB MLP ----------------
__device__ __forceinline__ float blockreduce64(float v, float* red){
    #pragma unroll
    for (int o = 16; o > 0; o >>= 1) v += __shfl_xor_sync(0xffffffffu, v, o);
    int t = threadIdx.x;
    if ((t & 31) == 0) red[t >> 5] = v;
    __syncthreads();
    float r = red[0] + red[1];
    __syncthreads();
    return r;
}
__global__ void dpb_kernel(
    const float* __restrict__ w1, const float* __restrict__ b1,
    const float* __restrict__ g1, const float* __restrict__ bb1,
    const float* __restrict__ w2, const float* __restrict__ b2,
    const float* __restrict__ g2, const float* __restrict__ bb2,
    const float* __restrict__ w3, const float* __restrict__ b3,
    const float* __restrict__ g3, const float* __restrict__ bb3,
    const float* __restrict__ w4, const float* __restrict__ b4)
{
    __shared__ float hs[64];
    __shared__ float red[2];
    int r = blockIdx.x, j = threadIdx.x;
    float r0 = (float)(r / 17 - 8), r1 = (float)(r % 17 - 8);
    float v = r0 * w1[j] + r1 * w1[64 + j] + b1[j];
    float m = blockreduce64(v, red) * (1.f/64.f);
    float d = v - m;
    float var = blockreduce64(d*d, red) * (1.f/64.f);
    v = fmaxf(d * rsqrtf(var + EPS) * g1[j] + bb1[j], 0.f);
    hs[j] = v; __syncthreads();
    float a = b2[j];
    #pragma unroll 8
    for (int k = 0; k < 64; k++) a += hs[k] * w2[k*64 + j];
    m = blockreduce64(a, red) * (1.f/64.f);
    d = a - m;
    var = blockreduce64(d*d, red) * (1.f/64.f);
    a = fmaxf(d * rsqrtf(var + EPS) * g2[j] + bb2[j], 0.f);
    __syncthreads(); hs[j] = a; __syncthreads();
    a = b3[j];
    #pragma unroll 8
    for (int k = 0; k < 64; k++) a += hs[k] * w3[k*64 + j];
    m = blockreduce64(a, red) * (1.f/64.f);
    d = a - m;
    var = blockreduce64(d*d, red) * (1.f/64.f);
    a = fmaxf(d * rsqrtf(var + EPS) * g3[j] + bb3[j], 0.f);
    __syncthreads(); hs[j] = a; __syncthreads();
    float c = blockreduce64(hs[j] * w4[j], red);
    if (j == 0) g_table[r] = c + b4[0];
}

// ---------------- fused attention ----------------
__global__ __launch_bounds__(256, 1) void attn_kernel(
    const float* __restrict__ x, const float* __restrict__ gw, const float* __restrict__ gb,
    const float* __restrict__ b_out, float* __restrict__ out)
{
    extern __shared__ u32 su[];
    float* sf = (float*)su;
    const int t = threadIdx.x, lane = t & 31, w = t >> 5;
    const int g = lane >> 2, tg = lane & 3;
    const int wid = blockIdx.x;
    const int bb = wid >> 10, wh = (wid >> 5) & 31, ww = wid & 31;
    const float* xb = x + ((size_t)bb << 24) + (size_t)(wh * 8) * 256 + ww * 8;

    if (t < 289) sf[O_TBL + t] = g_table[t];
    sf[O_BOUT + t] = b_out[t];
    sf[O_GW + t] = gw[t];
    sf[O_GB + t] = gb[t];

    // ---- load x (fp32) ----
    #pragma unroll
    for (int i = 0; i < 8; i++) {
        int s = i * 256 + t, d = s >> 3, ph = s & 7;
        const float* src = xb + (size_t)d * 65536 + (size_t)ph * 256;
        float* dst = sf + O_XF + d * 68 + ph * 8;
        cp16(dst, src); cp16(dst + 4, src + 4);
    }
    cp_commit(); cp_wait0(); __syncthreads();

    // ---- LN stats ----
    {
        int pix = t & 63, q4 = t >> 6;
        float s = 0.f, ss = 0.f;
        #pragma unroll 8
        for (int d = q4*64; d < q4*64 + 64; d++) {
            float v = sf[O_XF + d*68 + pix]; s += v; ss += v*v;
        }
        sf[O_RED + t] = s; sf[O_RED + 256 + t] = ss;
        __syncthreads();
        if (t < 64) {
            float s0 = sf[O_RED+t] + sf[O_RED+64+t] + sf[O_RED+128+t] + sf[O_RED+192+t];
            float s1 = sf[O_RED+256+t] + sf[O_RED+320+t] + sf[O_RED+384+t] + sf[O_RED+448+t];
            float mn = s0 * (1.f/256.f);
            float vr = s1 * (1.f/256.f) - mn*mn;
            sf[O_MEAN + t] = mn;
            sf[O_RSTD + t] = rsqrtf(vr + EPS);
        }
        __syncthreads();
    }
    // ---- normalize + split to X32 pairs ----
    {
        int pix = t & 63, cb = (t >> 6) * 64;
        float mn = sf[O_MEAN + pix], rs = sf[O_RSTD + pix];
        #pragma unroll 8
        for (int p = 0; p < 32; p++) {
            int c = cb + 2*p;
            float v0 = (sf[O_XF + c*68 + pix] - mn)*rs*sf[O_GW+c] + sf[O_GB+c];
            float v1 = (sf[O_XF + (c+1)*68 + pix] - mn)*rs*sf[O_GW+c+1] + sf[O_GB+c+1];
            u32 hh, ll; sp2(v0, v1, hh, ll);
            su[O_XH + pix*P_X + cb/2 + p] = hh;
            su[O_XL + pix*P_X + cb/2 + p] = ll;
        }
        __syncthreads();
    }

    const int mt  = w >> 1,  nb  = (w & 1) * 4;   // G1 qk tiles
    const int vmt = w & 1,   vnb = (w >> 1) * 2;  // G1 v tiles
    const int mt3 = w >> 1,  nb3 = (w & 1) * 2;   // GEMM3 tiles

    // ---- per-head ----
    for (int h = 0; h < 8; h++) {
        float cq[4][4], cv[2][4];
        #pragma unroll
        for (int i = 0; i < 4; i++) { cq[i][0]=cq[i][1]=cq[i][2]=cq[i][3]=0.f; }
        #pragma unroll
        for (int i = 0; i < 2; i++) { cv[i][0]=cv[i][1]=cv[i][2]=cv[i][3]=0.f; }

        // stage chunk 0
        {
            #pragma unroll
            for (int i = 0; i < 3; i++) {
                int id = i*256 + t, r = id >> 3, q = id & 7;
                cp16(su + O_ST + r*36 + q*4,        WqkvHi + (h*96 + r)*128 + q*4);
                cp16(su + O_ST + 3456 + r*36 + q*4, WqkvLo + (h*96 + r)*128 + q*4);
            }
            cp_commit();
        }
        for (int ch = 0; ch < 4; ch++) {
            if (ch < 3) {
                int buf = (ch + 1) & 1;
                #pragma unroll
                for (int i = 0; i < 3; i++) {
                    int id = i*256 + t, r = id >> 3, q = id & 7;
                    cp16(su + O_ST + buf*6912 + r*36 + q*4,
                         WqkvHi + (h*96 + r)*128 + (ch+1)*32 + q*4);
                    cp16(su + O_ST + buf*6912 + 3456 + r*36 + q*4,
                         WqkvLo + (h*96 + r)*128 + (ch+1)*32 + q*4);
                }
                cp_commit();
                cp_wait1();
            } else cp_wait0();
            __syncthreads();
            const u32* WH = su + O_ST + (ch & 1)*6912;
            const u32* WL = WH + 3456;
            #pragma unroll
            for (int ks = 0; ks < 4; ks++) {
                int ksg = ch*4 + ks;
                u32 axh[4], axl[4];
                ldA(axh, su + O_XH, mt*16, ksg*8, P_X, g, tg);
                ldA(axl, su + O_XL, mt*16, ksg*8, P_X, g, tg);
                #pragma unroll
                for (int nt = 0; nt < 4; nt++) {
                    u32 bh[2], bl[2];
                    ldBf(bh, WH, (nb+nt)*8, ks*8, 36, g, tg);
                    ldBf(bl, WL, (nb+nt)*8, ks*8, 36, g, tg);
                    mma3(cq[nt], axh, axl, bh, bl);
                }
                u32 awh[4], awl[4];
                ldA(awh, WH, 64 + vmt*16, ks*8, 36, g, tg);
                ldA(awl, WL, 64 + vmt*16, ks*8, 36, g, tg);
                #pragma unroll
                for (int vt = 0; vt < 2; vt++) {
                    u32 bh[2], bl[2];
                    ldBf(bh, su + O_XH, (vnb+vt)*8, ksg*8, P_X, g, tg);
                    ldBf(bl, su + O_XL, (vnb+vt)*8, ksg*8, P_X, g, tg);
                    mma3(cv[vt], awh, awl, bh, bl);
                }
            }
            __syncthreads();
        }
        // epilogue: q/k (transposed pairs along d) and v (pairs along pix)
        #pragma unroll
        for (int nt = 0; nt < 4; nt++) {
            int ch0 = (nb+nt)*8 + 2*tg;
            float sc = (ch0 < 32) ? QK_SCALE : 1.f;
            int col = (nb+nt)*4 + tg, p0 = mt*16 + g;
            u32 hh, ll;
            sp2(cq[nt][0]*sc, cq[nt][1]*sc, hh, ll);
            su[O_QKH + p0*36 + col] = hh; su[O_QKL + p0*36 + col] = ll;
            sp2(cq[nt][2]*sc, cq[nt][3]*sc, hh, ll);
            su[O_QKH + (p0+8)*36 + col] = hh; su[O_QKL + (p0+8)*36 + col] = ll;
        }
        #pragma unroll
        for (int vt = 0; vt < 2; vt++) {
            int col = (vnb+vt)*4 + tg, r0 = vmt*16 + g;
            u32 hh, ll;
            sp2(cv[vt][0], cv[vt][1], hh, ll);
            su[O_VH + r0*36 + col] = hh; su[O_VL + r0*36 + col] = ll;
            sp2(cv[vt][2], cv[vt][3], hh, ll);
            su[O_VH + (r0+8)*36 + col] = hh; su[O_VL + (r0+8)*36 + col] = ll;
        }
        __syncthreads();

        // GEMM2 + softmax (warps 0..3)
        if (w < 4) {
            float cs[8][4];
            #pragma unroll
            for (int nt = 0; nt < 8; nt++) {
                int i0 = w*16 + g, i1 = i0 + 8;
                int j0 = nt*8 + 2*tg, j1 = j0 + 1;
                cs[nt][0] = sf[O_TBL + ((i0>>3)-(j0>>3)+7)*15 + (i0&7)-(j0&7)+7];
                cs[nt][1] = sf[O_TBL + ((i0>>3)-(j1>>3)+7)*15 + (i0&7)-(j1&7)+7];
                cs[nt][2] = sf[O_TBL + ((i1>>3)-(j0>>3)+7)*15 + (i1&7)-(j0&7)+7];
                cs[nt][3] = sf[O_TBL + ((i1>>3)-(j1>>3)+7)*15 + (i1&7)-(j1&7)+7];
            }
            #pragma unroll
            for (int ks = 0; ks < 2; ks++) {
                u32 qh[4], ql[4];
                ldA(qh, su + O_QKH, w*16, ks*8, 36, g, tg);
                ldA(ql, su + O_QKL, w*16, ks*8, 36, g, tg);
                #pragma unroll
                for (int nt = 0; nt < 8; nt++) {
                    u32 bh[2], bl[2];
                    ldBf(bh, su + O_QKH, nt*8, 16 + ks*8, 36, g, tg);
                    ldBf(bl, su + O_QKL, nt*8, 16 + ks*8, 36, g, tg);
                    mma3(cs[nt], qh, ql, bh, bl);
                }
            }
            float mx0 = -1e30f, mx1 = -1e30f;
            #pragma unroll
            for (int nt = 0; nt < 8; nt++) {
                mx0 = fmaxf(mx0, fmaxf(cs[nt][0], cs[nt][1]));
                mx1 = fmaxf(mx1, fmaxf(cs[nt][2], cs[nt][3]));
            }
            mx0 = fmaxf(mx0, __shfl_xor_sync(0xffffffffu, mx0, 1));
            mx0 = fmaxf(mx0, __shfl_xor_sync(0xffffffffu, mx0, 2));
            mx1 = fmaxf(mx1, __shfl_xor_sync(0xffffffffu, mx1, 1));
            mx1 = fmaxf(mx1, __shfl_xor_sync(0xffffffffu, mx1, 2));
            float s0 = 0.f, s1 = 0.f;
            #pragma unroll
            for (int nt = 0; nt < 8; nt++) {
                cs[nt][0] = __expf(cs[nt][0] - mx0);
                cs[nt][1] = __expf(cs[nt][1] - mx0);
                cs[nt][2] = __expf(cs[nt][2] - mx1);
                cs[nt][3] = __expf(cs[nt][3] - mx1);
                s0 += cs[nt][0] + cs[nt][1];
                s1 += cs[nt][2] + cs[nt][3];
            }
            s0 += __shfl_xor_sync(0xffffffffu, s0, 1);
            s0 += __shfl_xor_sync(0xffffffffu, s0, 2);
            s1 += __shfl_xor_sync(0xffffffffu, s1, 1);
            s1 += __shfl_xor_sync(0xffffffffu, s1, 2);
            float i0 = 1.f / s0, i1 = 1.f / s1;
            int r0 = w*16 + g;
            #pragma unroll
            for (int nt = 0; nt < 8; nt++) {
                int col = nt*4 + tg;
                u32 hh, ll;
                sp2(cs[nt][0]*i0, cs[nt][1]*i0, hh, ll);
                su[O_PH + r0*36 + col] = hh; su[O_PL + r0*36 + col] = ll;
                sp2(cs[nt][2]*i1, cs[nt][3]*i1, hh, ll);
                su[O_PH + (r0+8)*36 + col] = hh; su[O_PL + (r0+8)*36 + col] = ll;
            }
        }
        __syncthreads();

        // GEMM3: out_h = P @ V
        {
            float co[2][4];
            #pragma unroll
            for (int i = 0; i < 2; i++) { co[i][0]=co[i][1]=co[i][2]=co[i][3]=0.f; }
            #pragma unroll
            for (int ks = 0; ks < 4; ks++) {
                u32 ph_[4], pl_[4];
                ldA(ph_, su + O_PH, mt3*16, ks*8, 36, g, tg);
                ldA(pl_, su + O_PL, mt3*16, ks*8, 36, g, tg);
                #pragma unroll
                for (int nt = 0; nt < 2; nt++) {
                    u32 bh[2], bl[2];
                    ldBf(bh, su + O_VH, (nb3+nt)*8, ks*8, 36, g, tg);
                    ldBf(bl, su + O_VL, (nb3+nt)*8, ks*8, 36, g, tg);
                    mma3(co[nt], ph_, pl_, bh, bl);
                }
            }
            #pragma unroll
            for (int nt = 0; nt < 2; nt++) {
                int col = h*16 + (nb3+nt)*4 + tg, r0 = mt3*16 + g;
                u32 hh, ll;
                sp2(co[nt][0], co[nt][1], hh, ll);
                su[O_AH + r0*P_X + col] = hh; su[O_AL + r0*P_X + col] = ll;
                sp2(co[nt][2], co[nt][3], hh, ll);
                su[O_AH + (r0+8)*P_X + col] = hh; su[O_AL + (r0+8)*P_X + col] = ll;
            }
        }
        __syncthreads();
    }

    // ---- GEMM4: out = Wout @ att ----
    {
        float c4[2][8][4];
        #pragma unroll
        for (int m = 0; m < 2; m++)
            #pragma unroll
            for (int nt = 0; nt < 8; nt++)
                c4[m][nt][0]=c4[m][nt][1]=c4[m][nt][2]=c4[m][nt][3]=0.f;

        {
            #pragma unroll
            for (int i = 0; i < 2; i++) {
                int id = i*256 + t, r = id >> 1, q = id & 1;
                cp16(su + O_ST + r*12 + q*4,        WoutHi + r*128 + q*4);
                cp16(su + O_ST + 3072 + r*12 + q*4, WoutLo + r*128 + q*4);
            }
            cp_commit();
        }
        for (int ks = 0; ks < 16; ks++) {
            if (ks < 15) {
                int buf = (ks + 1) & 1;
                #pragma unroll
                for (int i = 0; i < 2; i++) {
                    int id = i*256 + t, r = id >> 1, q = id & 1;
                    cp16(su + O_ST + buf*6144 + r*12 + q*4,
                         WoutHi + r*128 + (ks+1)*8 + q*4);
                    cp16(su + O_ST + buf*6144 + 3072 + r*12 + q*4,
                         WoutLo + r*128 + (ks+1)*8 + q*4);
                }
                cp_commit();
                cp_wait1();
            } else cp_wait0();
            __syncthreads();
            const u32* WH = su + O_ST + (ks & 1)*6144;
            const u32* WL = WH + 3072;
            u32 ah[2][4], al[2][4];
            ldA(ah[0], WH, (w*2)*16, 0, 12, g, tg);
            ldA(al[0], WL, (w*2)*16, 0, 12, g, tg);
            ldA(ah[1], WH, (w*2+1)*16, 0, 12, g, tg);
            ldA(al[1], WL, (w*2+1)*16, 0, 12, g, tg);
            #pragma unroll
            for (int nt = 0; nt < 8; nt++) {
                u32 bh[2], bl[2];
                ldBf(bh, su + O_AH, nt*8, ks*8, P_X, g, tg);
                ldBf(bl, su + O_AL, nt*8, ks*8, P_X, g, tg);
                mma3(c4[0][nt], ah[0], al[0], bh, bl);
                mma3(c4[1][nt], ah[1], al[1], bh, bl);
            }
            __syncthreads();
        }
        // C -> smem (pitch 66), +bias
        #pragma unroll
        for (int m = 0; m < 2; m++) {
            int o0 = (w*2 + m)*16 + g;
            float b0v = sf[O_BOUT + o0], b1v = sf[O_BOUT + o0 + 8];
            #pragma unroll
            for (int nt = 0; nt < 8; nt++) {
                int col = nt*8 + 2*tg;
                sf[o0*66 + col]       = c4[m][nt][0] + b0v;
                sf[o0*66 + col + 1]   = c4[m][nt][1] + b0v;
                sf[(o0+8)*66 + col]   = c4[m][nt][2] + b1v;
                sf[(o0+8)*66 + col+1] = c4[m][nt][3] + b1v;
            }
        }
        __syncthreads();
        // coalesced store
        float* ob = out + ((size_t)bb << 24) + (size_t)(wh*8)*256 + ww*8;
        #pragma unroll 4
        for (int i = 0; i < 32; i++) {
            int j = i*512 + t*2;
            int o = j >> 6, pix = j & 63;
            float2 v = *(float2*)&sf[o*66 + pix];
            *(float2*)&ob[(size_t)o*65536 + (size_t)(pix>>3)*256 + (pix&7)] = v;
        }
    }
}

// ---------------- launch ----------------
extern "C" void kernel_launch(void* const* d_in, const int* in_sizes, int n_in,
                              void* d_out, int out_size)
{
    (void)in_sizes; (void)n_in; (void)out_size;
    const float* x     = (const float*)d_in[0];
    const float* g     = (const float*)d_in[1];
    const float* b     = (const float*)d_in[2];
    const float* w_qkv = (const float*)d_in[3];
    const float* w_out = (const float*)d_in[4];
    const float* b_out = (const float*)d_in[5];

    cudaFuncSetAttribute(attn_kernel, cudaFuncAttributeMaxDynamicSharedMemorySize, SMEM_BYTES);

    dpb_kernel<<<289, 64>>>(
        (const float*)d_in[6],  (const float*)d_in[7],
        (const float*)d_in[8],  (const float*)d_in[9],
        (const float*)d_in[10], (const float*)d_in[11],
        (const float*)d_in[12], (const float*)d_in[13],
        (const float*)d_in[14], (const float*)d_in[15],
        (const float*)d_in[16], (const float*)d_in[17],
        (const float*)d_in[18], (const float*)d_in[19]);
    conv_qkv<<<768, 128>>>(w_qkv);
    conv_out<<<256, 128>>>(w_out);
    attn_kernel<<<4096, 256, SMEM_BYTES>>>(x, g, b, b_out, (float*)d_out);
}

// round 4
// speedup vs baseline: 2.8910x; 1.9658x over previous
#include <cuda_runtime.h>
#include <math.h>

#define EPS 1e-5f
#define QK_SCALE 0.17677669529663687f
typedef unsigned int u32;

__device__ float g_table[289];
// fragment-major weight arrays (hi/lo bf16x2 pairs), written by conv kernels
__device__ u32 WB1h[65536], WB1l[65536];   // qk B-frags [h][ks16][nt8][lane32][2]
__device__ u32 WA1h[32768], WA1l[32768];   // v  A-frags [h][ks16][mt2][lane32][4]
__device__ u32 WA4h[32768], WA4l[32768];   // out A-frags [ks16][mt16][lane32][4]

// ---------------- smem layout (u32 offsets) ----------------
#define P_X   132
#define O_XH  0
#define O_XL  8448
#define O_AH  16896
#define O_AL  25344
#define O_QKH 33792
#define O_QKL 36096
#define O_VH  38400
#define O_VL  39552
#define O_PH  40704
#define O_PL  43008
#define O_XF  16896      /* fp32 x temp, overlays AH/AL */
#define O_TBL 47616
#define O_BOUT 47936
#define O_GW  48192
#define O_GB  48448
#define O_RED 48704
#define O_MEAN 49216
#define O_RSTD 49280
#define SMEM_U32 49344
#define SMEM_BYTES (SMEM_U32*4)

// ---------------- helpers ----------------
__device__ __forceinline__ u32 pk2(float lo, float hi){
    u32 r; asm("cvt.rn.bf16x2.f32 %0, %1, %2;" : "=r"(r) : "f"(hi), "f"(lo)); return r;
}
__device__ __forceinline__ void sp2(float x0, float x1, u32& h, u32& l){
    h = pk2(x0, x1);
    float h0 = __uint_as_float(h << 16);
    float h1 = __uint_as_float(h & 0xffff0000u);
    l = pk2(x0 - h0, x1 - h1);
}
__device__ __forceinline__ void mma16(float* c, const u32* a, const u32* b){
    asm volatile("mma.sync.aligned.m16n8k16.row.col.f32.bf16.bf16.f32 "
        "{%0,%1,%2,%3},{%4,%5,%6,%7},{%8,%9},{%0,%1,%2,%3};"
        : "+f"(c[0]),"+f"(c[1]),"+f"(c[2]),"+f"(c[3])
        : "r"(a[0]),"r"(a[1]),"r"(a[2]),"r"(a[3]),"r"(b[0]),"r"(b[1]));
}
__device__ __forceinline__ void ldA(u32* a, const u32* s, int r0, int cp_, int pitch, int g, int tg){
    a[0]=s[(r0+g)*pitch+cp_+tg];   a[1]=s[(r0+g+8)*pitch+cp_+tg];
    a[2]=s[(r0+g)*pitch+cp_+tg+4]; a[3]=s[(r0+g+8)*pitch+cp_+tg+4];
}
__device__ __forceinline__ void ldBf(u32* b, const u32* s, int n0, int cp_, int pitch, int g, int tg){
    b[0]=s[(n0+g)*pitch+cp_+tg];   b[1]=s[(n0+g)*pitch+cp_+tg+4];
}
__device__ __forceinline__ void cp16(void* s, const void* gm){
    u32 sa = (u32)__cvta_generic_to_shared(s);
    asm volatile("cp.async.cg.shared.global [%0], [%1], 16;" :: "r"(sa), "l"(gm));
}
__device__ __forceinline__ void cp_commit(){ asm volatile("cp.async.commit_group;"); }
__device__ __forceinline__ void cp_wait0(){ asm volatile("cp.async.wait_group 0;"); }

// ---------------- weight precompute: fragment-major layouts ----------------
// qk B-frags: b[j] = pairs(row nt*8+g, pair ks*8+tg+j*4), j in {0,1}
__global__ void conv_b1(const float* __restrict__ w){
    int b = blockIdx.x;                  // (h*16+ks)*8+nt
    int h = b >> 7, ks = (b >> 3) & 15, nt = b & 7;
    int t = threadIdx.x;                 // lane*2 + j
    int lane = t >> 1, j = t & 1;
    int g = lane >> 2, tg = lane & 3;
    int r = nt*8 + g;
    int R = (r < 32) ? (h*32 + r) : (256 + h*32 + (r - 32));
    int p = ks*8 + tg + j*4;
    u32 hh, ll;
    sp2(w[R*256 + 2*p], w[R*256 + 2*p + 1], hh, ll);
    WB1h[b*64 + t] = hh;
    WB1l[b*64 + t] = ll;
}
// v A-frags: a[j] = pairs(vrow mt*16+g+(j&1)*8, pair ks*8+tg+(j>>1)*4)
__global__ void conv_a1v(const float* __restrict__ w){
    int b = blockIdx.x;                  // (h*16+ks)*2+mt
    int h = b >> 5, mt = b & 1;
    int t = threadIdx.x;                 // lane*4 + j
    int lane = t >> 2, j = t & 3;
    int g = lane >> 2, tg = lane & 3;
    int vrow = mt*16 + g + (j & 1)*8;
    int R = 512 + h*32 + vrow;
    int ks = (b >> 1) & 15;
    int p = ks*8 + tg + (j >> 1)*4;
    u32 hh, ll;
    sp2(w[R*256 + 2*p], w[R*256 + 2*p + 1], hh, ll);
    WA1h[b*128 + t] = hh;
    WA1l[b*128 + t] = ll;
}
// out-proj A-frags: a[j] = pairs(row mt*16+g+(j&1)*8, pair ks*8+tg+(j>>1)*4)
__global__ void conv_a4(const float* __restrict__ w){
    int b = blockIdx.x;                  // ks*16 + mt
    int ks = b >> 4, mt = b & 15;
    int t = threadIdx.x;
    int lane = t >> 2, j = t & 3;
    int g = lane >> 2, tg = lane & 3;
    int R = mt*16 + g + (j & 1)*8;
    int p = ks*8 + tg + (j >> 1)*4;
    u32 hh, ll;
    sp2(w[R*256 + 2*p], w[R*256 + 2*p + 1], hh, ll);
    WA4h[b*128 + t] = hh;
    WA4l[b*128 + t] = ll;
}

// ---------------- DPB MLP ----------------
__device__ __forceinline__ float blockreduce64(float v, float* red){
    #pragma unroll
    for (int o = 16; o > 0; o >>= 1) v += __shfl_xor_sync(0xffffffffu, v, o);
    int t = threadIdx.x;
    if ((t & 31) == 0) red[t >> 5] = v;
    __syncthreads();
    float r = red[0] + red[1];
    __syncthreads();
    return r;
}
__global__ void dpb_kernel(
    const float* __restrict__ w1, const float* __restrict__ b1,
    const float* __restrict__ g1, const float* __restrict__ bb1,
    const float* __restrict__ w2, const float* __restrict__ b2,
    const float* __restrict__ g2, const float* __restrict__ bb2,
    const float* __restrict__ w3, const float* __restrict__ b3,
    const float* __restrict__ g3, const float* __restrict__ bb3,
    const float* __restrict__ w4, const float* __restrict__ b4)
{
    __shared__ float hs[64];
    __shared__ float red[2];
    int r = blockIdx.x, j = threadIdx.x;
    float r0 = (float)(r / 17 - 8), r1 = (float)(r % 17 - 8);
    float v = r0 * w1[j] + r1 * w1[64 + j] + b1[j];
    float m = blockreduce64(v, red) * (1.f/64.f);
    float d = v - m;
    float var = blockreduce64(d*d, red) * (1.f/64.f);
    v = fmaxf(d * rsqrtf(var + EPS) * g1[j] + bb1[j], 0.f);
    hs[j] = v; __syncthreads();
    float a = b2[j];
    #pragma unroll 8
    for (int k = 0; k < 64; k++) a += hs[k] * w2[k*64 + j];
    m = blockreduce64(a, red) * (1.f/64.f);
    d = a - m;
    var = blockreduce64(d*d, red) * (1.f/64.f);
    a = fmaxf(d * rsqrtf(var + EPS) * g2[j] + bb2[j], 0.f);
    __syncthreads(); hs[j] = a; __syncthreads();
    a = b3[j];
    #pragma unroll 8
    for (int k = 0; k < 64; k++) a += hs[k] * w3[k*64 + j];
    m = blockreduce64(a, red) * (1.f/64.f);
    d = a - m;
    var = blockreduce64(d*d, red) * (1.f/64.f);
    a = fmaxf(d * rsqrtf(var + EPS) * g3[j] + bb3[j], 0.f);
    __syncthreads(); hs[j] = a; __syncthreads();
    float c = blockreduce64(hs[j] * w4[j], red);
    if (j == 0) g_table[r] = c + b4[0];
}

// ---------------- fused attention ----------------
__global__ __launch_bounds__(256, 1) void attn_kernel(
    const float* __restrict__ x, const float* __restrict__ gw, const float* __restrict__ gb,
    const float* __restrict__ b_out, float* __restrict__ out)
{
    extern __shared__ u32 su[];
    float* sf = (float*)su;
    const int t = threadIdx.x, lane = t & 31, w = t >> 5;
    const int g = lane >> 2, tg = lane & 3;
    const int wid = blockIdx.x;
    const int bb = wid >> 10, wh = (wid >> 5) & 31, ww = wid & 31;
    const float* xb = x + ((size_t)bb << 24) + (size_t)(wh * 8) * 256 + ww * 8;

    if (t < 289) sf[O_TBL + t] = g_table[t];
    sf[O_BOUT + t] = b_out[t];
    sf[O_GW + t] = gw[t];
    sf[O_GB + t] = gb[t];

    // ---- load x (fp32) ----
    #pragma unroll
    for (int i = 0; i < 8; i++) {
        int s = i * 256 + t, d = s >> 3, ph = s & 7;
        const float* src = xb + (size_t)d * 65536 + (size_t)ph * 256;
        float* dst = sf + O_XF + d * 68 + ph * 8;
        cp16(dst, src); cp16(dst + 4, src + 4);
    }
    cp_commit(); cp_wait0(); __syncthreads();

    // ---- LN stats ----
    {
        int pix = t & 63, q4 = t >> 6;
        float s = 0.f, ss = 0.f;
        #pragma unroll 8
        for (int d = q4*64; d < q4*64 + 64; d++) {
            float v = sf[O_XF + d*68 + pix]; s += v; ss += v*v;
        }
        sf[O_RED + t] = s; sf[O_RED + 256 + t] = ss;
        __syncthreads();
        if (t < 64) {
            float s0 = sf[O_RED+t] + sf[O_RED+64+t] + sf[O_RED+128+t] + sf[O_RED+192+t];
            float s1 = sf[O_RED+256+t] + sf[O_RED+320+t] + sf[O_RED+384+t] + sf[O_RED+448+t];
            float mn = s0 * (1.f/256.f);
            float vr = s1 * (1.f/256.f) - mn*mn;
            sf[O_MEAN + t] = mn;
            sf[O_RSTD + t] = rsqrtf(vr + EPS);
        }
        __syncthreads();
    }
    // ---- normalize + split to pairs ----
    {
        int pix = t & 63, cb = (t >> 6) * 64;
        float mn = sf[O_MEAN + pix], rs = sf[O_RSTD + pix];
        #pragma unroll 8
        for (int p = 0; p < 32; p++) {
            int c = cb + 2*p;
            float v0 = (sf[O_XF + c*68 + pix] - mn)*rs*sf[O_GW+c] + sf[O_GB+c];
            float v1 = (sf[O_XF + (c+1)*68 + pix] - mn)*rs*sf[O_GW+c+1] + sf[O_GB+c+1];
            u32 hh, ll; sp2(v0, v1, hh, ll);
            su[O_XH + pix*P_X + cb/2 + p] = hh;
            su[O_XL + pix*P_X + cb/2 + p] = ll;
        }
        __syncthreads();
    }

    const int mt  = w >> 1,  nb  = (w & 1) * 4;   // G1 qk tiles
    const int vmt = w & 1,   vnb = (w >> 1) * 2;  // G1 v tiles
    const int mt3 = w >> 1,  nb3 = (w & 1) * 2;   // GEMM3 tiles

    // ---- per-head ----
    for (int h = 0; h < 8; h++) {
        // GEMM1: dual-chain accumulators, weights streamed from L2 frag arrays
        float cqh_[4][4], cql_[4][4], cvh_[2][4], cvl_[2][4];
        #pragma unroll
        for (int i = 0; i < 4; i++)
            #pragma unroll
            for (int q = 0; q < 4; q++) { cqh_[i][q]=0.f; cql_[i][q]=0.f; }
        #pragma unroll
        for (int i = 0; i < 2; i++)
            #pragma unroll
            for (int q = 0; q < 4; q++) { cvh_[i][q]=0.f; cvl_[i][q]=0.f; }

        #pragma unroll 4
        for (int ks = 0; ks < 16; ks++) {
            u32 axh[4], axl[4];
            ldA(axh, su + O_XH, mt*16, ks*8, P_X, g, tg);
            ldA(axl, su + O_XL, mt*16, ks*8, P_X, g, tg);
            uint4 awh4 = *(const uint4*)&WA1h[((h*16+ks)*2+vmt)*128 + lane*4];
            uint4 awl4 = *(const uint4*)&WA1l[((h*16+ks)*2+vmt)*128 + lane*4];
            #pragma unroll
            for (int nt = 0; nt < 4; nt++) {
                uint2 b2h = *(const uint2*)&WB1h[((h*16+ks)*8+nb+nt)*64 + lane*2];
                uint2 b2l = *(const uint2*)&WB1l[((h*16+ks)*8+nb+nt)*64 + lane*2];
                u32 bh[2] = {b2h.x, b2h.y}, bl[2] = {b2l.x, b2l.y};
                mma16(cqh_[nt], axh, bh);
                mma16(cql_[nt], axl, bh);
                mma16(cql_[nt], axh, bl);
            }
            u32 awh[4] = {awh4.x, awh4.y, awh4.z, awh4.w};
            u32 awl[4] = {awl4.x, awl4.y, awl4.z, awl4.w};
            #pragma unroll
            for (int vt = 0; vt < 2; vt++) {
                u32 bxh[2], bxl[2];
                ldBf(bxh, su + O_XH, (vnb+vt)*8, ks*8, P_X, g, tg);
                ldBf(bxl, su + O_XL, (vnb+vt)*8, ks*8, P_X, g, tg);
                mma16(cvh_[vt], awh, bxh);
                mma16(cvl_[vt], awl, bxh);
                mma16(cvl_[vt], awh, bxl);
            }
        }
        // epilogue: q/k (transposed pairs along d) and v (pairs along pix)
        #pragma unroll
        for (int nt = 0; nt < 4; nt++) {
            float c0 = cqh_[nt][0] + cql_[nt][0];
            float c1 = cqh_[nt][1] + cql_[nt][1];
            float c2 = cqh_[nt][2] + cql_[nt][2];
            float c3 = cqh_[nt][3] + cql_[nt][3];
            int ch0 = (nb+nt)*8 + 2*tg;
            float sc = (ch0 < 32) ? QK_SCALE : 1.f;
            int col = (nb+nt)*4 + tg, p0 = mt*16 + g;
            u32 hh, ll;
            sp2(c0*sc, c1*sc, hh, ll);
            su[O_QKH + p0*36 + col] = hh; su[O_QKL + p0*36 + col] = ll;
            sp2(c2*sc, c3*sc, hh, ll);
            su[O_QKH + (p0+8)*36 + col] = hh; su[O_QKL + (p0+8)*36 + col] = ll;
        }
        #pragma unroll
        for (int vt = 0; vt < 2; vt++) {
            float c0 = cvh_[vt][0] + cvl_[vt][0];
            float c1 = cvh_[vt][1] + cvl_[vt][1];
            float c2 = cvh_[vt][2] + cvl_[vt][2];
            float c3 = cvh_[vt][3] + cvl_[vt][3];
            int col = (vnb+vt)*4 + tg, r0 = vmt*16 + g;
            u32 hh, ll;
            sp2(c0, c1, hh, ll);
            su[O_VH + r0*36 + col] = hh; su[O_VL + r0*36 + col] = ll;
            sp2(c2, c3, hh, ll);
            su[O_VH + (r0+8)*36 + col] = hh; su[O_VL + (r0+8)*36 + col] = ll;
        }
        __syncthreads();

        // GEMM2 + softmax (warps 0..3), dual-chain
        if (w < 4) {
            float csh_[8][4], csl_[8][4];
            #pragma unroll
            for (int nt = 0; nt < 8; nt++) {
                int i0 = w*16 + g, i1 = i0 + 8;
                int j0 = nt*8 + 2*tg, j1 = j0 + 1;
                csh_[nt][0] = sf[O_TBL + ((i0>>3)-(j0>>3)+7)*15 + (i0&7)-(j0&7)+7];
                csh_[nt][1] = sf[O_TBL + ((i0>>3)-(j1>>3)+7)*15 + (i0&7)-(j1&7)+7];
                csh_[nt][2] = sf[O_TBL + ((i1>>3)-(j0>>3)+7)*15 + (i1&7)-(j0&7)+7];
                csh_[nt][3] = sf[O_TBL + ((i1>>3)-(j1>>3)+7)*15 + (i1&7)-(j1&7)+7];
                csl_[nt][0]=csl_[nt][1]=csl_[nt][2]=csl_[nt][3]=0.f;
            }
            #pragma unroll
            for (int ks = 0; ks < 2; ks++) {
                u32 qh[4], ql[4];
                ldA(qh, su + O_QKH, w*16, ks*8, 36, g, tg);
                ldA(ql, su + O_QKL, w*16, ks*8, 36, g, tg);
                #pragma unroll
                for (int nt = 0; nt < 8; nt++) {
                    u32 bh[2], bl[2];
                    ldBf(bh, su + O_QKH, nt*8, 16 + ks*8, 36, g, tg);
                    ldBf(bl, su + O_QKL, nt*8, 16 + ks*8, 36, g, tg);
                    mma16(csh_[nt], qh, bh);
                    mma16(csl_[nt], ql, bh);
                    mma16(csl_[nt], qh, bl);
                }
            }
            float cs[8][4];
            #pragma unroll
            for (int nt = 0; nt < 8; nt++)
                #pragma unroll
                for (int q = 0; q < 4; q++) cs[nt][q] = csh_[nt][q] + csl_[nt][q];

            float mx0 = -1e30f, mx1 = -1e30f;
            #pragma unroll
            for (int nt = 0; nt < 8; nt++) {
                mx0 = fmaxf(mx0, fmaxf(cs[nt][0], cs[nt][1]));
                mx1 = fmaxf(mx1, fmaxf(cs[nt][2], cs[nt][3]));
            }
            mx0 = fmaxf(mx0, __shfl_xor_sync(0xffffffffu, mx0, 1));
            mx0 = fmaxf(mx0, __shfl_xor_sync(0xffffffffu, mx0, 2));
            mx1 = fmaxf(mx1, __shfl_xor_sync(0xffffffffu, mx1, 1));
            mx1 = fmaxf(mx1, __shfl_xor_sync(0xffffffffu, mx1, 2));
            float s0 = 0.f, s1 = 0.f;
            #pragma unroll
            for (int nt = 0; nt < 8; nt++) {
                cs[nt][0] = __expf(cs[nt][0] - mx0);
                cs[nt][1] = __expf(cs[nt][1] - mx0);
                cs[nt][2] = __expf(cs[nt][2] - mx1);
                cs[nt][3] = __expf(cs[nt][3] - mx1);
                s0 += cs[nt][0] + cs[nt][1];
                s1 += cs[nt][2] + cs[nt][3];
            }
            s0 += __shfl_xor_sync(0xffffffffu, s0, 1);
            s0 += __shfl_xor_sync(0xffffffffu, s0, 2);
            s1 += __shfl_xor_sync(0xffffffffu, s1, 1);
            s1 += __shfl_xor_sync(0xffffffffu, s1, 2);
            float i0 = 1.f / s0, i1 = 1.f / s1;
            int r0 = w*16 + g;
            #pragma unroll
            for (int nt = 0; nt < 8; nt++) {
                int col = nt*4 + tg;
                u32 hh, ll;
                sp2(cs[nt][0]*i0, cs[nt][1]*i0, hh, ll);
                su[O_PH + r0*36 + col] = hh; su[O_PL + r0*36 + col] = ll;
                sp2(cs[nt][2]*i1, cs[nt][3]*i1, hh, ll);
                su[O_PH + (r0+8)*36 + col] = hh; su[O_PL + (r0+8)*36 + col] = ll;
            }
        }
        __syncthreads();

        // GEMM3: out_h = P @ V (dual-chain)
        {
            float coh_[2][4], col2_[2][4];
            #pragma unroll
            for (int i = 0; i < 2; i++)
                #pragma unroll
                for (int q = 0; q < 4; q++) { coh_[i][q]=0.f; col2_[i][q]=0.f; }
            #pragma unroll
            for (int ks = 0; ks < 4; ks++) {
                u32 ph_[4], pl_[4];
                ldA(ph_, su + O_PH, mt3*16, ks*8, 36, g, tg);
                ldA(pl_, su + O_PL, mt3*16, ks*8, 36, g, tg);
                #pragma unroll
                for (int nt = 0; nt < 2; nt++) {
                    u32 bh[2], bl[2];
                    ldBf(bh, su + O_VH, (nb3+nt)*8, ks*8, 36, g, tg);
                    ldBf(bl, su + O_VL, (nb3+nt)*8, ks*8, 36, g, tg);
                    mma16(coh_[nt], ph_, bh);
                    mma16(col2_[nt], pl_, bh);
                    mma16(col2_[nt], ph_, bl);
                }
            }
            #pragma unroll
            for (int nt = 0; nt < 2; nt++) {
                float c0 = coh_[nt][0] + col2_[nt][0];
                float c1 = coh_[nt][1] + col2_[nt][1];
                float c2 = coh_[nt][2] + col2_[nt][2];
                float c3 = coh_[nt][3] + col2_[nt][3];
                int col = h*16 + (nb3+nt)*4 + tg, r0 = mt3*16 + g;
                u32 hh, ll;
                sp2(c0, c1, hh, ll);
                su[O_AH + r0*P_X + col] = hh; su[O_AL + r0*P_X + col] = ll;
                sp2(c2, c3, hh, ll);
                su[O_AH + (r0+8)*P_X + col] = hh; su[O_AL + (r0+8)*P_X + col] = ll;
            }
        }
        __syncthreads();
    }

    // ---- GEMM4: out = Wout @ att  (A-frags from L2, no barriers in k-loop) ----
    {
        float c4[2][8][4];
        #pragma unroll
        for (int m = 0; m < 2; m++)
            #pragma unroll
            for (int nt = 0; nt < 8; nt++)
                c4[m][nt][0]=c4[m][nt][1]=c4[m][nt][2]=c4[m][nt][3]=0.f;

        #pragma unroll 2
        for (int ks = 0; ks < 16; ks++) {
            u32 ah[2][4], al[2][4];
            #pragma unroll
            for (int m = 0; m < 2; m++) {
                uint4 vh4 = *(const uint4*)&WA4h[(ks*16 + (w*2+m))*128 + lane*4];
                uint4 vl4 = *(const uint4*)&WA4l[(ks*16 + (w*2+m))*128 + lane*4];
                ah[m][0]=vh4.x; ah[m][1]=vh4.y; ah[m][2]=vh4.z; ah[m][3]=vh4.w;
                al[m][0]=vl4.x; al[m][1]=vl4.y; al[m][2]=vl4.z; al[m][3]=vl4.w;
            }
            #pragma unroll
            for (int nt = 0; nt < 8; nt++) {
                u32 bh[2], bl[2];
                ldBf(bh, su + O_AH, nt*8, ks*8, P_X, g, tg);
                ldBf(bl, su + O_AL, nt*8, ks*8, P_X, g, tg);
                #pragma unroll
                for (int m = 0; m < 2; m++) {
                    mma16(c4[m][nt], ah[m], bh);
                    mma16(c4[m][nt], al[m], bh);
                    mma16(c4[m][nt], ah[m], bl);
                }
            }
        }
        // C -> smem (pitch 66), +bias   (writes land in XH/XL region, now dead)
        #pragma unroll
        for (int m = 0; m < 2; m++) {
            int o0 = (w*2 + m)*16 + g;
            float b0v = sf[O_BOUT + o0], b1v = sf[O_BOUT + o0 + 8];
            #pragma unroll
            for (int nt = 0; nt < 8; nt++) {
                int col = nt*8 + 2*tg;
                sf[o0*66 + col]       = c4[m][nt][0] + b0v;
                sf[o0*66 + col + 1]   = c4[m][nt][1] + b0v;
                sf[(o0+8)*66 + col]   = c4[m][nt][2] + b1v;
                sf[(o0+8)*66 + col+1] = c4[m][nt][3] + b1v;
            }
        }
        __syncthreads();
        // coalesced store
        float* ob = out + ((size_t)bb << 24) + (size_t)(wh*8)*256 + ww*8;
        #pragma unroll 4
        for (int i = 0; i < 32; i++) {
            int j = i*512 + t*2;
            int o = j >> 6, pix = j & 63;
            float2 v = *(float2*)&sf[o*66 + pix];
            *(float2*)&ob[(size_t)o*65536 + (size_t)(pix>>3)*256 + (pix&7)] = v;
        }
    }
}

// ---------------- launch ----------------
extern "C" void kernel_launch(void* const* d_in, const int* in_sizes, int n_in,
                              void* d_out, int out_size)
{
    (void)in_sizes; (void)n_in; (void)out_size;
    const float* x     = (const float*)d_in[0];
    const float* g     = (const float*)d_in[1];
    const float* b     = (const float*)d_in[2];
    const float* w_qkv = (const float*)d_in[3];
    const float* w_out = (const float*)d_in[4];
    const float* b_out = (const float*)d_in[5];

    cudaFuncSetAttribute(attn_kernel, cudaFuncAttributeMaxDynamicSharedMemorySize, SMEM_BYTES);

    dpb_kernel<<<289, 64>>>(
        (const float*)d_in[6],  (const float*)d_in[7],
        (const float*)d_in[8],  (const float*)d_in[9],
        (const float*)d_in[10], (const float*)d_in[11],
        (const float*)d_in[12], (const float*)d_in[13],
        (const float*)d_in[14], (const float*)d_in[15],
        (const float*)d_in[16], (const float*)d_in[17],
        (const float*)d_in[18], (const float*)d_in[19]);
    conv_b1<<<1024, 64>>>(w_qkv);
    conv_a1v<<<256, 128>>>(w_qkv);
    conv_a4<<<256, 128>>>(w_out);
    attn_kernel<<<4096, 256, SMEM_BYTES>>>(x, g, b, b_out, (float*)d_out);
}

// round 5
// speedup vs baseline: 2.8980x; 1.0024x over previous
#include <cuda_runtime.h>
#include <math.h>

#define EPS 1e-5f
#define QK_SCALE 0.17677669529663687f
typedef unsigned int u32;

__device__ float g_table[289];
// fragment-major weight arrays (hi/lo bf16x2 pairs), written by conv kernels
__device__ u32 WB1h[65536], WB1l[65536];   // qk B-frags [h][ks16][nt8][lane32][2]
__device__ u32 WA1h[32768], WA1l[32768];   // v  A-frags [h][ks16][mt2][lane32][4]
__device__ u32 WA4h[32768], WA4l[32768];   // out A-frags [ks16][mt16][lane32][4]

// ---------------- smem layout (u32 offsets) ----------------
#define P_X   132
#define O_XH  0
#define O_XL  8448
#define O_AH  16896
#define O_AL  25344
#define O_QKH 33792
#define O_QKL 36096
#define O_VH  38400
#define O_VL  39552
#define O_PH  40704
#define O_PL  43008
#define O_XF  16896      /* fp32 x temp, overlays AH/AL */
#define O_TBL 47616
#define O_BOUT 47936
#define O_GW  48192
#define O_GB  48448
#define O_RED 48704
#define O_MEAN 49216
#define O_RSTD 49280
#define SMEM_U32 49344
#define SMEM_BYTES (SMEM_U32*4)

// ---------------- helpers ----------------
__device__ __forceinline__ u32 pk2(float lo, float hi){
    u32 r; asm("cvt.rn.bf16x2.f32 %0, %1, %2;" : "=r"(r) : "f"(hi), "f"(lo)); return r;
}
__device__ __forceinline__ void sp2(float x0, float x1, u32& h, u32& l){
    h = pk2(x0, x1);
    float h0 = __uint_as_float(h << 16);
    float h1 = __uint_as_float(h & 0xffff0000u);
    l = pk2(x0 - h0, x1 - h1);
}
__device__ __forceinline__ void mma16(float* c, const u32* a, const u32* b){
    asm volatile("mma.sync.aligned.m16n8k16.row.col.f32.bf16.bf16.f32 "
        "{%0,%1,%2,%3},{%4,%5,%6,%7},{%8,%9},{%0,%1,%2,%3};"
        : "+f"(c[0]),"+f"(c[1]),"+f"(c[2]),"+f"(c[3])
        : "r"(a[0]),"r"(a[1]),"r"(a[2]),"r"(a[3]),"r"(b[0]),"r"(b[1]));
}
__device__ __forceinline__ void ldA(u32* a, const u32* s, int r0, int cp_, int pitch, int g, int tg){
    a[0]=s[(r0+g)*pitch+cp_+tg];   a[1]=s[(r0+g+8)*pitch+cp_+tg];
    a[2]=s[(r0+g)*pitch+cp_+tg+4]; a[3]=s[(r0+g+8)*pitch+cp_+tg+4];
}
__device__ __forceinline__ void ldBf(u32* b, const u32* s, int n0, int cp_, int pitch, int g, int tg){
    b[0]=s[(n0+g)*pitch+cp_+tg];   b[1]=s[(n0+g)*pitch+cp_+tg+4];
}
__device__ __forceinline__ void cp16(void* s, const void* gm){
    u32 sa = (u32)__cvta_generic_to_shared(s);
    asm volatile("cp.async.cg.shared.global [%0], [%1], 16;" :: "r"(sa), "l"(gm));
}
__device__ __forceinline__ void cp_commit(){ asm volatile("cp.async.commit_group;"); }
__device__ __forceinline__ void cp_wait0(){ asm volatile("cp.async.wait_group 0;"); }

// ---------------- weight precompute: fragment-major layouts ----------------
// qk B-frags: b[j] = pairs(row nt*8+g, pair ks*8+tg+j*4), j in {0,1}
__global__ void conv_b1(const float* __restrict__ w){
    int b = blockIdx.x;                  // (h*16+ks)*8+nt
    int h = b >> 7, ks = (b >> 3) & 15, nt = b & 7;
    int t = threadIdx.x;                 // lane*2 + j
    int lane = t >> 1, j = t & 1;
    int g = lane >> 2, tg = lane & 3;
    int r = nt*8 + g;
    int R = (r < 32) ? (h*32 + r) : (256 + h*32 + (r - 32));
    int p = ks*8 + tg + j*4;
    u32 hh, ll;
    sp2(w[R*256 + 2*p], w[R*256 + 2*p + 1], hh, ll);
    WB1h[b*64 + t] = hh;
    WB1l[b*64 + t] = ll;
}
// v A-frags: a[j] = pairs(vrow mt*16+g+(j&1)*8, pair ks*8+tg+(j>>1)*4)
__global__ void conv_a1v(const float* __restrict__ w){
    int b = blockIdx.x;                  // (h*16+ks)*2+mt
    int h = b >> 5, mt = b & 1;
    int t = threadIdx.x;                 // lane*4 + j
    int lane = t >> 2, j = t & 3;
    int g = lane >> 2, tg = lane & 3;
    int vrow = mt*16 + g + (j & 1)*8;
    int R = 512 + h*32 + vrow;
    int ks = (b >> 1) & 15;
    int p = ks*8 + tg + (j >> 1)*4;
    u32 hh, ll;
    sp2(w[R*256 + 2*p], w[R*256 + 2*p + 1], hh, ll);
    WA1h[b*128 + t] = hh;
    WA1l[b*128 + t] = ll;
}
// out-proj A-frags: a[j] = pairs(row mt*16+g+(j&1)*8, pair ks*8+tg+(j>>1)*4)
__global__ void conv_a4(const float* __restrict__ w){
    int b = blockIdx.x;                  // ks*16 + mt
    int ks = b >> 4, mt = b & 15;
    int t = threadIdx.x;
    int lane = t >> 2, j = t & 3;
    int g = lane >> 2, tg = lane & 3;
    int R = mt*16 + g + (j & 1)*8;
    int p = ks*8 + tg + (j >> 1)*4;
    u32 hh, ll;
    sp2(w[R*256 + 2*p], w[R*256 + 2*p + 1], hh, ll);
    WA4h[b*128 + t] = hh;
    WA4l[b*128 + t] = ll;
}

// ---------------- DPB MLP ----------------
__device__ __forceinline__ float blockreduce64(float v, float* red){
    #pragma unroll
    for (int o = 16; o > 0; o >>= 1) v += __shfl_xor_sync(0xffffffffu, v, o);
    int t = threadIdx.x;
    if ((t & 31) == 0) red[t >> 5] = v;
    __syncthreads();
    float r = red[0] + red[1];
    __syncthreads();
    return r;
}
__global__ void dpb_kernel(
    const float* __restrict__ w1, const float* __restrict__ b1,
    const float* __restrict__ g1, const float* __restrict__ bb1,
    const float* __restrict__ w2, const float* __restrict__ b2,
    const float* __restrict__ g2, const float* __restrict__ bb2,
    const float* __restrict__ w3, const float* __restrict__ b3,
    const float* __restrict__ g3, const float* __restrict__ bb3,
    const float* __restrict__ w4, const float* __restrict__ b4)
{
    __shared__ float hs[64];
    __shared__ float red[2];
    int r = blockIdx.x, j = threadIdx.x;
    float r0 = (float)(r / 17 - 8), r1 = (float)(r % 17 - 8);
    float v = r0 * w1[j] + r1 * w1[64 + j] + b1[j];
    float m = blockreduce64(v, red) * (1.f/64.f);
    float d = v - m;
    float var = blockreduce64(d*d, red) * (1.f/64.f);
    v = fmaxf(d * rsqrtf(var + EPS) * g1[j] + bb1[j], 0.f);
    hs[j] = v; __syncthreads();
    float a = b2[j];
    #pragma unroll 8
    for (int k = 0; k < 64; k++) a += hs[k] * w2[k*64 + j];
    m = blockreduce64(a, red) * (1.f/64.f);
    d = a - m;
    var = blockreduce64(d*d, red) * (1.f/64.f);
    a = fmaxf(d * rsqrtf(var + EPS) * g2[j] + bb2[j], 0.f);
    __syncthreads(); hs[j] = a; __syncthreads();
    a = b3[j];
    #pragma unroll 8
    for (int k = 0; k < 64; k++) a += hs[k] * w3[k*64 + j];
    m = blockreduce64(a, red) * (1.f/64.f);
    d = a - m;
    var = blockreduce64(d*d, red) * (1.f/64.f);
    a = fmaxf(d * rsqrtf(var + EPS) * g3[j] + bb3[j], 0.f);
    __syncthreads(); hs[j] = a; __syncthreads();
    float c = blockreduce64(hs[j] * w4[j], red);
    if (j == 0) g_table[r] = c + b4[0];
}

// ---------------- fused attention ----------------
__global__ __launch_bounds__(256, 1) void attn_kernel(
    const float* __restrict__ x, const float* __restrict__ gw, const float* __restrict__ gb,
    const float* __restrict__ b_out, float* __restrict__ out)
{
    extern __shared__ u32 su[];
    float* sf = (float*)su;
    const int t = threadIdx.x, lane = t & 31, w = t >> 5;
    const int g = lane >> 2, tg = lane & 3;
    const int wid = blockIdx.x;
    const int bb = wid >> 10, wh = (wid >> 5) & 31, ww = wid & 31;
    const float* xb = x + ((size_t)bb << 24) + (size_t)(wh * 8) * 256 + ww * 8;

    if (t < 289) sf[O_TBL + t] = g_table[t];
    sf[O_BOUT + t] = b_out[t];
    sf[O_GW + t] = gw[t];
    sf[O_GB + t] = gb[t];

    // ---- load x (fp32) ----
    #pragma unroll
    for (int i = 0; i < 8; i++) {
        int s = i * 256 + t, d = s >> 3, ph = s & 7;
        const float* src = xb + (size_t)d * 65536 + (size_t)ph * 256;
        float* dst = sf + O_XF + d * 68 + ph * 8;
        cp16(dst, src); cp16(dst + 4, src + 4);
    }
    cp_commit(); cp_wait0(); __syncthreads();

    // ---- LN stats ----
    {
        int pix = t & 63, q4 = t >> 6;
        float s = 0.f, ss = 0.f;
        #pragma unroll 8
        for (int d = q4*64; d < q4*64 + 64; d++) {
            float v = sf[O_XF + d*68 + pix]; s += v; ss += v*v;
        }
        sf[O_RED + t] = s; sf[O_RED + 256 + t] = ss;
        __syncthreads();
        if (t < 64) {
            float s0 = sf[O_RED+t] + sf[O_RED+64+t] + sf[O_RED+128+t] + sf[O_RED+192+t];
            float s1 = sf[O_RED+256+t] + sf[O_RED+320+t] + sf[O_RED+384+t] + sf[O_RED+448+t];
            float mn = s0 * (1.f/256.f);
            float vr = s1 * (1.f/256.f) - mn*mn;
            sf[O_MEAN + t] = mn;
            sf[O_RSTD + t] = rsqrtf(vr + EPS);
        }
        __syncthreads();
    }
    // ---- normalize + split to pairs ----
    {
        int pix = t & 63, cb = (t >> 6) * 64;
        float mn = sf[O_MEAN + pix], rs = sf[O_RSTD + pix];
        #pragma unroll 8
        for (int p = 0; p < 32; p++) {
            int c = cb + 2*p;
            float v0 = (sf[O_XF + c*68 + pix] - mn)*rs*sf[O_GW+c] + sf[O_GB+c];
            float v1 = (sf[O_XF + (c+1)*68 + pix] - mn)*rs*sf[O_GW+c+1] + sf[O_GB+c+1];
            u32 hh, ll; sp2(v0, v1, hh, ll);
            su[O_XH + pix*P_X + cb/2 + p] = hh;
            su[O_XL + pix*P_X + cb/2 + p] = ll;
        }
        __syncthreads();
    }

    const int mt  = w >> 1,  nb  = (w & 1) * 4;   // G1 qk tiles
    const int vmt = w & 1,   vnb = (w >> 1) * 2;  // G1 v tiles
    const int mt3 = w >> 1,  nb3 = (w & 1) * 2;   // GEMM3 tiles

    // ---- per-head ----
    for (int h = 0; h < 8; h++) {
        // GEMM1: dual-chain accumulators, weights streamed from L2 frag arrays
        float cqh_[4][4], cql_[4][4], cvh_[2][4], cvl_[2][4];
        #pragma unroll
        for (int i = 0; i < 4; i++)
            #pragma unroll
            for (int q = 0; q < 4; q++) { cqh_[i][q]=0.f; cql_[i][q]=0.f; }
        #pragma unroll
        for (int i = 0; i < 2; i++)
            #pragma unroll
            for (int q = 0; q < 4; q++) { cvh_[i][q]=0.f; cvl_[i][q]=0.f; }

        #pragma unroll 4
        for (int ks = 0; ks < 16; ks++) {
            u32 axh[4], axl[4];
            ldA(axh, su + O_XH, mt*16, ks*8, P_X, g, tg);
            ldA(axl, su + O_XL, mt*16, ks*8, P_X, g, tg);
            uint4 awh4 = *(const uint4*)&WA1h[((h*16+ks)*2+vmt)*128 + lane*4];
            uint4 awl4 = *(const uint4*)&WA1l[((h*16+ks)*2+vmt)*128 + lane*4];
            #pragma unroll
            for (int nt = 0; nt < 4; nt++) {
                uint2 b2h = *(const uint2*)&WB1h[((h*16+ks)*8+nb+nt)*64 + lane*2];
                uint2 b2l = *(const uint2*)&WB1l[((h*16+ks)*8+nb+nt)*64 + lane*2];
                u32 bh[2] = {b2h.x, b2h.y}, bl[2] = {b2l.x, b2l.y};
                mma16(cqh_[nt], axh, bh);
                mma16(cql_[nt], axl, bh);
                mma16(cql_[nt], axh, bl);
            }
            u32 awh[4] = {awh4.x, awh4.y, awh4.z, awh4.w};
            u32 awl[4] = {awl4.x, awl4.y, awl4.z, awl4.w};
            #pragma unroll
            for (int vt = 0; vt < 2; vt++) {
                u32 bxh[2], bxl[2];
                ldBf(bxh, su + O_XH, (vnb+vt)*8, ks*8, P_X, g, tg);
                ldBf(bxl, su + O_XL, (vnb+vt)*8, ks*8, P_X, g, tg);
                mma16(cvh_[vt], awh, bxh);
                mma16(cvl_[vt], awl, bxh);
                mma16(cvl_[vt], awh, bxl);
            }
        }
        // epilogue: q/k (transposed pairs along d) and v (pairs along pix)
        #pragma unroll
        for (int nt = 0; nt < 4; nt++) {
            float c0 = cqh_[nt][0] + cql_[nt][0];
            float c1 = cqh_[nt][1] + cql_[nt][1];
            float c2 = cqh_[nt][2] + cql_[nt][2];
            float c3 = cqh_[nt][3] + cql_[nt][3];
            int ch0 = (nb+nt)*8 + 2*tg;
            float sc = (ch0 < 32) ? QK_SCALE : 1.f;
            int col = (nb+nt)*4 + tg, p0 = mt*16 + g;
            u32 hh, ll;
            sp2(c0*sc, c1*sc, hh, ll);
            su[O_QKH + p0*36 + col] = hh; su[O_QKL + p0*36 + col] = ll;
            sp2(c2*sc, c3*sc, hh, ll);
            su[O_QKH + (p0+8)*36 + col] = hh; su[O_QKL + (p0+8)*36 + col] = ll;
        }
        #pragma unroll
        for (int vt = 0; vt < 2; vt++) {
            float c0 = cvh_[vt][0] + cvl_[vt][0];
            float c1 = cvh_[vt][1] + cvl_[vt][1];
            float c2 = cvh_[vt][2] + cvl_[vt][2];
            float c3 = cvh_[vt][3] + cvl_[vt][3];
            int col = (vnb+vt)*4 + tg, r0 = vmt*16 + g;
            u32 hh, ll;
            sp2(c0, c1, hh, ll);
            su[O_VH + r0*36 + col] = hh; su[O_VL + r0*36 + col] = ll;
            sp2(c2, c3, hh, ll);
            su[O_VH + (r0+8)*36 + col] = hh; su[O_VL + (r0+8)*36 + col] = ll;
        }
        __syncthreads();

        // GEMM2 + softmax (warps 0..3), dual-chain
        if (w < 4) {
            float csh_[8][4], csl_[8][4];
            #pragma unroll
            for (int nt = 0; nt < 8; nt++) {
                int i0 = w*16 + g, i1 = i0 + 8;
                int j0 = nt*8 + 2*tg, j1 = j0 + 1;
                csh_[nt][0] = sf[O_TBL + ((i0>>3)-(j0>>3)+7)*15 + (i0&7)-(j0&7)+7];
                csh_[nt][1] = sf[O_TBL + ((i0>>3)-(j1>>3)+7)*15 + (i0&7)-(j1&7)+7];
                csh_[nt][2] = sf[O_TBL + ((i1>>3)-(j0>>3)+7)*15 + (i1&7)-(j0&7)+7];
                csh_[nt][3] = sf[O_TBL + ((i1>>3)-(j1>>3)+7)*15 + (i1&7)-(j1&7)+7];
                csl_[nt][0]=csl_[nt][1]=csl_[nt][2]=csl_[nt][3]=0.f;
            }
            #pragma unroll
            for (int ks = 0; ks < 2; ks++) {
                u32 qh[4], ql[4];
                ldA(qh, su + O_QKH, w*16, ks*8, 36, g, tg);
                ldA(ql, su + O_QKL, w*16, ks*8, 36, g, tg);
                #pragma unroll
                for (int nt = 0; nt < 8; nt++) {
                    u32 bh[2], bl[2];
                    ldBf(bh, su + O_QKH, nt*8, 16 + ks*8, 36, g, tg);
                    ldBf(bl, su + O_QKL, nt*8, 16 + ks*8, 36, g, tg);
                    mma16(csh_[nt], qh, bh);
                    mma16(csl_[nt], ql, bh);
                    mma16(csl_[nt], qh, bl);
                }
            }
            float cs[8][4];
            #pragma unroll
            for (int nt = 0; nt < 8; nt++)
                #pragma unroll
                for (int q = 0; q < 4; q++) cs[nt][q] = csh_[nt][q] + csl_[nt][q];

            float mx0 = -1e30f, mx1 = -1e30f;
            #pragma unroll
            for (int nt = 0; nt < 8; nt++) {
                mx0 = fmaxf(mx0, fmaxf(cs[nt][0], cs[nt][1]));
                mx1 = fmaxf(mx1, fmaxf(cs[nt][2], cs[nt][3]));
            }
            mx0 = fmaxf(mx0, __shfl_xor_sync(0xffffffffu, mx0, 1));
            mx0 = fmaxf(mx0, __shfl_xor_sync(0xffffffffu, mx0, 2));
            mx1 = fmaxf(mx1, __shfl_xor_sync(0xffffffffu, mx1, 1));
            mx1 = fmaxf(mx1, __shfl_xor_sync(0xffffffffu, mx1, 2));
            float s0 = 0.f, s1 = 0.f;
            #pragma unroll
            for (int nt = 0; nt < 8; nt++) {
                cs[nt][0] = __expf(cs[nt][0] - mx0);
                cs[nt][1] = __expf(cs[nt][1] - mx0);
                cs[nt][2] = __expf(cs[nt][2] - mx1);
                cs[nt][3] = __expf(cs[nt][3] - mx1);
                s0 += cs[nt][0] + cs[nt][1];
                s1 += cs[nt][2] + cs[nt][3];
            }
            s0 += __shfl_xor_sync(0xffffffffu, s0, 1);
            s0 += __shfl_xor_sync(0xffffffffu, s0, 2);
            s1 += __shfl_xor_sync(0xffffffffu, s1, 1);
            s1 += __shfl_xor_sync(0xffffffffu, s1, 2);
            float i0 = 1.f / s0, i1 = 1.f / s1;
            int r0 = w*16 + g;
            #pragma unroll
            for (int nt = 0; nt < 8; nt++) {
                int col = nt*4 + tg;
                u32 hh, ll;
                sp2(cs[nt][0]*i0, cs[nt][1]*i0, hh, ll);
                su[O_PH + r0*36 + col] = hh; su[O_PL + r0*36 + col] = ll;
                sp2(cs[nt][2]*i1, cs[nt][3]*i1, hh, ll);
                su[O_PH + (r0+8)*36 + col] = hh; su[O_PL + (r0+8)*36 + col] = ll;
            }
        }
        __syncthreads();

        // GEMM3: out_h = P @ V (dual-chain)
        {
            float coh_[2][4], col2_[2][4];
            #pragma unroll
            for (int i = 0; i < 2; i++)
                #pragma unroll
                for (int q = 0; q < 4; q++) { coh_[i][q]=0.f; col2_[i][q]=0.f; }
            #pragma unroll
            for (int ks = 0; ks < 4; ks++) {
                u32 ph_[4], pl_[4];
                ldA(ph_, su + O_PH, mt3*16, ks*8, 36, g, tg);
                ldA(pl_, su + O_PL, mt3*16, ks*8, 36, g, tg);
                #pragma unroll
                for (int nt = 0; nt < 2; nt++) {
                    u32 bh[2], bl[2];
                    ldBf(bh, su + O_VH, (nb3+nt)*8, ks*8, 36, g, tg);
                    ldBf(bl, su + O_VL, (nb3+nt)*8, ks*8, 36, g, tg);
                    mma16(coh_[nt], ph_, bh);
                    mma16(col2_[nt], pl_, bh);
                    mma16(col2_[nt], ph_, bl);
                }
            }
            #pragma unroll
            for (int nt = 0; nt < 2; nt++) {
                float c0 = coh_[nt][0] + col2_[nt][0];
                float c1 = coh_[nt][1] + col2_[nt][1];
                float c2 = coh_[nt][2] + col2_[nt][2];
                float c3 = coh_[nt][3] + col2_[nt][3];
                int col = h*16 + (nb3+nt)*4 + tg, r0 = mt3*16 + g;
                u32 hh, ll;
                sp2(c0, c1, hh, ll);
                su[O_AH + r0*P_X + col] = hh; su[O_AL + r0*P_X + col] = ll;
                sp2(c2, c3, hh, ll);
                su[O_AH + (r0+8)*P_X + col] = hh; su[O_AL + (r0+8)*P_X + col] = ll;
            }
        }
        __syncthreads();
    }

    // ---- GEMM4: out = Wout @ att  (A-frags from L2, no barriers in k-loop) ----
    {
        float c4[2][8][4];
        #pragma unroll
        for (int m = 0; m < 2; m++)
            #pragma unroll
            for (int nt = 0; nt < 8; nt++)
                c4[m][nt][0]=c4[m][nt][1]=c4[m][nt][2]=c4[m][nt][3]=0.f;

        #pragma unroll 2
        for (int ks = 0; ks < 16; ks++) {
            u32 ah[2][4], al[2][4];
            #pragma unroll
            for (int m = 0; m < 2; m++) {
                uint4 vh4 = *(const uint4*)&WA4h[(ks*16 + (w*2+m))*128 + lane*4];
                uint4 vl4 = *(const uint4*)&WA4l[(ks*16 + (w*2+m))*128 + lane*4];
                ah[m][0]=vh4.x; ah[m][1]=vh4.y; ah[m][2]=vh4.z; ah[m][3]=vh4.w;
                al[m][0]=vl4.x; al[m][1]=vl4.y; al[m][2]=vl4.z; al[m][3]=vl4.w;
            }
            #pragma unroll
            for (int nt = 0; nt < 8; nt++) {
                u32 bh[2], bl[2];
                ldBf(bh, su + O_AH, nt*8, ks*8, P_X, g, tg);
                ldBf(bl, su + O_AL, nt*8, ks*8, P_X, g, tg);
                #pragma unroll
                for (int m = 0; m < 2; m++) {
                    mma16(c4[m][nt], ah[m], bh);
                    mma16(c4[m][nt], al[m], bh);
                    mma16(c4[m][nt], ah[m], bl);
                }
            }
        }
        // C -> smem (pitch 66), +bias   (writes land in XH/XL region, now dead)
        #pragma unroll
        for (int m = 0; m < 2; m++) {
            int o0 = (w*2 + m)*16 + g;
            float b0v = sf[O_BOUT + o0], b1v = sf[O_BOUT + o0 + 8];
            #pragma unroll
            for (int nt = 0; nt < 8; nt++) {
                int col = nt*8 + 2*tg;
                sf[o0*66 + col]       = c4[m][nt][0] + b0v;
                sf[o0*66 + col + 1]   = c4[m][nt][1] + b0v;
                sf[(o0+8)*66 + col]   = c4[m][nt][2] + b1v;
                sf[(o0+8)*66 + col+1] = c4[m][nt][3] + b1v;
            }
        }
        __syncthreads();
        // coalesced store
        float* ob = out + ((size_t)bb << 24) + (size_t)(wh*8)*256 + ww*8;
        #pragma unroll 4
        for (int i = 0; i < 32; i++) {
            int j = i*512 + t*2;
            int o = j >> 6, pix = j & 63;
            float2 v = *(float2*)&sf[o*66 + pix];
            *(float2*)&ob[(size_t)o*65536 + (size_t)(pix>>3)*256 + (pix&7)] = v;
        }
    }
}

// ---------------- launch ----------------
extern "C" void kernel_launch(void* const* d_in, const int* in_sizes, int n_in,
                              void* d_out, int out_size)
{
    (void)in_sizes; (void)n_in; (void)out_size;
    const float* x     = (const float*)d_in[0];
    const float* g     = (const float*)d_in[1];
    const float* b     = (const float*)d_in[2];
    const float* w_qkv = (const float*)d_in[3];
    const float* w_out = (const float*)d_in[4];
    const float* b_out = (const float*)d_in[5];

    cudaFuncSetAttribute(attn_kernel, cudaFuncAttributeMaxDynamicSharedMemorySize, SMEM_BYTES);

    dpb_kernel<<<289, 64>>>(
        (const float*)d_in[6],  (const float*)d_in[7],
        (const float*)d_in[8],  (const float*)d_in[9],
        (const float*)d_in[10], (const float*)d_in[11],
        (const float*)d_in[12], (const float*)d_in[13],
        (const float*)d_in[14], (const float*)d_in[15],
        (const float*)d_in[16], (const float*)d_in[17],
        (const float*)d_in[18], (const float*)d_in[19]);
    conv_b1<<<1024, 64>>>(w_qkv);
    conv_a1v<<<256, 128>>>(w_qkv);
    conv_a4<<<256, 128>>>(w_out);
    attn_kernel<<<4096, 256, SMEM_BYTES>>>(x, g, b, b_out, (float*)d_out);
}

// round 6
// speedup vs baseline: 3.8283x; 1.3210x over previous
#include <cuda_runtime.h>
#include <cuda_fp16.h>
#include <math.h>

#define EPS 1e-5f
#define QK_SCALE 0.17677669529663687f
typedef unsigned int u32;

__device__ float g_table[289];
// fragment-major weight arrays (fp16x2 pairs, hi only), written by conv kernels
__device__ u32 WB1h[65536];   // qk B-frags [h][ks16][nt8][lane32][2]
__device__ u32 WA1h[32768];   // v  A-frags [h][ks16][mt2][lane32][4]
__device__ u32 WA4h[32768];   // out A-frags [ks16][mt16][lane32][4]

// ---------------- smem layout (u32 offsets) ----------------
#define P_X   132
#define O_XH  0
#define O_XL  8448
#define O_AH  16896
#define O_AL  25344
#define O_QKH 33792
#define O_QKL 36096
#define O_VH  38400
#define O_VL  39552
#define O_PH  40704
#define O_XF  16896      /* fp32 x temp, overlays AH/AL */
#define O_TBL 47616
#define O_BOUT 47936
#define O_GW  48192
#define O_GB  48448
#define O_RED 48704
#define O_MEAN 49216
#define O_RSTD 49280
#define SMEM_U32 49344
#define SMEM_BYTES (SMEM_U32*4)

// ---------------- helpers ----------------
__device__ __forceinline__ u32 pk2(float x0, float x1){
    __half2 h = __floats2half2_rn(x0, x1);   // x0 -> lower half
    return *(u32*)&h;
}
__device__ __forceinline__ void sp2(float x0, float x1, u32& h, u32& l){
    h = pk2(x0, x1);
    __half2 hh = *(__half2*)&h;
    l = pk2(x0 - __low2float(hh), x1 - __high2float(hh));
}
__device__ __forceinline__ void mma16(float* c, const u32* a, const u32* b){
    asm volatile("mma.sync.aligned.m16n8k16.row.col.f32.f16.f16.f32 "
        "{%0,%1,%2,%3},{%4,%5,%6,%7},{%8,%9},{%0,%1,%2,%3};"
        : "+f"(c[0]),"+f"(c[1]),"+f"(c[2]),"+f"(c[3])
        : "r"(a[0]),"r"(a[1]),"r"(a[2]),"r"(a[3]),"r"(b[0]),"r"(b[1]));
}
__device__ __forceinline__ void ldA(u32* a, const u32* s, int r0, int cp_, int pitch, int g, int tg){
    a[0]=s[(r0+g)*pitch+cp_+tg];   a[1]=s[(r0+g+8)*pitch+cp_+tg];
    a[2]=s[(r0+g)*pitch+cp_+tg+4]; a[3]=s[(r0+g+8)*pitch+cp_+tg+4];
}
__device__ __forceinline__ void ldBf(u32* b, const u32* s, int n0, int cp_, int pitch, int g, int tg){
    b[0]=s[(n0+g)*pitch+cp_+tg];   b[1]=s[(n0+g)*pitch+cp_+tg+4];
}
__device__ __forceinline__ void cp16(void* s, const void* gm){
    u32 sa = (u32)__cvta_generic_to_shared(s);
    asm volatile("cp.async.cg.shared.global [%0], [%1], 16;" :: "r"(sa), "l"(gm));
}
__device__ __forceinline__ void cp_commit(){ asm volatile("cp.async.commit_group;"); }
__device__ __forceinline__ void cp_wait0(){ asm volatile("cp.async.wait_group 0;"); }

// ---------------- weight precompute: fragment-major fp16 hi layouts ----------------
__global__ void conv_b1(const float* __restrict__ w){
    int b = blockIdx.x;                  // (h*16+ks)*8+nt
    int h = b >> 7, ks = (b >> 3) & 15, nt = b & 7;
    int t = threadIdx.x;                 // lane*2 + j
    int lane = t >> 1, j = t & 1;
    int g = lane >> 2, tg = lane & 3;
    int r = nt*8 + g;
    int R = (r < 32) ? (h*32 + r) : (256 + h*32 + (r - 32));
    int p = ks*8 + tg + j*4;
    WB1h[b*64 + t] = pk2(w[R*256 + 2*p], w[R*256 + 2*p + 1]);
}
__global__ void conv_a1v(const float* __restrict__ w){
    int b = blockIdx.x;                  // (h*16+ks)*2+mt
    int h = b >> 5, mt = b & 1;
    int t = threadIdx.x;                 // lane*4 + j
    int lane = t >> 2, j = t & 3;
    int g = lane >> 2, tg = lane & 3;
    int vrow = mt*16 + g + (j & 1)*8;
    int R = 512 + h*32 + vrow;
    int ks = (b >> 1) & 15;
    int p = ks*8 + tg + (j >> 1)*4;
    WA1h[b*128 + t] = pk2(w[R*256 + 2*p], w[R*256 + 2*p + 1]);
}
__global__ void conv_a4(const float* __restrict__ w){
    int b = blockIdx.x;                  // ks*16 + mt
    int ks = b >> 4, mt = b & 15;
    int t = threadIdx.x;
    int lane = t >> 2, j = t & 3;
    int g = lane >> 2, tg = lane & 3;
    int R = mt*16 + g + (j & 1)*8;
    int p = ks*8 + tg + (j >> 1)*4;
    WA4h[b*128 + t] = pk2(w[R*256 + 2*p], w[R*256 + 2*p + 1]);
}

// ---------------- DPB MLP ----------------
__device__ __forceinline__ float blockreduce64(float v, float* red){
    #pragma unroll
    for (int o = 16; o > 0; o >>= 1) v += __shfl_xor_sync(0xffffffffu, v, o);
    int t = threadIdx.x;
    if ((t & 31) == 0) red[t >> 5] = v;
    __syncthreads();
    float r = red[0] + red[1];
    __syncthreads();
    return r;
}
__global__ void dpb_kernel(
    const float* __restrict__ w1, const float* __restrict__ b1,
    const float* __restrict__ g1, const float* __restrict__ bb1,
    const float* __restrict__ w2, const float* __restrict__ b2,
    const float* __restrict__ g2, const float* __restrict__ bb2,
    const float* __restrict__ w3, const float* __restrict__ b3,
    const float* __restrict__ g3, const float* __restrict__ bb3,
    const float* __restrict__ w4, const float* __restrict__ b4)
{
    __shared__ float hs[64];
    __shared__ float red[2];
    int r = blockIdx.x, j = threadIdx.x;
    float r0 = (float)(r / 17 - 8), r1 = (float)(r % 17 - 8);
    float v = r0 * w1[j] + r1 * w1[64 + j] + b1[j];
    float m = blockreduce64(v, red) * (1.f/64.f);
    float d = v - m;
    float var = blockreduce64(d*d, red) * (1.f/64.f);
    v = fmaxf(d * rsqrtf(var + EPS) * g1[j] + bb1[j], 0.f);
    hs[j] = v; __syncthreads();
    float a = b2[j];
    #pragma unroll 8
    for (int k = 0; k < 64; k++) a += hs[k] * w2[k*64 + j];
    m = blockreduce64(a, red) * (1.f/64.f);
    d = a - m;
    var = blockreduce64(d*d, red) * (1.f/64.f);
    a = fmaxf(d * rsqrtf(var + EPS) * g2[j] + bb2[j], 0.f);
    __syncthreads(); hs[j] = a; __syncthreads();
    a = b3[j];
    #pragma unroll 8
    for (int k = 0; k < 64; k++) a += hs[k] * w3[k*64 + j];
    m = blockreduce64(a, red) * (1.f/64.f);
    d = a - m;
    var = blockreduce64(d*d, red) * (1.f/64.f);
    a = fmaxf(d * rsqrtf(var + EPS) * g3[j] + bb3[j], 0.f);
    __syncthreads(); hs[j] = a; __syncthreads();
    float c = blockreduce64(hs[j] * w4[j], red);
    if (j == 0) g_table[r] = c + b4[0];
}

// ---------------- fused attention ----------------
__global__ __launch_bounds__(256, 1) void attn_kernel(
    const float* __restrict__ x, const float* __restrict__ gw, const float* __restrict__ gb,
    const float* __restrict__ b_out, float* __restrict__ out)
{
    extern __shared__ u32 su[];
    float* sf = (float*)su;
    const int t = threadIdx.x, lane = t & 31, w = t >> 5;
    const int g = lane >> 2, tg = lane & 3;
    const int wid = blockIdx.x;
    const int bb = wid >> 10, wh = (wid >> 5) & 31, ww = wid & 31;
    const float* xb = x + ((size_t)bb << 24) + (size_t)(wh * 8) * 256 + ww * 8;

    if (t < 289) sf[O_TBL + t] = g_table[t];
    sf[O_BOUT + t] = b_out[t];
    sf[O_GW + t] = gw[t];
    sf[O_GB + t] = gb[t];

    // ---- load x (fp32) ----
    #pragma unroll
    for (int i = 0; i < 8; i++) {
        int s = i * 256 + t, d = s >> 3, ph = s & 7;
        const float* src = xb + (size_t)d * 65536 + (size_t)ph * 256;
        float* dst = sf + O_XF + d * 68 + ph * 8;
        cp16(dst, src); cp16(dst + 4, src + 4);
    }
    cp_commit(); cp_wait0(); __syncthreads();

    // ---- LN stats ----
    {
        int pix = t & 63, q4 = t >> 6;
        float s = 0.f, ss = 0.f;
        #pragma unroll 8
        for (int d = q4*64; d < q4*64 + 64; d++) {
            float v = sf[O_XF + d*68 + pix]; s += v; ss += v*v;
        }
        sf[O_RED + t] = s; sf[O_RED + 256 + t] = ss;
        __syncthreads();
        if (t < 64) {
            float s0 = sf[O_RED+t] + sf[O_RED+64+t] + sf[O_RED+128+t] + sf[O_RED+192+t];
            float s1 = sf[O_RED+256+t] + sf[O_RED+320+t] + sf[O_RED+384+t] + sf[O_RED+448+t];
            float mn = s0 * (1.f/256.f);
            float vr = s1 * (1.f/256.f) - mn*mn;
            sf[O_MEAN + t] = mn;
            sf[O_RSTD + t] = rsqrtf(vr + EPS);
        }
        __syncthreads();
    }
    // ---- normalize + split to fp16 pairs ----
    {
        int pix = t & 63, cb = (t >> 6) * 64;
        float mn = sf[O_MEAN + pix], rs = sf[O_RSTD + pix];
        #pragma unroll 8
        for (int p = 0; p < 32; p++) {
            int c = cb + 2*p;
            float v0 = (sf[O_XF + c*68 + pix] - mn)*rs*sf[O_GW+c] + sf[O_GB+c];
            float v1 = (sf[O_XF + (c+1)*68 + pix] - mn)*rs*sf[O_GW+c+1] + sf[O_GB+c+1];
            u32 hh, ll; sp2(v0, v1, hh, ll);
            su[O_XH + pix*P_X + cb/2 + p] = hh;
            su[O_XL + pix*P_X + cb/2 + p] = ll;
        }
        __syncthreads();
    }

    const int mt  = w >> 1,  nb  = (w & 1) * 4;   // G1 qk tiles
    const int vmt = w & 1,   vnb = (w >> 1) * 2;  // G1 v tiles
    const int mt3 = w >> 1,  nb3 = (w & 1) * 2;   // GEMM3 tiles

    // ---- per-head ----
    for (int h = 0; h < 8; h++) {
        // GEMM1: 2-term fp16, dual chains; weights (hi only) streamed from L2
        float cqh_[4][4], cql_[4][4], cvh_[2][4], cvl_[2][4];
        #pragma unroll
        for (int i = 0; i < 4; i++)
            #pragma unroll
            for (int q = 0; q < 4; q++) { cqh_[i][q]=0.f; cql_[i][q]=0.f; }
        #pragma unroll
        for (int i = 0; i < 2; i++)
            #pragma unroll
            for (int q = 0; q < 4; q++) { cvh_[i][q]=0.f; cvl_[i][q]=0.f; }

        #pragma unroll 4
        for (int ks = 0; ks < 16; ks++) {
            u32 axh[4], axl[4];
            ldA(axh, su + O_XH, mt*16, ks*8, P_X, g, tg);
            ldA(axl, su + O_XL, mt*16, ks*8, P_X, g, tg);
            uint4 awh4 = *(const uint4*)&WA1h[((h*16+ks)*2+vmt)*128 + lane*4];
            #pragma unroll
            for (int nt = 0; nt < 4; nt++) {
                uint2 b2h = *(const uint2*)&WB1h[((h*16+ks)*8+nb+nt)*64 + lane*2];
                u32 bh[2] = {b2h.x, b2h.y};
                mma16(cqh_[nt], axh, bh);   // Xh * Wh
                mma16(cql_[nt], axl, bh);   // Xl * Wh
            }
            u32 awh[4] = {awh4.x, awh4.y, awh4.z, awh4.w};
            #pragma unroll
            for (int vt = 0; vt < 2; vt++) {
                u32 bxh[2], bxl[2];
                ldBf(bxh, su + O_XH, (vnb+vt)*8, ks*8, P_X, g, tg);
                ldBf(bxl, su + O_XL, (vnb+vt)*8, ks*8, P_X, g, tg);
                mma16(cvh_[vt], awh, bxh);  // Wh * Xh
                mma16(cvl_[vt], awh, bxl);  // Wh * Xl
            }
        }
        // epilogue: q tiles store hi+lo (GEMM2 A), k tiles hi only (GEMM2 B)
        #pragma unroll
        for (int nt = 0; nt < 4; nt++) {
            float c0 = cqh_[nt][0] + cql_[nt][0];
            float c1 = cqh_[nt][1] + cql_[nt][1];
            float c2 = cqh_[nt][2] + cql_[nt][2];
            float c3 = cqh_[nt][3] + cql_[nt][3];
            int isq = (nb + nt) < 4;            // channels < 32 -> q
            float sc = isq ? QK_SCALE : 1.f;
            int col = (nb+nt)*4 + tg, p0 = mt*16 + g;
            u32 hh, ll;
            sp2(c0*sc, c1*sc, hh, ll);
            su[O_QKH + p0*36 + col] = hh;
            if (isq) su[O_QKL + p0*36 + col] = ll;
            sp2(c2*sc, c3*sc, hh, ll);
            su[O_QKH + (p0+8)*36 + col] = hh;
            if (isq) su[O_QKL + (p0+8)*36 + col] = ll;
        }
        #pragma unroll
        for (int vt = 0; vt < 2; vt++) {
            float c0 = cvh_[vt][0] + cvl_[vt][0];
            float c1 = cvh_[vt][1] + cvl_[vt][1];
            float c2 = cvh_[vt][2] + cvl_[vt][2];
            float c3 = cvh_[vt][3] + cvl_[vt][3];
            int col = (vnb+vt)*4 + tg, r0 = vmt*16 + g;
            u32 hh, ll;
            sp2(c0, c1, hh, ll);
            su[O_VH + r0*36 + col] = hh; su[O_VL + r0*36 + col] = ll;
            sp2(c2, c3, hh, ll);
            su[O_VH + (r0+8)*36 + col] = hh; su[O_VL + (r0+8)*36 + col] = ll;
        }
        __syncthreads();

        // GEMM2 + softmax (warps 0..3): A = q hi+lo, B = k hi
        if (w < 4) {
            float csh_[8][4], csl_[8][4];
            #pragma unroll
            for (int nt = 0; nt < 8; nt++) {
                int i0 = w*16 + g, i1 = i0 + 8;
                int j0 = nt*8 + 2*tg, j1 = j0 + 1;
                csh_[nt][0] = sf[O_TBL + ((i0>>3)-(j0>>3)+7)*15 + (i0&7)-(j0&7)+7];
                csh_[nt][1] = sf[O_TBL + ((i0>>3)-(j1>>3)+7)*15 + (i0&7)-(j1&7)+7];
                csh_[nt][2] = sf[O_TBL + ((i1>>3)-(j0>>3)+7)*15 + (i1&7)-(j0&7)+7];
                csh_[nt][3] = sf[O_TBL + ((i1>>3)-(j1>>3)+7)*15 + (i1&7)-(j1&7)+7];
                csl_[nt][0]=csl_[nt][1]=csl_[nt][2]=csl_[nt][3]=0.f;
            }
            #pragma unroll
            for (int ks = 0; ks < 2; ks++) {
                u32 qh[4], ql[4];
                ldA(qh, su + O_QKH, w*16, ks*8, 36, g, tg);
                ldA(ql, su + O_QKL, w*16, ks*8, 36, g, tg);
                #pragma unroll
                for (int nt = 0; nt < 8; nt++) {
                    u32 bh[2];
                    ldBf(bh, su + O_QKH, nt*8, 16 + ks*8, 36, g, tg);
                    mma16(csh_[nt], qh, bh);
                    mma16(csl_[nt], ql, bh);
                }
            }
            float cs[8][4];
            #pragma unroll
            for (int nt = 0; nt < 8; nt++)
                #pragma unroll
                for (int q = 0; q < 4; q++) cs[nt][q] = csh_[nt][q] + csl_[nt][q];

            float mx0 = -1e30f, mx1 = -1e30f;
            #pragma unroll
            for (int nt = 0; nt < 8; nt++) {
                mx0 = fmaxf(mx0, fmaxf(cs[nt][0], cs[nt][1]));
                mx1 = fmaxf(mx1, fmaxf(cs[nt][2], cs[nt][3]));
            }
            mx0 = fmaxf(mx0, __shfl_xor_sync(0xffffffffu, mx0, 1));
            mx0 = fmaxf(mx0, __shfl_xor_sync(0xffffffffu, mx0, 2));
            mx1 = fmaxf(mx1, __shfl_xor_sync(0xffffffffu, mx1, 1));
            mx1 = fmaxf(mx1, __shfl_xor_sync(0xffffffffu, mx1, 2));
            float s0 = 0.f, s1 = 0.f;
            #pragma unroll
            for (int nt = 0; nt < 8; nt++) {
                cs[nt][0] = __expf(cs[nt][0] - mx0);
                cs[nt][1] = __expf(cs[nt][1] - mx0);
                cs[nt][2] = __expf(cs[nt][2] - mx1);
                cs[nt][3] = __expf(cs[nt][3] - mx1);
                s0 += cs[nt][0] + cs[nt][1];
                s1 += cs[nt][2] + cs[nt][3];
            }
            s0 += __shfl_xor_sync(0xffffffffu, s0, 1);
            s0 += __shfl_xor_sync(0xffffffffu, s0, 2);
            s1 += __shfl_xor_sync(0xffffffffu, s1, 1);
            s1 += __shfl_xor_sync(0xffffffffu, s1, 2);
            float i0 = 1.f / s0, i1 = 1.f / s1;
            int r0 = w*16 + g;
            #pragma unroll
            for (int nt = 0; nt < 8; nt++) {
                int col = nt*4 + tg;
                su[O_PH + r0*36 + col]     = pk2(cs[nt][0]*i0, cs[nt][1]*i0);
                su[O_PH + (r0+8)*36 + col] = pk2(cs[nt][2]*i1, cs[nt][3]*i1);
            }
        }
        __syncthreads();

        // GEMM3: out_h = P @ V  (A = P hi, B = V hi+lo)
        {
            float coh_[2][4], col2_[2][4];
            #pragma unroll
            for (int i = 0; i < 2; i++)
                #pragma unroll
                for (int q = 0; q < 4; q++) { coh_[i][q]=0.f; col2_[i][q]=0.f; }
            #pragma unroll
            for (int ks = 0; ks < 4; ks++) {
                u32 ph_[4];
                ldA(ph_, su + O_PH, mt3*16, ks*8, 36, g, tg);
                #pragma unroll
                for (int nt = 0; nt < 2; nt++) {
                    u32 bh[2], bl[2];
                    ldBf(bh, su + O_VH, (nb3+nt)*8, ks*8, 36, g, tg);
                    ldBf(bl, su + O_VL, (nb3+nt)*8, ks*8, 36, g, tg);
                    mma16(coh_[nt], ph_, bh);
                    mma16(col2_[nt], ph_, bl);
                }
            }
            #pragma unroll
            for (int nt = 0; nt < 2; nt++) {
                float c0 = coh_[nt][0] + col2_[nt][0];
                float c1 = coh_[nt][1] + col2_[nt][1];
                float c2 = coh_[nt][2] + col2_[nt][2];
                float c3 = coh_[nt][3] + col2_[nt][3];
                int col = h*16 + (nb3+nt)*4 + tg, r0 = mt3*16 + g;
                u32 hh, ll;
                sp2(c0, c1, hh, ll);
                su[O_AH + r0*P_X + col] = hh; su[O_AL + r0*P_X + col] = ll;
                sp2(c2, c3, hh, ll);
                su[O_AH + (r0+8)*P_X + col] = hh; su[O_AL + (r0+8)*P_X + col] = ll;
            }
        }
        __syncthreads();
    }

    // ---- GEMM4: out = Wout @ att  (A = Wh from L2, B = att hi+lo) ----
    {
        float c4[2][8][4];
        #pragma unroll
        for (int m = 0; m < 2; m++)
            #pragma unroll
            for (int nt = 0; nt < 8; nt++)
                c4[m][nt][0]=c4[m][nt][1]=c4[m][nt][2]=c4[m][nt][3]=0.f;

        #pragma unroll 2
        for (int ks = 0; ks < 16; ks++) {
            u32 ah[2][4];
            #pragma unroll
            for (int m = 0; m < 2; m++) {
                uint4 vh4 = *(const uint4*)&WA4h[(ks*16 + (w*2+m))*128 + lane*4];
                ah[m][0]=vh4.x; ah[m][1]=vh4.y; ah[m][2]=vh4.z; ah[m][3]=vh4.w;
            }
            #pragma unroll
            for (int nt = 0; nt < 8; nt++) {
                u32 bh[2], bl[2];
                ldBf(bh, su + O_AH, nt*8, ks*8, P_X, g, tg);
                ldBf(bl, su + O_AL, nt*8, ks*8, P_X, g, tg);
                #pragma unroll
                for (int m = 0; m < 2; m++) {
                    mma16(c4[m][nt], ah[m], bh);
                    mma16(c4[m][nt], ah[m], bl);
                }
            }
        }
        // C -> smem (pitch 66), +bias   (writes land in XH/XL region, now dead)
        #pragma unroll
        for (int m = 0; m < 2; m++) {
            int o0 = (w*2 + m)*16 + g;
            float b0v = sf[O_BOUT + o0], b1v = sf[O_BOUT + o0 + 8];
            #pragma unroll
            for (int nt = 0; nt < 8; nt++) {
                int col = nt*8 + 2*tg;
                sf[o0*66 + col]       = c4[m][nt][0] + b0v;
                sf[o0*66 + col + 1]   = c4[m][nt][1] + b0v;
                sf[(o0+8)*66 + col]   = c4[m][nt][2] + b1v;
                sf[(o0+8)*66 + col+1] = c4[m][nt][3] + b1v;
            }
        }
        __syncthreads();
        // coalesced store
        float* ob = out + ((size_t)bb << 24) + (size_t)(wh*8)*256 + ww*8;
        #pragma unroll 4
        for (int i = 0; i < 32; i++) {
            int j = i*512 + t*2;
            int o = j >> 6, pix = j & 63;
            float2 v = *(float2*)&sf[o*66 + pix];
            *(float2*)&ob[(size_t)o*65536 + (size_t)(pix>>3)*256 + (pix&7)] = v;
        }
    }
}

// ---------------- launch ----------------
extern "C" void kernel_launch(void* const* d_in, const int* in_sizes, int n_in,
                              void* d_out, int out_size)
{
    (void)in_sizes; (void)n_in; (void)out_size;
    const float* x     = (const float*)d_in[0];
    const float* g     = (const float*)d_in[1];
    const float* b     = (const float*)d_in[2];
    const float* w_qkv = (const float*)d_in[3];
    const float* w_out = (const float*)d_in[4];
    const float* b_out = (const float*)d_in[5];

    cudaFuncSetAttribute(attn_kernel, cudaFuncAttributeMaxDynamicSharedMemorySize, SMEM_BYTES);

    dpb_kernel<<<289, 64>>>(
        (const float*)d_in[6],  (const float*)d_in[7],
        (const float*)d_in[8],  (const float*)d_in[9],
        (const float*)d_in[10], (const float*)d_in[11],
        (const float*)d_in[12], (const float*)d_in[13],
        (const float*)d_in[14], (const float*)d_in[15],
        (const float*)d_in[16], (const float*)d_in[17],
        (const float*)d_in[18], (const float*)d_in[19]);
    conv_b1<<<1024, 64>>>(w_qkv);
    conv_a1v<<<256, 128>>>(w_qkv);
    conv_a4<<<256, 128>>>(w_out);
    attn_kernel<<<4096, 256, SMEM_BYTES>>>(x, g, b, b_out, (float*)d_out);
}

// round 7
// speedup vs baseline: 4.5213x; 1.1810x over previous
#include <cuda_runtime.h>
#include <cuda_fp16.h>
#include <math.h>

#define EPS 1e-5f
#define QK_SCALE 0.17677669529663687f
typedef unsigned int u32;

__device__ float g_table[289];
// fragment-major weight arrays (fp16x2 pairs, hi only), written by conv kernels
__device__ u32 WB1h[65536];   // qk B-frags [h][ks16][nt8][lane32][2]
__device__ u32 WA1h[32768];   // v  A-frags [h][ks16][mt2][lane32][4]
__device__ u32 WA4h[32768];   // out A-frags [ks16][mt16][lane32][4]

// ---------------- smem layout (u32 offsets) ----------------
#define P_X   132
#define O_XH  0
#define O_XL  8448
#define O_AH  16896
#define O_QKH 33792
#define O_QKL 36096
#define O_VH  38400
#define O_PH  40704
#define O_XF  16896      /* fp32 x temp, overlays AH region (dead at that time) */
#define O_TBL 47616
#define O_BOUT 47936
#define O_GW  48192
#define O_GB  48448
#define O_RED 48704
#define O_MEAN 49216
#define O_RSTD 49280
#define SMEM_U32 49344
#define SMEM_BYTES (SMEM_U32*4)

// ---------------- helpers ----------------
__device__ __forceinline__ u32 pk2(float x0, float x1){
    __half2 h = __floats2half2_rn(x0, x1);   // x0 -> lower half
    return *(u32*)&h;
}
__device__ __forceinline__ void sp2(float x0, float x1, u32& h, u32& l){
    h = pk2(x0, x1);
    __half2 hh = *(__half2*)&h;
    l = pk2(x0 - __low2float(hh), x1 - __high2float(hh));
}
__device__ __forceinline__ void mma16(float* c, const u32* a, const u32* b){
    asm volatile("mma.sync.aligned.m16n8k16.row.col.f32.f16.f16.f32 "
        "{%0,%1,%2,%3},{%4,%5,%6,%7},{%8,%9},{%0,%1,%2,%3};"
        : "+f"(c[0]),"+f"(c[1]),"+f"(c[2]),"+f"(c[3])
        : "r"(a[0]),"r"(a[1]),"r"(a[2]),"r"(a[3]),"r"(b[0]),"r"(b[1]));
}
__device__ __forceinline__ void ldA(u32* a, const u32* s, int r0, int cp_, int pitch, int g, int tg){
    a[0]=s[(r0+g)*pitch+cp_+tg];   a[1]=s[(r0+g+8)*pitch+cp_+tg];
    a[2]=s[(r0+g)*pitch+cp_+tg+4]; a[3]=s[(r0+g+8)*pitch+cp_+tg+4];
}
__device__ __forceinline__ void ldBf(u32* b, const u32* s, int n0, int cp_, int pitch, int g, int tg){
    b[0]=s[(n0+g)*pitch+cp_+tg];   b[1]=s[(n0+g)*pitch+cp_+tg+4];
}
__device__ __forceinline__ void cp16(void* s, const void* gm){
    u32 sa = (u32)__cvta_generic_to_shared(s);
    asm volatile("cp.async.cg.shared.global [%0], [%1], 16;" :: "r"(sa), "l"(gm));
}
__device__ __forceinline__ void cp_commit(){ asm volatile("cp.async.commit_group;"); }
__device__ __forceinline__ void cp_wait0(){ asm volatile("cp.async.wait_group 0;"); }

// ---------------- weight precompute: fragment-major fp16 hi layouts ----------------
__global__ void conv_b1(const float* __restrict__ w){
    int b = blockIdx.x;                  // (h*16+ks)*8+nt
    int h = b >> 7, ks = (b >> 3) & 15, nt = b & 7;
    int t = threadIdx.x;                 // lane*2 + j
    int lane = t >> 1, j = t & 1;
    int g = lane >> 2, tg = lane & 3;
    int r = nt*8 + g;
    int R = (r < 32) ? (h*32 + r) : (256 + h*32 + (r - 32));
    int p = ks*8 + tg + j*4;
    WB1h[b*64 + t] = pk2(w[R*256 + 2*p], w[R*256 + 2*p + 1]);
}
__global__ void conv_a1v(const float* __restrict__ w){
    int b = blockIdx.x;                  // (h*16+ks)*2+mt
    int h = b >> 5, mt = b & 1;
    int t = threadIdx.x;                 // lane*4 + j
    int lane = t >> 2, j = t & 3;
    int g = lane >> 2, tg = lane & 3;
    int vrow = mt*16 + g + (j & 1)*8;
    int R = 512 + h*32 + vrow;
    int ks = (b >> 1) & 15;
    int p = ks*8 + tg + (j >> 1)*4;
    WA1h[b*128 + t] = pk2(w[R*256 + 2*p], w[R*256 + 2*p + 1]);
}
__global__ void conv_a4(const float* __restrict__ w){
    int b = blockIdx.x;                  // ks*16 + mt
    int ks = b >> 4, mt = b & 15;
    int t = threadIdx.x;
    int lane = t >> 2, j = t & 3;
    int g = lane >> 2, tg = lane & 3;
    int R = mt*16 + g + (j & 1)*8;
    int p = ks*8 + tg + (j >> 1)*4;
    WA4h[b*128 + t] = pk2(w[R*256 + 2*p], w[R*256 + 2*p + 1]);
}

// ---------------- DPB MLP ----------------
__device__ __forceinline__ float blockreduce64(float v, float* red){
    #pragma unroll
    for (int o = 16; o > 0; o >>= 1) v += __shfl_xor_sync(0xffffffffu, v, o);
    int t = threadIdx.x;
    if ((t & 31) == 0) red[t >> 5] = v;
    __syncthreads();
    float r = red[0] + red[1];
    __syncthreads();
    return r;
}
__global__ void dpb_kernel(
    const float* __restrict__ w1, const float* __restrict__ b1,
    const float* __restrict__ g1, const float* __restrict__ bb1,
    const float* __restrict__ w2, const float* __restrict__ b2,
    const float* __restrict__ g2, const float* __restrict__ bb2,
    const float* __restrict__ w3, const float* __restrict__ b3,
    const float* __restrict__ g3, const float* __restrict__ bb3,
    const float* __restrict__ w4, const float* __restrict__ b4)
{
    __shared__ float hs[64];
    __shared__ float red[2];
    int r = blockIdx.x, j = threadIdx.x;
    float r0 = (float)(r / 17 - 8), r1 = (float)(r % 17 - 8);
    float v = r0 * w1[j] + r1 * w1[64 + j] + b1[j];
    float m = blockreduce64(v, red) * (1.f/64.f);
    float d = v - m;
    float var = blockreduce64(d*d, red) * (1.f/64.f);
    v = fmaxf(d * rsqrtf(var + EPS) * g1[j] + bb1[j], 0.f);
    hs[j] = v; __syncthreads();
    float a = b2[j];
    #pragma unroll 8
    for (int k = 0; k < 64; k++) a += hs[k] * w2[k*64 + j];
    m = blockreduce64(a, red) * (1.f/64.f);
    d = a - m;
    var = blockreduce64(d*d, red) * (1.f/64.f);
    a = fmaxf(d * rsqrtf(var + EPS) * g2[j] + bb2[j], 0.f);
    __syncthreads(); hs[j] = a; __syncthreads();
    a = b3[j];
    #pragma unroll 8
    for (int k = 0; k < 64; k++) a += hs[k] * w3[k*64 + j];
    m = blockreduce64(a, red) * (1.f/64.f);
    d = a - m;
    var = blockreduce64(d*d, red) * (1.f/64.f);
    a = fmaxf(d * rsqrtf(var + EPS) * g3[j] + bb3[j], 0.f);
    __syncthreads(); hs[j] = a; __syncthreads();
    float c = blockreduce64(hs[j] * w4[j], red);
    if (j == 0) g_table[r] = c + b4[0];
}

// ---------------- fused attention ----------------
__global__ __launch_bounds__(256, 1) void attn_kernel(
    const float* __restrict__ x, const float* __restrict__ gw, const float* __restrict__ gb,
    const float* __restrict__ b_out, float* __restrict__ out)
{
    extern __shared__ u32 su[];
    float* sf = (float*)su;
    const int t = threadIdx.x, lane = t & 31, w = t >> 5;
    const int g = lane >> 2, tg = lane & 3;
    const int wid = blockIdx.x;
    const int bb = wid >> 10, wh = (wid >> 5) & 31, ww = wid & 31;
    const float* xb = x + ((size_t)bb << 24) + (size_t)(wh * 8) * 256 + ww * 8;

    if (t < 289) sf[O_TBL + t] = g_table[t];
    sf[O_BOUT + t] = b_out[t];
    sf[O_GW + t] = gw[t];
    sf[O_GB + t] = gb[t];

    // ---- load x (fp32) ----
    #pragma unroll
    for (int i = 0; i < 8; i++) {
        int s = i * 256 + t, d = s >> 3, ph = s & 7;
        const float* src = xb + (size_t)d * 65536 + (size_t)ph * 256;
        float* dst = sf + O_XF + d * 68 + ph * 8;
        cp16(dst, src); cp16(dst + 4, src + 4);
    }
    cp_commit(); cp_wait0(); __syncthreads();

    // ---- LN stats ----
    {
        int pix = t & 63, q4 = t >> 6;
        float s = 0.f, ss = 0.f;
        #pragma unroll 8
        for (int d = q4*64; d < q4*64 + 64; d++) {
            float v = sf[O_XF + d*68 + pix]; s += v; ss += v*v;
        }
        sf[O_RED + t] = s; sf[O_RED + 256 + t] = ss;
        __syncthreads();
        if (t < 64) {
            float s0 = sf[O_RED+t] + sf[O_RED+64+t] + sf[O_RED+128+t] + sf[O_RED+192+t];
            float s1 = sf[O_RED+256+t] + sf[O_RED+320+t] + sf[O_RED+384+t] + sf[O_RED+448+t];
            float mn = s0 * (1.f/256.f);
            float vr = s1 * (1.f/256.f) - mn*mn;
            sf[O_MEAN + t] = mn;
            sf[O_RSTD + t] = rsqrtf(vr + EPS);
        }
        __syncthreads();
    }
    // ---- normalize + split to fp16 pairs ----
    {
        int pix = t & 63, cb = (t >> 6) * 64;
        float mn = sf[O_MEAN + pix], rs = sf[O_RSTD + pix];
        #pragma unroll 8
        for (int p = 0; p < 32; p++) {
            int c = cb + 2*p;
            float v0 = (sf[O_XF + c*68 + pix] - mn)*rs*sf[O_GW+c] + sf[O_GB+c];
            float v1 = (sf[O_XF + (c+1)*68 + pix] - mn)*rs*sf[O_GW+c+1] + sf[O_GB+c+1];
            u32 hh, ll; sp2(v0, v1, hh, ll);
            su[O_XH + pix*P_X + cb/2 + p] = hh;
            su[O_XL + pix*P_X + cb/2 + p] = ll;
        }
        __syncthreads();
    }

    const int mt  = w >> 1,  nb  = (w & 1) * 4;   // G1 qk tiles
    const int vmt = w & 1,   vnb = (w >> 1) * 2;  // G1 v tiles
    const int mt3 = w >> 1,  nb3 = (w & 1) * 2;   // GEMM3 tiles

    // ---- per-head ----
    for (int h = 0; h < 8; h++) {
        // GEMM1: q/k 2-term (Xh+Xl vs Wh); v single-term (Xh vs Wh)
        float cqh_[4][4], cql_[4][4], cvh_[2][4];
        #pragma unroll
        for (int i = 0; i < 4; i++)
            #pragma unroll
            for (int q = 0; q < 4; q++) { cqh_[i][q]=0.f; cql_[i][q]=0.f; }
        #pragma unroll
        for (int i = 0; i < 2; i++)
            #pragma unroll
            for (int q = 0; q < 4; q++) { cvh_[i][q]=0.f; }

        #pragma unroll 4
        for (int ks = 0; ks < 16; ks++) {
            u32 axh[4], axl[4];
            ldA(axh, su + O_XH, mt*16, ks*8, P_X, g, tg);
            ldA(axl, su + O_XL, mt*16, ks*8, P_X, g, tg);
            uint4 awh4 = *(const uint4*)&WA1h[((h*16+ks)*2+vmt)*128 + lane*4];
            #pragma unroll
            for (int nt = 0; nt < 4; nt++) {
                uint2 b2h = *(const uint2*)&WB1h[((h*16+ks)*8+nb+nt)*64 + lane*2];
                u32 bh[2] = {b2h.x, b2h.y};
                mma16(cqh_[nt], axh, bh);   // Xh * Wh
                mma16(cql_[nt], axl, bh);   // Xl * Wh
            }
            u32 awh[4] = {awh4.x, awh4.y, awh4.z, awh4.w};
            #pragma unroll
            for (int vt = 0; vt < 2; vt++) {
                u32 bxh[2];
                ldBf(bxh, su + O_XH, (vnb+vt)*8, ks*8, P_X, g, tg);
                mma16(cvh_[vt], awh, bxh);  // Wh * Xh
            }
        }
        // epilogue: q tiles store hi+lo (GEMM2 A), k tiles hi only (GEMM2 B)
        #pragma unroll
        for (int nt = 0; nt < 4; nt++) {
            float c0 = cqh_[nt][0] + cql_[nt][0];
            float c1 = cqh_[nt][1] + cql_[nt][1];
            float c2 = cqh_[nt][2] + cql_[nt][2];
            float c3 = cqh_[nt][3] + cql_[nt][3];
            int isq = (nb + nt) < 4;            // channels < 32 -> q
            float sc = isq ? QK_SCALE : 1.f;
            int col = (nb+nt)*4 + tg, p0 = mt*16 + g;
            u32 hh, ll;
            sp2(c0*sc, c1*sc, hh, ll);
            su[O_QKH + p0*36 + col] = hh;
            if (isq) su[O_QKL + p0*36 + col] = ll;
            sp2(c2*sc, c3*sc, hh, ll);
            su[O_QKH + (p0+8)*36 + col] = hh;
            if (isq) su[O_QKL + (p0+8)*36 + col] = ll;
        }
        #pragma unroll
        for (int vt = 0; vt < 2; vt++) {
            int col = (vnb+vt)*4 + tg, r0 = vmt*16 + g;
            su[O_VH + r0*36 + col]     = pk2(cvh_[vt][0], cvh_[vt][1]);
            su[O_VH + (r0+8)*36 + col] = pk2(cvh_[vt][2], cvh_[vt][3]);
        }
        __syncthreads();

        // GEMM2 + softmax (warps 0..3): A = q hi+lo, B = k hi
        if (w < 4) {
            float csh_[8][4], csl_[8][4];
            #pragma unroll
            for (int nt = 0; nt < 8; nt++) {
                int i0 = w*16 + g, i1 = i0 + 8;
                int j0 = nt*8 + 2*tg, j1 = j0 + 1;
                csh_[nt][0] = sf[O_TBL + ((i0>>3)-(j0>>3)+7)*15 + (i0&7)-(j0&7)+7];
                csh_[nt][1] = sf[O_TBL + ((i0>>3)-(j1>>3)+7)*15 + (i0&7)-(j1&7)+7];
                csh_[nt][2] = sf[O_TBL + ((i1>>3)-(j0>>3)+7)*15 + (i1&7)-(j0&7)+7];
                csh_[nt][3] = sf[O_TBL + ((i1>>3)-(j1>>3)+7)*15 + (i1&7)-(j1&7)+7];
                csl_[nt][0]=csl_[nt][1]=csl_[nt][2]=csl_[nt][3]=0.f;
            }
            #pragma unroll
            for (int ks = 0; ks < 2; ks++) {
                u32 qh[4], ql[4];
                ldA(qh, su + O_QKH, w*16, ks*8, 36, g, tg);
                ldA(ql, su + O_QKL, w*16, ks*8, 36, g, tg);
                #pragma unroll
                for (int nt = 0; nt < 8; nt++) {
                    u32 bh[2];
                    ldBf(bh, su + O_QKH, nt*8, 16 + ks*8, 36, g, tg);
                    mma16(csh_[nt], qh, bh);
                    mma16(csl_[nt], ql, bh);
                }
            }
            float cs[8][4];
            #pragma unroll
            for (int nt = 0; nt < 8; nt++)
                #pragma unroll
                for (int q = 0; q < 4; q++) cs[nt][q] = csh_[nt][q] + csl_[nt][q];

            float mx0 = -1e30f, mx1 = -1e30f;
            #pragma unroll
            for (int nt = 0; nt < 8; nt++) {
                mx0 = fmaxf(mx0, fmaxf(cs[nt][0], cs[nt][1]));
                mx1 = fmaxf(mx1, fmaxf(cs[nt][2], cs[nt][3]));
            }
            mx0 = fmaxf(mx0, __shfl_xor_sync(0xffffffffu, mx0, 1));
            mx0 = fmaxf(mx0, __shfl_xor_sync(0xffffffffu, mx0, 2));
            mx1 = fmaxf(mx1, __shfl_xor_sync(0xffffffffu, mx1, 1));
            mx1 = fmaxf(mx1, __shfl_xor_sync(0xffffffffu, mx1, 2));
            float s0 = 0.f, s1 = 0.f;
            #pragma unroll
            for (int nt = 0; nt < 8; nt++) {
                cs[nt][0] = __expf(cs[nt][0] - mx0);
                cs[nt][1] = __expf(cs[nt][1] - mx0);
                cs[nt][2] = __expf(cs[nt][2] - mx1);
                cs[nt][3] = __expf(cs[nt][3] - mx1);
                s0 += cs[nt][0] + cs[nt][1];
                s1 += cs[nt][2] + cs[nt][3];
            }
            s0 += __shfl_xor_sync(0xffffffffu, s0, 1);
            s0 += __shfl_xor_sync(0xffffffffu, s0, 2);
            s1 += __shfl_xor_sync(0xffffffffu, s1, 1);
            s1 += __shfl_xor_sync(0xffffffffu, s1, 2);
            float i0 = 1.f / s0, i1 = 1.f / s1;
            int r0 = w*16 + g;
            #pragma unroll
            for (int nt = 0; nt < 8; nt++) {
                int col = nt*4 + tg;
                su[O_PH + r0*36 + col]     = pk2(cs[nt][0]*i0, cs[nt][1]*i0);
                su[O_PH + (r0+8)*36 + col] = pk2(cs[nt][2]*i1, cs[nt][3]*i1);
            }
        }
        __syncthreads();

        // GEMM3: out_h = P @ V  (A = P hi, B = V hi)
        {
            float coh_[2][4];
            #pragma unroll
            for (int i = 0; i < 2; i++)
                #pragma unroll
                for (int q = 0; q < 4; q++) { coh_[i][q]=0.f; }
            #pragma unroll
            for (int ks = 0; ks < 4; ks++) {
                u32 ph_[4];
                ldA(ph_, su + O_PH, mt3*16, ks*8, 36, g, tg);
                #pragma unroll
                for (int nt = 0; nt < 2; nt++) {
                    u32 bh[2];
                    ldBf(bh, su + O_VH, (nb3+nt)*8, ks*8, 36, g, tg);
                    mma16(coh_[nt], ph_, bh);
                }
            }
            #pragma unroll
            for (int nt = 0; nt < 2; nt++) {
                int col = h*16 + (nb3+nt)*4 + tg, r0 = mt3*16 + g;
                su[O_AH + r0*P_X + col]     = pk2(coh_[nt][0], coh_[nt][1]);
                su[O_AH + (r0+8)*P_X + col] = pk2(coh_[nt][2], coh_[nt][3]);
            }
        }
        __syncthreads();
    }

    // ---- GEMM4: out = Wout @ att  (A = Wh from L2, B = att hi) ----
    {
        float c4[2][8][4];
        #pragma unroll
        for (int m = 0; m < 2; m++)
            #pragma unroll
            for (int nt = 0; nt < 8; nt++)
                c4[m][nt][0]=c4[m][nt][1]=c4[m][nt][2]=c4[m][nt][3]=0.f;

        #pragma unroll 2
        for (int ks = 0; ks < 16; ks++) {
            u32 ah[2][4];
            #pragma unroll
            for (int m = 0; m < 2; m++) {
                uint4 vh4 = *(const uint4*)&WA4h[(ks*16 + (w*2+m))*128 + lane*4];
                ah[m][0]=vh4.x; ah[m][1]=vh4.y; ah[m][2]=vh4.z; ah[m][3]=vh4.w;
            }
            #pragma unroll
            for (int nt = 0; nt < 8; nt++) {
                u32 bh[2];
                ldBf(bh, su + O_AH, nt*8, ks*8, P_X, g, tg);
                #pragma unroll
                for (int m = 0; m < 2; m++) {
                    mma16(c4[m][nt], ah[m], bh);
                }
            }
        }
        // C -> smem (pitch 66), +bias   (writes land in XH/XL region, now dead)
        #pragma unroll
        for (int m = 0; m < 2; m++) {
            int o0 = (w*2 + m)*16 + g;
            float b0v = sf[O_BOUT + o0], b1v = sf[O_BOUT + o0 + 8];
            #pragma unroll
            for (int nt = 0; nt < 8; nt++) {
                int col = nt*8 + 2*tg;
                sf[o0*66 + col]       = c4[m][nt][0] + b0v;
                sf[o0*66 + col + 1]   = c4[m][nt][1] + b0v;
                sf[(o0+8)*66 + col]   = c4[m][nt][2] + b1v;
                sf[(o0+8)*66 + col+1] = c4[m][nt][3] + b1v;
            }
        }
        __syncthreads();
        // coalesced store
        float* ob = out + ((size_t)bb << 24) + (size_t)(wh*8)*256 + ww*8;
        #pragma unroll 4
        for (int i = 0; i < 32; i++) {
            int j = i*512 + t*2;
            int o = j >> 6, pix = j & 63;
            float2 v = *(float2*)&sf[o*66 + pix];
            *(float2*)&ob[(size_t)o*65536 + (size_t)(pix>>3)*256 + (pix&7)] = v;
        }
    }
}

// ---------------- launch ----------------
extern "C" void kernel_launch(void* const* d_in, const int* in_sizes, int n_in,
                              void* d_out, int out_size)
{
    (void)in_sizes; (void)n_in; (void)out_size;
    const float* x     = (const float*)d_in[0];
    const float* g     = (const float*)d_in[1];
    const float* b     = (const float*)d_in[2];
    const float* w_qkv = (const float*)d_in[3];
    const float* w_out = (const float*)d_in[4];
    const float* b_out = (const float*)d_in[5];

    cudaFuncSetAttribute(attn_kernel, cudaFuncAttributeMaxDynamicSharedMemorySize, SMEM_BYTES);

    dpb_kernel<<<289, 64>>>(
        (const float*)d_in[6],  (const float*)d_in[7],
        (const float*)d_in[8],  (const float*)d_in[9],
        (const float*)d_in[10], (const float*)d_in[11],
        (const float*)d_in[12], (const float*)d_in[13],
        (const float*)d_in[14], (const float*)d_in[15],
        (const float*)d_in[16], (const float*)d_in[17],
        (const float*)d_in[18], (const float*)d_in[19]);
    conv_b1<<<1024, 64>>>(w_qkv);
    conv_a1v<<<256, 128>>>(w_qkv);
    conv_a4<<<256, 128>>>(w_out);
    attn_kernel<<<4096, 256, SMEM_BYTES>>>(x, g, b, b_out, (float*)d_out);
}

// round 9
// speedup vs baseline: 5.0607x; 1.1193x over previous
#include <cuda_runtime.h>
#include <cuda_fp16.h>
#include <math.h>

#define EPS 1e-5f
#define QK_SCALE 0.17677669529663687f
typedef unsigned int u32;

__device__ float g_table[289];
// fragment-major weight arrays (fp16x2 pairs, hi only), written by conv kernels
__device__ u32 WB1h[65536];   // qk B-frags [h][ks16][nt8][lane32][2]
__device__ u32 WA1h[32768];   // v  A-frags [h][ks16][mt2][lane32][4]
__device__ u32 WA4h[32768];   // out A-frags [ks16][mt16][lane32][4]

// ---------------- smem layout (u32 offsets) ----------------
#define P_X   132
#define O_XH  0
#define O_AH  16896
#define O_QKH 33792
#define O_QKL 36096
#define O_VH  38400
#define O_PH  40704
#define O_XF  16896      /* fp32 x temp, overlays AH region (dead at that time) */
#define O_TBL 47616
#define O_BOUT 47936
#define O_GW  48192
#define O_GB  48448
#define O_RED 48704
#define O_MEAN 49216
#define O_RSTD 49280
#define SMEM_U32 49344
#define SMEM_BYTES (SMEM_U32*4)

// ---------------- helpers ----------------
__device__ __forceinline__ u32 pk2(float x0, float x1){
    __half2 h = __floats2half2_rn(x0, x1);   // x0 -> lower half
    return *(u32*)&h;
}
__device__ __forceinline__ void sp2(float x0, float x1, u32& h, u32& l){
    h = pk2(x0, x1);
    __half2 hh = *(__half2*)&h;
    l = pk2(x0 - __low2float(hh), x1 - __high2float(hh));
}
__device__ __forceinline__ void mma16(float* c, const u32* a, const u32* b){
    asm volatile("mma.sync.aligned.m16n8k16.row.col.f32.f16.f16.f32 "
        "{%0,%1,%2,%3},{%4,%5,%6,%7},{%8,%9},{%0,%1,%2,%3};"
        : "+f"(c[0]),"+f"(c[1]),"+f"(c[2]),"+f"(c[3])
        : "r"(a[0]),"r"(a[1]),"r"(a[2]),"r"(a[3]),"r"(b[0]),"r"(b[1]));
}
__device__ __forceinline__ void ldA(u32* a, const u32* s, int r0, int cp_, int pitch, int g, int tg){
    a[0]=s[(r0+g)*pitch+cp_+tg];   a[1]=s[(r0+g+8)*pitch+cp_+tg];
    a[2]=s[(r0+g)*pitch+cp_+tg+4]; a[3]=s[(r0+g+8)*pitch+cp_+tg+4];
}
__device__ __forceinline__ void ldBf(u32* b, const u32* s, int n0, int cp_, int pitch, int g, int tg){
    b[0]=s[(n0+g)*pitch+cp_+tg];   b[1]=s[(n0+g)*pitch+cp_+tg+4];
}
__device__ __forceinline__ void cp16(void* s, const void* gm){
    u32 sa = (u32)__cvta_generic_to_shared(s);
    asm volatile("cp.async.cg.shared.global [%0], [%1], 16;" :: "r"(sa), "l"(gm));
}
__device__ __forceinline__ void cp_commit(){ asm volatile("cp.async.commit_group;"); }
__device__ __forceinline__ void cp_wait0(){ asm volatile("cp.async.wait_group 0;"); }

// ---------------- weight precompute: fragment-major fp16 hi layouts ----------------
__global__ void conv_b1(const float* __restrict__ w){
    int b = blockIdx.x;                  // (h*16+ks)*8+nt
    int h = b >> 7, ks = (b >> 3) & 15, nt = b & 7;
    int t = threadIdx.x;                 // lane*2 + j
    int lane = t >> 1, j = t & 1;
    int g = lane >> 2, tg = lane & 3;
    int r = nt*8 + g;
    int R = (r < 32) ? (h*32 + r) : (256 + h*32 + (r - 32));
    int p = ks*8 + tg + j*4;
    WB1h[b*64 + t] = pk2(w[R*256 + 2*p], w[R*256 + 2*p + 1]);
}
__global__ void conv_a1v(const float* __restrict__ w){
    int b = blockIdx.x;                  // (h*16+ks)*2+mt
    int h = b >> 5, mt = b & 1;
    int t = threadIdx.x;                 // lane*4 + j
    int lane = t >> 2, j = t & 3;
    int g = lane >> 2, tg = lane & 3;
    int vrow = mt*16 + g + (j & 1)*8;
    int R = 512 + h*32 + vrow;
    int ks = (b >> 1) & 15;
    int p = ks*8 + tg + (j >> 1)*4;
    WA1h[b*128 + t] = pk2(w[R*256 + 2*p], w[R*256 + 2*p + 1]);
}
__global__ void conv_a4(const float* __restrict__ w){
    int b = blockIdx.x;                  // ks*16 + mt
    int ks = b >> 4, mt = b & 15;
    int t = threadIdx.x;
    int lane = t >> 2, j = t & 3;
    int g = lane >> 2, tg = lane & 3;
    int R = mt*16 + g + (j & 1)*8;
    int p = ks*8 + tg + (j >> 1)*4;
    WA4h[b*128 + t] = pk2(w[R*256 + 2*p], w[R*256 + 2*p + 1]);
}

// ---------------- DPB MLP ----------------
__device__ __forceinline__ float blockreduce64(float v, float* red){
    #pragma unroll
    for (int o = 16; o > 0; o >>= 1) v += __shfl_xor_sync(0xffffffffu, v, o);
    int t = threadIdx.x;
    if ((t & 31) == 0) red[t >> 5] = v;
    __syncthreads();
    float r = red[0] + red[1];
    __syncthreads();
    return r;
}
__global__ void dpb_kernel(
    const float* __restrict__ w1, const float* __restrict__ b1,
    const float* __restrict__ g1, const float* __restrict__ bb1,
    const float* __restrict__ w2, const float* __restrict__ b2,
    const float* __restrict__ g2, const float* __restrict__ bb2,
    const float* __restrict__ w3, const float* __restrict__ b3,
    const float* __restrict__ g3, const float* __restrict__ bb3,
    const float* __restrict__ w4, const float* __restrict__ b4)
{
    __shared__ float hs[64];
    __shared__ float red[2];
    int r = blockIdx.x, j = threadIdx.x;
    float r0 = (float)(r / 17 - 8), r1 = (float)(r % 17 - 8);
    float v = r0 * w1[j] + r1 * w1[64 + j] + b1[j];
    float m = blockreduce64(v, red) * (1.f/64.f);
    float d = v - m;
    float var = blockreduce64(d*d, red) * (1.f/64.f);
    v = fmaxf(d * rsqrtf(var + EPS) * g1[j] + bb1[j], 0.f);
    hs[j] = v; __syncthreads();
    float a = b2[j];
    #pragma unroll 8
    for (int k = 0; k < 64; k++) a += hs[k] * w2[k*64 + j];
    m = blockreduce64(a, red) * (1.f/64.f);
    d = a - m;
    var = blockreduce64(d*d, red) * (1.f/64.f);
    a = fmaxf(d * rsqrtf(var + EPS) * g2[j] + bb2[j], 0.f);
    __syncthreads(); hs[j] = a; __syncthreads();
    a = b3[j];
    #pragma unroll 8
    for (int k = 0; k < 64; k++) a += hs[k] * w3[k*64 + j];
    m = blockreduce64(a, red) * (1.f/64.f);
    d = a - m;
    var = blockreduce64(d*d, red) * (1.f/64.f);
    a = fmaxf(d * rsqrtf(var + EPS) * g3[j] + bb3[j], 0.f);
    __syncthreads(); hs[j] = a; __syncthreads();
    float c = blockreduce64(hs[j] * w4[j], red);
    if (j == 0) g_table[r] = c + b4[0];
}

// ---------------- fused attention ----------------
__global__ __launch_bounds__(256, 1) void attn_kernel(
    const float* __restrict__ x, const float* __restrict__ gw, const float* __restrict__ gb,
    const float* __restrict__ b_out, float* __restrict__ out)
{
    extern __shared__ u32 su[];
    float* sf = (float*)su;
    const int t = threadIdx.x, lane = t & 31, w = t >> 5;
    const int g = lane >> 2, tg = lane & 3;
    const int wid = blockIdx.x;
    const int bb = wid >> 10, wh = (wid >> 5) & 31, ww = wid & 31;
    const float* xb = x + ((size_t)bb << 24) + (size_t)(wh * 8) * 256 + ww * 8;

    if (t < 289) sf[O_TBL + t] = g_table[t];
    sf[O_BOUT + t] = b_out[t];
    sf[O_GW + t] = gw[t];
    sf[O_GB + t] = gb[t];

    // ---- load x (fp32) ----
    #pragma unroll
    for (int i = 0; i < 8; i++) {
        int s = i * 256 + t, d = s >> 3, ph = s & 7;
        const float* src = xb + (size_t)d * 65536 + (size_t)ph * 256;
        float* dst = sf + O_XF + d * 68 + ph * 8;
        cp16(dst, src); cp16(dst + 4, src + 4);
    }
    cp_commit(); cp_wait0(); __syncthreads();

    // ---- LN stats ----
    {
        int pix = t & 63, q4 = t >> 6;
        float s = 0.f, ss = 0.f;
        #pragma unroll 8
        for (int d = q4*64; d < q4*64 + 64; d++) {
            float v = sf[O_XF + d*68 + pix]; s += v; ss += v*v;
        }
        sf[O_RED + t] = s; sf[O_RED + 256 + t] = ss;
        __syncthreads();
        if (t < 64) {
            float s0 = sf[O_RED+t] + sf[O_RED+64+t] + sf[O_RED+128+t] + sf[O_RED+192+t];
            float s1 = sf[O_RED+256+t] + sf[O_RED+320+t] + sf[O_RED+384+t] + sf[O_RED+448+t];
            float mn = s0 * (1.f/256.f);
            float vr = s1 * (1.f/256.f) - mn*mn;
            sf[O_MEAN + t] = mn;
            sf[O_RSTD + t] = rsqrtf(vr + EPS);
        }
        __syncthreads();
    }
    // ---- normalize + pack to fp16 pairs (hi only) ----
    {
        int pix = t & 63, cb = (t >> 6) * 64;
        float mn = sf[O_MEAN + pix], rs = sf[O_RSTD + pix];
        #pragma unroll 8
        for (int p = 0; p < 32; p++) {
            int c = cb + 2*p;
            float v0 = (sf[O_XF + c*68 + pix] - mn)*rs*sf[O_GW+c] + sf[O_GB+c];
            float v1 = (sf[O_XF + (c+1)*68 + pix] - mn)*rs*sf[O_GW+c+1] + sf[O_GB+c+1];
            su[O_XH + pix*P_X + cb/2 + p] = pk2(v0, v1);
        }
        __syncthreads();
    }

    const int mt  = w >> 1,  nb  = (w & 1) * 4;   // G1 qk tiles
    const int vmt = w & 1,   vnb = (w >> 1) * 2;  // G1 v tiles
    const int mt3 = w >> 1,  nb3 = (w & 1) * 2;   // GEMM3 tiles

    // ---- per-head ----
    for (int h = 0; h < 8; h++) {
        // GEMM1: all single-term fp16 hi (q/k/v)
        float cqh_[4][4], cvh_[2][4];
        #pragma unroll
        for (int i = 0; i < 4; i++)
            #pragma unroll
            for (int q = 0; q < 4; q++) { cqh_[i][q]=0.f; }
        #pragma unroll
        for (int i = 0; i < 2; i++)
            #pragma unroll
            for (int q = 0; q < 4; q++) { cvh_[i][q]=0.f; }

        #pragma unroll 4
        for (int ks = 0; ks < 16; ks++) {
            u32 axh[4];
            ldA(axh, su + O_XH, mt*16, ks*8, P_X, g, tg);
            uint4 awh4 = *(const uint4*)&WA1h[((h*16+ks)*2+vmt)*128 + lane*4];
            #pragma unroll
            for (int nt = 0; nt < 4; nt++) {
                uint2 b2h = *(const uint2*)&WB1h[((h*16+ks)*8+nb+nt)*64 + lane*2];
                u32 bh[2] = {b2h.x, b2h.y};
                mma16(cqh_[nt], axh, bh);   // Xh * Wh
            }
            u32 awh[4] = {awh4.x, awh4.y, awh4.z, awh4.w};
            #pragma unroll
            for (int vt = 0; vt < 2; vt++) {
                u32 bxh[2];
                ldBf(bxh, su + O_XH, (vnb+vt)*8, ks*8, P_X, g, tg);
                mma16(cvh_[vt], awh, bxh);  // Wh * Xh
            }
        }
        // epilogue: q tiles store hi+lo (GEMM2 A), k tiles hi only (GEMM2 B)
        #pragma unroll
        for (int nt = 0; nt < 4; nt++) {
            float c0 = cqh_[nt][0], c1 = cqh_[nt][1];
            float c2 = cqh_[nt][2], c3 = cqh_[nt][3];
            int isq = (nb + nt) < 4;            // channels < 32 -> q
            float sc = isq ? QK_SCALE : 1.f;
            int col = (nb+nt)*4 + tg, p0 = mt*16 + g;
            u32 hh, ll;
            sp2(c0*sc, c1*sc, hh, ll);
            su[O_QKH + p0*36 + col] = hh;
            if (isq) su[O_QKL + p0*36 + col] = ll;
            sp2(c2*sc, c3*sc, hh, ll);
            su[O_QKH + (p0+8)*36 + col] = hh;
            if (isq) su[O_QKL + (p0+8)*36 + col] = ll;
        }
        #pragma unroll
        for (int vt = 0; vt < 2; vt++) {
            int col = (vnb+vt)*4 + tg, r0 = vmt*16 + g;
            su[O_VH + r0*36 + col]     = pk2(cvh_[vt][0], cvh_[vt][1]);
            su[O_VH + (r0+8)*36 + col] = pk2(cvh_[vt][2], cvh_[vt][3]);
        }
        __syncthreads();

        // GEMM2 + softmax (warps 0..3): A = q hi+lo, B = k hi
        if (w < 4) {
            float csh_[8][4], csl_[8][4];
            #pragma unroll
            for (int nt = 0; nt < 8; nt++) {
                int i0 = w*16 + g, i1 = i0 + 8;
                int j0 = nt*8 + 2*tg, j1 = j0 + 1;
                csh_[nt][0] = sf[O_TBL + ((i0>>3)-(j0>>3)+7)*15 + (i0&7)-(j0&7)+7];
                csh_[nt][1] = sf[O_TBL + ((i0>>3)-(j1>>3)+7)*15 + (i0&7)-(j1&7)+7];
                csh_[nt][2] = sf[O_TBL + ((i1>>3)-(j0>>3)+7)*15 + (i1&7)-(j0&7)+7];
                csh_[nt][3] = sf[O_TBL + ((i1>>3)-(j1>>3)+7)*15 + (i1&7)-(j1&7)+7];
                csl_[nt][0]=csl_[nt][1]=csl_[nt][2]=csl_[nt][3]=0.f;
            }
            #pragma unroll
            for (int ks = 0; ks < 2; ks++) {
                u32 qh[4], ql[4];
                ldA(qh, su + O_QKH, w*16, ks*8, 36, g, tg);
                ldA(ql, su + O_QKL, w*16, ks*8, 36, g, tg);
                #pragma unroll
                for (int nt = 0; nt < 8; nt++) {
                    u32 bh[2];
                    ldBf(bh, su + O_QKH, nt*8, 16 + ks*8, 36, g, tg);
                    mma16(csh_[nt], qh, bh);
                    mma16(csl_[nt], ql, bh);
                }
            }
            float cs[8][4];
            #pragma unroll
            for (int nt = 0; nt < 8; nt++)
                #pragma unroll
                for (int q = 0; q < 4; q++) cs[nt][q] = csh_[nt][q] + csl_[nt][q];

            float mx0 = -1e30f, mx1 = -1e30f;
            #pragma unroll
            for (int nt = 0; nt < 8; nt++) {
                mx0 = fmaxf(mx0, fmaxf(cs[nt][0], cs[nt][1]));
                mx1 = fmaxf(mx1, fmaxf(cs[nt][2], cs[nt][3]));
            }
            mx0 = fmaxf(mx0, __shfl_xor_sync(0xffffffffu, mx0, 1));
            mx0 = fmaxf(mx0, __shfl_xor_sync(0xffffffffu, mx0, 2));
            mx1 = fmaxf(mx1, __shfl_xor_sync(0xffffffffu, mx1, 1));
            mx1 = fmaxf(mx1, __shfl_xor_sync(0xffffffffu, mx1, 2));
            float s0 = 0.f, s1 = 0.f;
            #pragma unroll
            for (int nt = 0; nt < 8; nt++) {
                cs[nt][0] = __expf(cs[nt][0] - mx0);
                cs[nt][1] = __expf(cs[nt][1] - mx0);
                cs[nt][2] = __expf(cs[nt][2] - mx1);
                cs[nt][3] = __expf(cs[nt][3] - mx1);
                s0 += cs[nt][0] + cs[nt][1];
                s1 += cs[nt][2] + cs[nt][3];
            }
            s0 += __shfl_xor_sync(0xffffffffu, s0, 1);
            s0 += __shfl_xor_sync(0xffffffffu, s0, 2);
            s1 += __shfl_xor_sync(0xffffffffu, s1, 1);
            s1 += __shfl_xor_sync(0xffffffffu, s1, 2);
            float i0 = 1.f / s0, i1 = 1.f / s1;
            int r0 = w*16 + g;
            #pragma unroll
            for (int nt = 0; nt < 8; nt++) {
                int col = nt*4 + tg;
                su[O_PH + r0*36 + col]     = pk2(cs[nt][0]*i0, cs[nt][1]*i0);
                su[O_PH + (r0+8)*36 + col] = pk2(cs[nt][2]*i1, cs[nt][3]*i1);
            }
        }
        __syncthreads();

        // GEMM3: out_h = P @ V  (A = P hi, B = V hi)
        {
            float coh_[2][4];
            #pragma unroll
            for (int i = 0; i < 2; i++)
                #pragma unroll
                for (int q = 0; q < 4; q++) { coh_[i][q]=0.f; }
            #pragma unroll
            for (int ks = 0; ks < 4; ks++) {
                u32 ph_[4];
                ldA(ph_, su + O_PH, mt3*16, ks*8, 36, g, tg);
                #pragma unroll
                for (int nt = 0; nt < 2; nt++) {
                    u32 bh[2];
                    ldBf(bh, su + O_VH, (nb3+nt)*8, ks*8, 36, g, tg);
                    mma16(coh_[nt], ph_, bh);
                }
            }
            #pragma unroll
            for (int nt = 0; nt < 2; nt++) {
                int col = h*16 + (nb3+nt)*4 + tg, r0 = mt3*16 + g;
                su[O_AH + r0*P_X + col]     = pk2(coh_[nt][0], coh_[nt][1]);
                su[O_AH + (r0+8)*P_X + col] = pk2(coh_[nt][2], coh_[nt][3]);
            }
        }
        __syncthreads();
    }

    // ---- GEMM4: out = Wout @ att  (A = Wh from L2, B = att hi) ----
    {
        float c4[2][8][4];
        #pragma unroll
        for (int m = 0; m < 2; m++)
            #pragma unroll
            for (int nt = 0; nt < 8; nt++)
                c4[m][nt][0]=c4[m][nt][1]=c4[m][nt][2]=c4[m][nt][3]=0.f;

        #pragma unroll 2
        for (int ks = 0; ks < 16; ks++) {
            u32 ah[2][4];
            #pragma unroll
            for (int m = 0; m < 2; m++) {
                uint4 vh4 = *(const uint4*)&WA4h[(ks*16 + (w*2+m))*128 + lane*4];
                ah[m][0]=vh4.x; ah[m][1]=vh4.y; ah[m][2]=vh4.z; ah[m][3]=vh4.w;
            }
            #pragma unroll
            for (int nt = 0; nt < 8; nt++) {
                u32 bh[2];
                ldBf(bh, su + O_AH, nt*8, ks*8, P_X, g, tg);
                #pragma unroll
                for (int m = 0; m < 2; m++) {
                    mma16(c4[m][nt], ah[m], bh);
                }
            }
        }
        // C -> smem (pitch 66), +bias   (writes land in XH region, now dead)
        #pragma unroll
        for (int m = 0; m < 2; m++) {
            int o0 = (w*2 + m)*16 + g;
            float b0v = sf[O_BOUT + o0], b1v = sf[O_BOUT + o0 + 8];
            #pragma unroll
            for (int nt = 0; nt < 8; nt++) {
                int col = nt*8 + 2*tg;
                sf[o0*66 + col]       = c4[m][nt][0] + b0v;
                sf[o0*66 + col + 1]   = c4[m][nt][1] + b0v;
                sf[(o0+8)*66 + col]   = c4[m][nt][2] + b1v;
                sf[(o0+8)*66 + col+1] = c4[m][nt][3] + b1v;
            }
        }
        __syncthreads();
        // coalesced store
        float* ob = out + ((size_t)bb << 24) + (size_t)(wh*8)*256 + ww*8;
        #pragma unroll 4
        for (int i = 0; i < 32; i++) {
            int j = i*512 + t*2;
            int o = j >> 6, pix = j & 63;
            float2 v = *(float2*)&sf[o*66 + pix];
            *(float2*)&ob[(size_t)o*65536 + (size_t)(pix>>3)*256 + (pix&7)] = v;
        }
    }
}

// ---------------- launch ----------------
extern "C" void kernel_launch(void* const* d_in, const int* in_sizes, int n_in,
                              void* d_out, int out_size)
{
    (void)in_sizes; (void)n_in; (void)out_size;
    const float* x     = (const float*)d_in[0];
    const float* g     = (const float*)d_in[1];
    const float* b     = (const float*)d_in[2];
    const float* w_qkv = (const float*)d_in[3];
    const float* w_out = (const float*)d_in[4];
    const float* b_out = (const float*)d_in[5];

    cudaFuncSetAttribute(attn_kernel, cudaFuncAttributeMaxDynamicSharedMemorySize, SMEM_BYTES);

    dpb_kernel<<<289, 64>>>(
        (const float*)d_in[6],  (const float*)d_in[7],
        (const float*)d_in[8],  (const float*)d_in[9],
        (const float*)d_in[10], (const float*)d_in[11],
        (const float*)d_in[12], (const float*)d_in[13],
        (const float*)d_in[14], (const float*)d_in[15],
        (const float*)d_in[16], (const float*)d_in[17],
        (const float*)d_in[18], (const float*)d_in[19]);
    conv_b1<<<1024, 64>>>(w_qkv);
    conv_a1v<<<256, 128>>>(w_qkv);
    conv_a4<<<256, 128>>>(w_out);
    attn_kernel<<<4096, 256, SMEM_BYTES>>>(x, g, b, b_out, (float*)d_out);
}

// round 11
// speedup vs baseline: 6.0708x; 1.1996x over previous
#include <cuda_runtime.h>
#include <cuda_fp16.h>
#include <math.h>

#define EPS 1e-5f
#define QK_SCALE 0.17677669529663687f
typedef unsigned int u32;

__device__ float g_table[289];
// fragment-major weight arrays (fp16x2 pairs, hi only), written by conv kernels
__device__ u32 WB1h[65536];   // qk B-frags [h][ks16][nt8][lane32][2]
__device__ u32 WA1h[32768];   // v  A-frags [h][ks16][mt2][lane32][4]
__device__ u32 WA4h[32768];   // out A-frags [ks16][mt16][lane32][4]

// ---------------- compact smem layout (u32 offsets), 2 CTAs/SM ----------------
#define P_X   132
#define O_XH   0        /* 64 x 132            = 8448  */
#define O_AH   8448     /* 64 x 132            = 8448  */
#define O_QKH  16896    /* 64 x 36             = 2304  */
#define O_QKL  19200    /* 64 x 36             = 2304  */
#define O_VH   21504    /* 32 x 36             = 1152  */
#define O_PH   22656    /* 64 x 36             = 2304  */
#define O_TBL  24960    /* 320 */
#define O_BOUT 25280    /* 256 */
#define O_RED  25536    /* 512 */
#define O_MEAN 26048    /* 64  */
#define O_RSTD 26112    /* 64  */
#define O_GW   26176    /* 256 */
#define O_GB   26432    /* 256 */
#define SMEM_U32 26688
#define SMEM_BYTES (SMEM_U32*4)
/* GEMM4 fp32 output staging: 256 rows x pitch 66 = 16896 floats overlaying
   XH+AH (offsets 0..16896), both dead after the GEMM4 k-loop + barrier. */

// ---------------- helpers ----------------
__device__ __forceinline__ u32 pk2(float x0, float x1){
    __half2 h = __floats2half2_rn(x0, x1);   // x0 -> lower half
    return *(u32*)&h;
}
__device__ __forceinline__ void sp2(float x0, float x1, u32& h, u32& l){
    h = pk2(x0, x1);
    __half2 hh = *(__half2*)&h;
    l = pk2(x0 - __low2float(hh), x1 - __high2float(hh));
}
__device__ __forceinline__ void mma16(float* c, const u32* a, const u32* b){
    asm volatile("mma.sync.aligned.m16n8k16.row.col.f32.f16.f16.f32 "
        "{%0,%1,%2,%3},{%4,%5,%6,%7},{%8,%9},{%0,%1,%2,%3};"
        : "+f"(c[0]),"+f"(c[1]),"+f"(c[2]),"+f"(c[3])
        : "r"(a[0]),"r"(a[1]),"r"(a[2]),"r"(a[3]),"r"(b[0]),"r"(b[1]));
}
__device__ __forceinline__ void ldA(u32* a, const u32* s, int r0, int cp_, int pitch, int g, int tg){
    a[0]=s[(r0+g)*pitch+cp_+tg];   a[1]=s[(r0+g+8)*pitch+cp_+tg];
    a[2]=s[(r0+g)*pitch+cp_+tg+4]; a[3]=s[(r0+g+8)*pitch+cp_+tg+4];
}
__device__ __forceinline__ void ldBf(u32* b, const u32* s, int n0, int cp_, int pitch, int g, int tg){
    b[0]=s[(n0+g)*pitch+cp_+tg];   b[1]=s[(n0+g)*pitch+cp_+tg+4];
}

// ---------------- weight precompute: fragment-major fp16 hi layouts ----------------
__global__ void conv_b1(const float* __restrict__ w){
    int b = blockIdx.x;                  // (h*16+ks)*8+nt
    int h = b >> 7, ks = (b >> 3) & 15, nt = b & 7;
    int t = threadIdx.x;                 // lane*2 + j
    int lane = t >> 1, j = t & 1;
    int g = lane >> 2, tg = lane & 3;
    int r = nt*8 + g;
    int R = (r < 32) ? (h*32 + r) : (256 + h*32 + (r - 32));
    int p = ks*8 + tg + j*4;
    WB1h[b*64 + t] = pk2(w[R*256 + 2*p], w[R*256 + 2*p + 1]);
}
__global__ void conv_a1v(const float* __restrict__ w){
    int b = blockIdx.x;                  // (h*16+ks)*2+mt
    int h = b >> 5, mt = b & 1;
    int t = threadIdx.x;                 // lane*4 + j
    int lane = t >> 2, j = t & 3;
    int g = lane >> 2, tg = lane & 3;
    int vrow = mt*16 + g + (j & 1)*8;
    int R = 512 + h*32 + vrow;
    int ks = (b >> 1) & 15;
    int p = ks*8 + tg + (j >> 1)*4;
    WA1h[b*128 + t] = pk2(w[R*256 + 2*p], w[R*256 + 2*p + 1]);
}
__global__ void conv_a4(const float* __restrict__ w){
    int b = blockIdx.x;                  // ks*16 + mt
    int ks = b >> 4, mt = b & 15;
    int t = threadIdx.x;
    int lane = t >> 2, j = t & 3;
    int g = lane >> 2, tg = lane & 3;
    int R = mt*16 + g + (j & 1)*8;
    int p = ks*8 + tg + (j >> 1)*4;
    WA4h[b*128 + t] = pk2(w[R*256 + 2*p], w[R*256 + 2*p + 1]);
}

// ---------------- DPB MLP ----------------
__device__ __forceinline__ float blockreduce64(float v, float* red){
    #pragma unroll
    for (int o = 16; o > 0; o >>= 1) v += __shfl_xor_sync(0xffffffffu, v, o);
    int t = threadIdx.x;
    if ((t & 31) == 0) red[t >> 5] = v;
    __syncthreads();
    float r = red[0] + red[1];
    __syncthreads();
    return r;
}
__global__ void dpb_kernel(
    const float* __restrict__ w1, const float* __restrict__ b1,
    const float* __restrict__ g1, const float* __restrict__ bb1,
    const float* __restrict__ w2, const float* __restrict__ b2,
    const float* __restrict__ g2, const float* __restrict__ bb2,
    const float* __restrict__ w3, const float* __restrict__ b3,
    const float* __restrict__ g3, const float* __restrict__ bb3,
    const float* __restrict__ w4, const float* __restrict__ b4)
{
    __shared__ float hs[64];
    __shared__ float red[2];
    int r = blockIdx.x, j = threadIdx.x;
    float r0 = (float)(r / 17 - 8), r1 = (float)(r % 17 - 8);
    float v = r0 * w1[j] + r1 * w1[64 + j] + b1[j];
    float m = blockreduce64(v, red) * (1.f/64.f);
    float d = v - m;
    float var = blockreduce64(d*d, red) * (1.f/64.f);
    v = fmaxf(d * rsqrtf(var + EPS) * g1[j] + bb1[j], 0.f);
    hs[j] = v; __syncthreads();
    float a = b2[j];
    #pragma unroll 8
    for (int k = 0; k < 64; k++) a += hs[k] * w2[k*64 + j];
    m = blockreduce64(a, red) * (1.f/64.f);
    d = a - m;
    var = blockreduce64(d*d, red) * (1.f/64.f);
    a = fmaxf(d * rsqrtf(var + EPS) * g2[j] + bb2[j], 0.f);
    __syncthreads(); hs[j] = a; __syncthreads();
    a = b3[j];
    #pragma unroll 8
    for (int k = 0; k < 64; k++) a += hs[k] * w3[k*64 + j];
    m = blockreduce64(a, red) * (1.f/64.f);
    d = a - m;
    var = blockreduce64(d*d, red) * (1.f/64.f);
    a = fmaxf(d * rsqrtf(var + EPS) * g3[j] + bb3[j], 0.f);
    __syncthreads(); hs[j] = a; __syncthreads();
    float c = blockreduce64(hs[j] * w4[j], red);
    if (j == 0) g_table[r] = c + b4[0];
}

// ---------------- fused attention (2 CTAs/SM) ----------------
__global__ __launch_bounds__(256, 2) void attn_kernel(
    const float* __restrict__ x, const float* __restrict__ gw, const float* __restrict__ gb,
    const float* __restrict__ b_out, float* __restrict__ out)
{
    extern __shared__ u32 su[];
    float* sf = (float*)su;
    const int t = threadIdx.x, lane = t & 31, w = t >> 5;
    const int g = lane >> 2, tg = lane & 3;
    const int wid = blockIdx.x;
    const int bb = wid >> 10, wh = (wid >> 5) & 31, ww = wid & 31;
    const float* xb = x + ((size_t)bb << 24) + (size_t)(wh * 8) * 256 + ww * 8;

    if (t < 289) sf[O_TBL + t] = g_table[t];
    sf[O_BOUT + t] = b_out[t];
    sf[O_GW + t] = gw[t];
    sf[O_GB + t] = gb[t];

    // ---- LN pass 1: stats streamed straight from global ----
    {
        int pix = t & 63, q4 = t >> 6;
        const float* xp = xb + (size_t)((pix >> 3) * 256 + (pix & 7))
                             + (size_t)(q4 * 64) * 65536;
        float s = 0.f, ss = 0.f;
        #pragma unroll 8
        for (int d = 0; d < 64; d++) {
            float v = xp[(size_t)d * 65536];
            s += v; ss += v * v;
        }
        sf[O_RED + t] = s; sf[O_RED + 256 + t] = ss;
        __syncthreads();
        if (t < 64) {
            float s0 = sf[O_RED+t] + sf[O_RED+64+t] + sf[O_RED+128+t] + sf[O_RED+192+t];
            float s1 = sf[O_RED+256+t] + sf[O_RED+320+t] + sf[O_RED+384+t] + sf[O_RED+448+t];
            float mn = s0 * (1.f/256.f);
            float vr = s1 * (1.f/256.f) - mn*mn;
            sf[O_MEAN + t] = mn;
            sf[O_RSTD + t] = rsqrtf(vr + EPS);
        }
        __syncthreads();
    }
    // ---- LN pass 2: re-read (L2-hot), normalize + pack to fp16 pairs ----
    {
        int pix = t & 63, cb = (t >> 6) * 64;
        float mn = sf[O_MEAN + pix], rs = sf[O_RSTD + pix];
        const float* xp = xb + (size_t)((pix >> 3) * 256 + (pix & 7));
        #pragma unroll 8
        for (int p = 0; p < 32; p++) {
            int c = cb + 2*p;
            float v0 = (xp[(size_t)c * 65536]     - mn)*rs*sf[O_GW+c]   + sf[O_GB+c];
            float v1 = (xp[(size_t)(c+1) * 65536] - mn)*rs*sf[O_GW+c+1] + sf[O_GB+c+1];
            su[O_XH + pix*P_X + cb/2 + p] = pk2(v0, v1);
        }
        __syncthreads();
    }

    const int mt  = w >> 1,  nb  = (w & 1) * 4;   // G1 qk tiles
    const int vmt = w & 1,   vnb = (w >> 1) * 2;  // G1 v tiles
    const int mt3 = w >> 1,  nb3 = (w & 1) * 2;   // GEMM3 tiles

    // ---- per-head ----
    for (int h = 0; h < 8; h++) {
        // GEMM1: all single-term fp16 hi (q/k/v)
        float cqh_[4][4], cvh_[2][4];
        #pragma unroll
        for (int i = 0; i < 4; i++)
            #pragma unroll
            for (int q = 0; q < 4; q++) { cqh_[i][q]=0.f; }
        #pragma unroll
        for (int i = 0; i < 2; i++)
            #pragma unroll
            for (int q = 0; q < 4; q++) { cvh_[i][q]=0.f; }

        #pragma unroll 4
        for (int ks = 0; ks < 16; ks++) {
            u32 axh[4];
            ldA(axh, su + O_XH, mt*16, ks*8, P_X, g, tg);
            uint4 awh4 = *(const uint4*)&WA1h[((h*16+ks)*2+vmt)*128 + lane*4];
            #pragma unroll
            for (int nt = 0; nt < 4; nt++) {
                uint2 b2h = *(const uint2*)&WB1h[((h*16+ks)*8+nb+nt)*64 + lane*2];
                u32 bh[2] = {b2h.x, b2h.y};
                mma16(cqh_[nt], axh, bh);   // Xh * Wh
            }
            u32 awh[4] = {awh4.x, awh4.y, awh4.z, awh4.w};
            #pragma unroll
            for (int vt = 0; vt < 2; vt++) {
                u32 bxh[2];
                ldBf(bxh, su + O_XH, (vnb+vt)*8, ks*8, P_X, g, tg);
                mma16(cvh_[vt], awh, bxh);  // Wh * Xh
            }
        }
        // epilogue: q tiles store hi+lo (GEMM2 A), k tiles hi only (GEMM2 B)
        #pragma unroll
        for (int nt = 0; nt < 4; nt++) {
            float c0 = cqh_[nt][0], c1 = cqh_[nt][1];
            float c2 = cqh_[nt][2], c3 = cqh_[nt][3];
            int isq = (nb + nt) < 4;            // channels < 32 -> q
            float sc = isq ? QK_SCALE : 1.f;
            int col = (nb+nt)*4 + tg, p0 = mt*16 + g;
            u32 hh, ll;
            sp2(c0*sc, c1*sc, hh, ll);
            su[O_QKH + p0*36 + col] = hh;
            if (isq) su[O_QKL + p0*36 + col] = ll;
            sp2(c2*sc, c3*sc, hh, ll);
            su[O_QKH + (p0+8)*36 + col] = hh;
            if (isq) su[O_QKL + (p0+8)*36 + col] = ll;
        }
        #pragma unroll
        for (int vt = 0; vt < 2; vt++) {
            int col = (vnb+vt)*4 + tg, r0 = vmt*16 + g;
            su[O_VH + r0*36 + col]     = pk2(cvh_[vt][0], cvh_[vt][1]);
            su[O_VH + (r0+8)*36 + col] = pk2(cvh_[vt][2], cvh_[vt][3]);
        }
        __syncthreads();

        // GEMM2 + softmax (warps 0..3): A = q hi+lo, B = k hi
        if (w < 4) {
            float csh_[8][4], csl_[8][4];
            #pragma unroll
            for (int nt = 0; nt < 8; nt++) {
                int i0 = w*16 + g, i1 = i0 + 8;
                int j0 = nt*8 + 2*tg, j1 = j0 + 1;
                csh_[nt][0] = sf[O_TBL + ((i0>>3)-(j0>>3)+7)*15 + (i0&7)-(j0&7)+7];
                csh_[nt][1] = sf[O_TBL + ((i0>>3)-(j1>>3)+7)*15 + (i0&7)-(j1&7)+7];
                csh_[nt][2] = sf[O_TBL + ((i1>>3)-(j0>>3)+7)*15 + (i1&7)-(j0&7)+7];
                csh_[nt][3] = sf[O_TBL + ((i1>>3)-(j1>>3)+7)*15 + (i1&7)-(j1&7)+7];
                csl_[nt][0]=csl_[nt][1]=csl_[nt][2]=csl_[nt][3]=0.f;
            }
            #pragma unroll
            for (int ks = 0; ks < 2; ks++) {
                u32 qh[4], ql[4];
                ldA(qh, su + O_QKH, w*16, ks*8, 36, g, tg);
                ldA(ql, su + O_QKL, w*16, ks*8, 36, g, tg);
                #pragma unroll
                for (int nt = 0; nt < 8; nt++) {
                    u32 bh[2];
                    ldBf(bh, su + O_QKH, nt*8, 16 + ks*8, 36, g, tg);
                    mma16(csh_[nt], qh, bh);
                    mma16(csl_[nt], ql, bh);
                }
            }
            float cs[8][4];
            #pragma unroll
            for (int nt = 0; nt < 8; nt++)
                #pragma unroll
                for (int q = 0; q < 4; q++) cs[nt][q] = csh_[nt][q] + csl_[nt][q];

            float mx0 = -1e30f, mx1 = -1e30f;
            #pragma unroll
            for (int nt = 0; nt < 8; nt++) {
                mx0 = fmaxf(mx0, fmaxf(cs[nt][0], cs[nt][1]));
                mx1 = fmaxf(mx1, fmaxf(cs[nt][2], cs[nt][3]));
            }
            mx0 = fmaxf(mx0, __shfl_xor_sync(0xffffffffu, mx0, 1));
            mx0 = fmaxf(mx0, __shfl_xor_sync(0xffffffffu, mx0, 2));
            mx1 = fmaxf(mx1, __shfl_xor_sync(0xffffffffu, mx1, 1));
            mx1 = fmaxf(mx1, __shfl_xor_sync(0xffffffffu, mx1, 2));
            float s0 = 0.f, s1 = 0.f;
            #pragma unroll
            for (int nt = 0; nt < 8; nt++) {
                cs[nt][0] = __expf(cs[nt][0] - mx0);
                cs[nt][1] = __expf(cs[nt][1] - mx0);
                cs[nt][2] = __expf(cs[nt][2] - mx1);
                cs[nt][3] = __expf(cs[nt][3] - mx1);
                s0 += cs[nt][0] + cs[nt][1];
                s1 += cs[nt][2] + cs[nt][3];
            }
            s0 += __shfl_xor_sync(0xffffffffu, s0, 1);
            s0 += __shfl_xor_sync(0xffffffffu, s0, 2);
            s1 += __shfl_xor_sync(0xffffffffu, s1, 1);
            s1 += __shfl_xor_sync(0xffffffffu, s1, 2);
            float i0 = 1.f / s0, i1 = 1.f / s1;
            int r0 = w*16 + g;
            #pragma unroll
            for (int nt = 0; nt < 8; nt++) {
                int col = nt*4 + tg;
                su[O_PH + r0*36 + col]     = pk2(cs[nt][0]*i0, cs[nt][1]*i0);
                su[O_PH + (r0+8)*36 + col] = pk2(cs[nt][2]*i1, cs[nt][3]*i1);
            }
        }
        __syncthreads();

        // GEMM3: out_h = P @ V  (A = P hi, B = V hi)
        {
            float coh_[2][4];
            #pragma unroll
            for (int i = 0; i < 2; i++)
                #pragma unroll
                for (int q = 0; q < 4; q++) { coh_[i][q]=0.f; }
            #pragma unroll
            for (int ks = 0; ks < 4; ks++) {
                u32 ph_[4];
                ldA(ph_, su + O_PH, mt3*16, ks*8, 36, g, tg);
                #pragma unroll
                for (int nt = 0; nt < 2; nt++) {
                    u32 bh[2];
                    ldBf(bh, su + O_VH, (nb3+nt)*8, ks*8, 36, g, tg);
                    mma16(coh_[nt], ph_, bh);
                }
            }
            #pragma unroll
            for (int nt = 0; nt < 2; nt++) {
                int col = h*16 + (nb3+nt)*4 + tg, r0 = mt3*16 + g;
                su[O_AH + r0*P_X + col]     = pk2(coh_[nt][0], coh_[nt][1]);
                su[O_AH + (r0+8)*P_X + col] = pk2(coh_[nt][2], coh_[nt][3]);
            }
        }
        __syncthreads();
    }

    // ---- GEMM4: out = Wout @ att  (A = Wh from L2, B = att hi) ----
    {
        float c4[2][8][4];
        #pragma unroll
        for (int m = 0; m < 2; m++)
            #pragma unroll
            for (int nt = 0; nt < 8; nt++)
                c4[m][nt][0]=c4[m][nt][1]=c4[m][nt][2]=c4[m][nt][3]=0.f;

        #pragma unroll 2
        for (int ks = 0; ks < 16; ks++) {
            u32 ah[2][4];
            #pragma unroll
            for (int m = 0; m < 2; m++) {
                uint4 vh4 = *(const uint4*)&WA4h[(ks*16 + (w*2+m))*128 + lane*4];
                ah[m][0]=vh4.x; ah[m][1]=vh4.y; ah[m][2]=vh4.z; ah[m][3]=vh4.w;
            }
            #pragma unroll
            for (int nt = 0; nt < 8; nt++) {
                u32 bh[2];
                ldBf(bh, su + O_AH, nt*8, ks*8, P_X, g, tg);
                #pragma unroll
                for (int m = 0; m < 2; m++) {
                    mma16(c4[m][nt], ah[m], bh);
                }
            }
        }
        // all warps done reading AH before staging overwrites it
        __syncthreads();

        // C -> smem (pitch 66), +bias  (staging overlays XH+AH, offsets 0..16896)
        #pragma unroll
        for (int m = 0; m < 2; m++) {
            int o0 = (w*2 + m)*16 + g;
            float b0v = sf[O_BOUT + o0], b1v = sf[O_BOUT + o0 + 8];
            #pragma unroll
            for (int nt = 0; nt < 8; nt++) {
                int col = nt*8 + 2*tg;
                sf[o0*66 + col]       = c4[m][nt][0] + b0v;
                sf[o0*66 + col + 1]   = c4[m][nt][1] + b0v;
                sf[(o0+8)*66 + col]   = c4[m][nt][2] + b1v;
                sf[(o0+8)*66 + col+1] = c4[m][nt][3] + b1v;
            }
        }
        __syncthreads();
        // coalesced store
        float* ob = out + ((size_t)bb << 24) + (size_t)(wh*8)*256 + ww*8;
        #pragma unroll 4
        for (int i = 0; i < 32; i++) {
            int j = i*512 + t*2;
            int o = j >> 6, pix = j & 63;
            float2 v = *(float2*)&sf[o*66 + pix];
            *(float2*)&ob[(size_t)o*65536 + (size_t)(pix>>3)*256 + (pix&7)] = v;
        }
    }
}

// ---------------- launch ----------------
extern "C" void kernel_launch(void* const* d_in, const int* in_sizes, int n_in,
                              void* d_out, int out_size)
{
    (void)in_sizes; (void)n_in; (void)out_size;
    const float* x     = (const float*)d_in[0];
    const float* g     = (const float*)d_in[1];
    const float* b     = (const float*)d_in[2];
    const float* w_qkv = (const float*)d_in[3];
    const float* w_out = (const float*)d_in[4];
    const float* b_out = (const float*)d_in[5];

    cudaFuncSetAttribute(attn_kernel, cudaFuncAttributeMaxDynamicSharedMemorySize, SMEM_BYTES);

    dpb_kernel<<<289, 64>>>(
        (const float*)d_in[6],  (const float*)d_in[7],
        (const float*)d_in[8],  (const float*)d_in[9],
        (const float*)d_in[10], (const float*)d_in[11],
        (const float*)d_in[12], (const float*)d_in[13],
        (const float*)d_in[14], (const float*)d_in[15],
        (const float*)d_in[16], (const float*)d_in[17],
        (const float*)d_in[18], (const float*)d_in[19]);
    conv_b1<<<1024, 64>>>(w_qkv);
    conv_a1v<<<256, 128>>>(w_qkv);
    conv_a4<<<256, 128>>>(w_out);
    attn_kernel<<<4096, 256, SMEM_BYTES>>>(x, g, b, b_out, (float*)d_out);
}

// round 12
// speedup vs baseline: 6.5432x; 1.0778x over previous
#include <cuda_runtime.h>
#include <cuda_fp16.h>
#include <math.h>

#define EPS 1e-5f
#define QK_SCALE 0.17677669529663687f
typedef unsigned int u32;

__device__ float g_table[289];
// fragment-major weight arrays (fp16x2 pairs, hi only), written by conv kernels
__device__ u32 WB1h[65536];   // qk B-frags [h][ks16][nt8][lane32][2]
__device__ u32 WA1h[32768];   // v  A-frags [h][ks16][mt2][lane32][4]
__device__ u32 WA4h[32768];   // out A-frags [ks16][mt16][lane32][4]

// ---------------- compact smem layout (u32 offsets), 2 CTAs/SM ----------------
#define P_X    132
#define O_XH   0        /* 64 x 132 = 8448 */
#define O_AH   8448     /* 64 x 132 = 8448 */
#define O_QKH0 16896    /* 64 x 36  = 2304 */
#define O_QKH1 19200    /* 64 x 36  = 2304 */
#define O_VH0  21504    /* 32 x 36  = 1152 */
#define O_VH1  22656    /* 32 x 36  = 1152 */
#define O_PH   23808    /* 64 x 36  = 2304 */
#define O_TBL  26112    /* 320 */
#define O_BOUT 26432    /* 256 */
#define O_RED  26688    /* 512 */
#define O_MEAN 27200    /* 64  */
#define O_RSTD 27264    /* 64  */
#define O_GW   27328    /* 256 */
#define O_GB   27584    /* 256 */
#define SMEM_U32 27840
#define SMEM_BYTES (SMEM_U32*4)
/* GEMM4 fp32 output staging: 256 rows x pitch 66 = 16896 floats overlaying
   XH+AH (offsets 0..16896), both dead after the GEMM4 k-loop + barrier. */

// ---------------- helpers ----------------
__device__ __forceinline__ u32 pk2(float x0, float x1){
    __half2 h = __floats2half2_rn(x0, x1);   // x0 -> lower half
    return *(u32*)&h;
}
__device__ __forceinline__ void mma16(float* c, const u32* a, const u32* b){
    asm volatile("mma.sync.aligned.m16n8k16.row.col.f32.f16.f16.f32 "
        "{%0,%1,%2,%3},{%4,%5,%6,%7},{%8,%9},{%0,%1,%2,%3};"
        : "+f"(c[0]),"+f"(c[1]),"+f"(c[2]),"+f"(c[3])
        : "r"(a[0]),"r"(a[1]),"r"(a[2]),"r"(a[3]),"r"(b[0]),"r"(b[1]));
}
__device__ __forceinline__ void ldA(u32* a, const u32* s, int r0, int cp_, int pitch, int g, int tg){
    a[0]=s[(r0+g)*pitch+cp_+tg];   a[1]=s[(r0+g+8)*pitch+cp_+tg];
    a[2]=s[(r0+g)*pitch+cp_+tg+4]; a[3]=s[(r0+g+8)*pitch+cp_+tg+4];
}
__device__ __forceinline__ void ldBf(u32* b, const u32* s, int n0, int cp_, int pitch, int g, int tg){
    b[0]=s[(n0+g)*pitch+cp_+tg];   b[1]=s[(n0+g)*pitch+cp_+tg+4];
}

// ---------------- weight precompute: fragment-major fp16 hi layouts ----------------
__global__ void conv_b1(const float* __restrict__ w){
    int b = blockIdx.x;                  // (h*16+ks)*8+nt
    int h = b >> 7, ks = (b >> 3) & 15, nt = b & 7;
    int t = threadIdx.x;                 // lane*2 + j
    int lane = t >> 1, j = t & 1;
    int g = lane >> 2, tg = lane & 3;
    int r = nt*8 + g;
    int R = (r < 32) ? (h*32 + r) : (256 + h*32 + (r - 32));
    int p = ks*8 + tg + j*4;
    WB1h[b*64 + t] = pk2(w[R*256 + 2*p], w[R*256 + 2*p + 1]);
}
__global__ void conv_a1v(const float* __restrict__ w){
    int b = blockIdx.x;                  // (h*16+ks)*2+mt
    int h = b >> 5, mt = b & 1;
    int t = threadIdx.x;                 // lane*4 + j
    int lane = t >> 2, j = t & 3;
    int g = lane >> 2, tg = lane & 3;
    int vrow = mt*16 + g + (j & 1)*8;
    int R = 512 + h*32 + vrow;
    int ks = (b >> 1) & 15;
    int p = ks*8 + tg + (j >> 1)*4;
    WA1h[b*128 + t] = pk2(w[R*256 + 2*p], w[R*256 + 2*p + 1]);
}
__global__ void conv_a4(const float* __restrict__ w){
    int b = blockIdx.x;                  // ks*16 + mt
    int ks = b >> 4, mt = b & 15;
    int t = threadIdx.x;
    int lane = t >> 2, j = t & 3;
    int g = lane >> 2, tg = lane & 3;
    int R = mt*16 + g + (j & 1)*8;
    int p = ks*8 + tg + (j >> 1)*4;
    WA4h[b*128 + t] = pk2(w[R*256 + 2*p], w[R*256 + 2*p + 1]);
}

// ---------------- DPB MLP ----------------
__device__ __forceinline__ float blockreduce64(float v, float* red){
    #pragma unroll
    for (int o = 16; o > 0; o >>= 1) v += __shfl_xor_sync(0xffffffffu, v, o);
    int t = threadIdx.x;
    if ((t & 31) == 0) red[t >> 5] = v;
    __syncthreads();
    float r = red[0] + red[1];
    __syncthreads();
    return r;
}
__global__ void dpb_kernel(
    const float* __restrict__ w1, const float* __restrict__ b1,
    const float* __restrict__ g1, const float* __restrict__ bb1,
    const float* __restrict__ w2, const float* __restrict__ b2,
    const float* __restrict__ g2, const float* __restrict__ bb2,
    const float* __restrict__ w3, const float* __restrict__ b3,
    const float* __restrict__ g3, const float* __restrict__ bb3,
    const float* __restrict__ w4, const float* __restrict__ b4)
{
    __shared__ float hs[64];
    __shared__ float red[2];
    int r = blockIdx.x, j = threadIdx.x;
    float r0 = (float)(r / 17 - 8), r1 = (float)(r % 17 - 8);
    float v = r0 * w1[j] + r1 * w1[64 + j] + b1[j];
    float m = blockreduce64(v, red) * (1.f/64.f);
    float d = v - m;
    float var = blockreduce64(d*d, red) * (1.f/64.f);
    v = fmaxf(d * rsqrtf(var + EPS) * g1[j] + bb1[j], 0.f);
    hs[j] = v; __syncthreads();
    float a = b2[j];
    #pragma unroll 8
    for (int k = 0; k < 64; k++) a += hs[k] * w2[k*64 + j];
    m = blockreduce64(a, red) * (1.f/64.f);
    d = a - m;
    var = blockreduce64(d*d, red) * (1.f/64.f);
    a = fmaxf(d * rsqrtf(var + EPS) * g2[j] + bb2[j], 0.f);
    __syncthreads(); hs[j] = a; __syncthreads();
    a = b3[j];
    #pragma unroll 8
    for (int k = 0; k < 64; k++) a += hs[k] * w3[k*64 + j];
    m = blockreduce64(a, red) * (1.f/64.f);
    d = a - m;
    var = blockreduce64(d*d, red) * (1.f/64.f);
    a = fmaxf(d * rsqrtf(var + EPS) * g3[j] + bb3[j], 0.f);
    __syncthreads(); hs[j] = a; __syncthreads();
    float c = blockreduce64(hs[j] * w4[j], red);
    if (j == 0) g_table[r] = c + b4[0];
}

// ---------------- fused attention (2 CTAs/SM) ----------------
__global__ __launch_bounds__(256, 2) void attn_kernel(
    const float* __restrict__ x, const float* __restrict__ gw, const float* __restrict__ gb,
    const float* __restrict__ b_out, float* __restrict__ out)
{
    extern __shared__ u32 su[];
    float* sf = (float*)su;
    const int t = threadIdx.x, lane = t & 31, w = t >> 5;
    const int g = lane >> 2, tg = lane & 3;
    const int wid = blockIdx.x;
    const int bb = wid >> 10, wh = (wid >> 5) & 31, ww = wid & 31;
    const float* xb = x + ((size_t)bb << 24) + (size_t)(wh * 8) * 256 + ww * 8;

    if (t < 289) sf[O_TBL + t] = g_table[t];
    sf[O_BOUT + t] = b_out[t];
    sf[O_GW + t] = gw[t];
    sf[O_GB + t] = gb[t];

    // ---- LN pass 1: single global read; fp32 stats + pack raw fp16 pairs ----
    {
        int pix = t & 63, q4 = t >> 6;
        const float* xp = xb + (size_t)((pix >> 3) * 256 + (pix & 7))
                             + (size_t)(q4 * 64) * 65536;
        float s = 0.f, ss = 0.f;
        #pragma unroll 4
        for (int j = 0; j < 32; j++) {
            float v0 = xp[(size_t)(2*j)     * 65536];
            float v1 = xp[(size_t)(2*j + 1) * 65536];
            s += v0 + v1; ss += v0*v0 + v1*v1;
            su[O_XH + pix*P_X + q4*32 + j] = pk2(v0, v1);
        }
        sf[O_RED + t] = s; sf[O_RED + 256 + t] = ss;
        __syncthreads();
        if (t < 64) {
            float s0 = sf[O_RED+t] + sf[O_RED+64+t] + sf[O_RED+128+t] + sf[O_RED+192+t];
            float s1 = sf[O_RED+256+t] + sf[O_RED+320+t] + sf[O_RED+384+t] + sf[O_RED+448+t];
            float mn = s0 * (1.f/256.f);
            float vr = s1 * (1.f/256.f) - mn*mn;
            sf[O_MEAN + t] = mn;
            sf[O_RSTD + t] = rsqrtf(vr + EPS);
        }
        __syncthreads();
    }
    // ---- LN pass 2: normalize XH in place (thread-local read/write) ----
    {
        int pix = t & 63, q4 = t >> 6;
        float mn = sf[O_MEAN + pix], rs = sf[O_RSTD + pix];
        #pragma unroll 8
        for (int j = 0; j < 32; j++) {
            int c = q4*64 + 2*j;
            u32 hv = su[O_XH + pix*P_X + q4*32 + j];
            __half2 h2 = *(__half2*)&hv;
            float v0 = (__low2float(h2)  - mn)*rs*sf[O_GW+c]   + sf[O_GB+c];
            float v1 = (__high2float(h2) - mn)*rs*sf[O_GW+c+1] + sf[O_GB+c+1];
            su[O_XH + pix*P_X + q4*32 + j] = pk2(v0, v1);
        }
        __syncthreads();
    }

    const int mt  = w >> 1,  nb  = (w & 1) * 4;   // G1 qk tiles
    const int vmt = w & 1,   vnb = (w >> 1) * 2;  // G1 v tiles
    const int mt3 = w >> 1,  nb3 = (w & 1) * 2;   // GEMM3 tiles

    // ---- per-head ----
    for (int h = 0; h < 8; h++) {
        u32* qkh = su + ((h & 1) ? O_QKH1 : O_QKH0);
        u32* vh  = su + ((h & 1) ? O_VH1  : O_VH0);

        // GEMM1: all single-term fp16 hi (q/k/v)
        float cqh_[4][4], cvh_[2][4];
        #pragma unroll
        for (int i = 0; i < 4; i++)
            #pragma unroll
            for (int q = 0; q < 4; q++) { cqh_[i][q]=0.f; }
        #pragma unroll
        for (int i = 0; i < 2; i++)
            #pragma unroll
            for (int q = 0; q < 4; q++) { cvh_[i][q]=0.f; }

        #pragma unroll 4
        for (int ks = 0; ks < 16; ks++) {
            u32 axh[4];
            ldA(axh, su + O_XH, mt*16, ks*8, P_X, g, tg);
            uint4 awh4 = *(const uint4*)&WA1h[((h*16+ks)*2+vmt)*128 + lane*4];
            #pragma unroll
            for (int nt = 0; nt < 4; nt++) {
                uint2 b2h = *(const uint2*)&WB1h[((h*16+ks)*8+nb+nt)*64 + lane*2];
                u32 bh[2] = {b2h.x, b2h.y};
                mma16(cqh_[nt], axh, bh);   // Xh * Wh
            }
            u32 awh[4] = {awh4.x, awh4.y, awh4.z, awh4.w};
            #pragma unroll
            for (int vt = 0; vt < 2; vt++) {
                u32 bxh[2];
                ldBf(bxh, su + O_XH, (vnb+vt)*8, ks*8, P_X, g, tg);
                mma16(cvh_[vt], awh, bxh);  // Wh * Xh
            }
        }
        // epilogue: q/k transposed pairs (hi only) to parity buffer
        #pragma unroll
        for (int nt = 0; nt < 4; nt++) {
            int isq = (nb + nt) < 4;            // channels < 32 -> q
            float sc = isq ? QK_SCALE : 1.f;
            int col = (nb+nt)*4 + tg, p0 = mt*16 + g;
            qkh[p0*36 + col]     = pk2(cqh_[nt][0]*sc, cqh_[nt][1]*sc);
            qkh[(p0+8)*36 + col] = pk2(cqh_[nt][2]*sc, cqh_[nt][3]*sc);
        }
        #pragma unroll
        for (int vt = 0; vt < 2; vt++) {
            int col = (vnb+vt)*4 + tg, r0 = vmt*16 + g;
            vh[r0*36 + col]     = pk2(cvh_[vt][0], cvh_[vt][1]);
            vh[(r0+8)*36 + col] = pk2(cvh_[vt][2], cvh_[vt][3]);
        }
        __syncthreads();    // SYNC-A

        // GEMM2 + softmax (warps 0..3): single fp16 chain
        if (w < 4) {
            float cs[8][4];
            #pragma unroll
            for (int nt = 0; nt < 8; nt++) {
                int i0 = w*16 + g, i1 = i0 + 8;
                int j0 = nt*8 + 2*tg, j1 = j0 + 1;
                cs[nt][0] = sf[O_TBL + ((i0>>3)-(j0>>3)+7)*15 + (i0&7)-(j0&7)+7];
                cs[nt][1] = sf[O_TBL + ((i0>>3)-(j1>>3)+7)*15 + (i0&7)-(j1&7)+7];
                cs[nt][2] = sf[O_TBL + ((i1>>3)-(j0>>3)+7)*15 + (i1&7)-(j0&7)+7];
                cs[nt][3] = sf[O_TBL + ((i1>>3)-(j1>>3)+7)*15 + (i1&7)-(j1&7)+7];
            }
            #pragma unroll
            for (int ks = 0; ks < 2; ks++) {
                u32 qh[4];
                ldA(qh, qkh, w*16, ks*8, 36, g, tg);
                #pragma unroll
                for (int nt = 0; nt < 8; nt++) {
                    u32 bh[2];
                    ldBf(bh, qkh, nt*8, 16 + ks*8, 36, g, tg);
                    mma16(cs[nt], qh, bh);
                }
            }
            float mx0 = -1e30f, mx1 = -1e30f;
            #pragma unroll
            for (int nt = 0; nt < 8; nt++) {
                mx0 = fmaxf(mx0, fmaxf(cs[nt][0], cs[nt][1]));
                mx1 = fmaxf(mx1, fmaxf(cs[nt][2], cs[nt][3]));
            }
            mx0 = fmaxf(mx0, __shfl_xor_sync(0xffffffffu, mx0, 1));
            mx0 = fmaxf(mx0, __shfl_xor_sync(0xffffffffu, mx0, 2));
            mx1 = fmaxf(mx1, __shfl_xor_sync(0xffffffffu, mx1, 1));
            mx1 = fmaxf(mx1, __shfl_xor_sync(0xffffffffu, mx1, 2));
            float s0 = 0.f, s1 = 0.f;
            #pragma unroll
            for (int nt = 0; nt < 8; nt++) {
                cs[nt][0] = __expf(cs[nt][0] - mx0);
                cs[nt][1] = __expf(cs[nt][1] - mx0);
                cs[nt][2] = __expf(cs[nt][2] - mx1);
                cs[nt][3] = __expf(cs[nt][3] - mx1);
                s0 += cs[nt][0] + cs[nt][1];
                s1 += cs[nt][2] + cs[nt][3];
            }
            s0 += __shfl_xor_sync(0xffffffffu, s0, 1);
            s0 += __shfl_xor_sync(0xffffffffu, s0, 2);
            s1 += __shfl_xor_sync(0xffffffffu, s1, 1);
            s1 += __shfl_xor_sync(0xffffffffu, s1, 2);
            float i0 = 1.f / s0, i1 = 1.f / s1;
            int r0 = w*16 + g;
            #pragma unroll
            for (int nt = 0; nt < 8; nt++) {
                int col = nt*4 + tg;
                su[O_PH + r0*36 + col]     = pk2(cs[nt][0]*i0, cs[nt][1]*i0);
                su[O_PH + (r0+8)*36 + col] = pk2(cs[nt][2]*i1, cs[nt][3]*i1);
            }
        }
        __syncthreads();    // SYNC-B

        // GEMM3: out_h = P @ V  (A = P hi, B = V hi)
        {
            float coh_[2][4];
            #pragma unroll
            for (int i = 0; i < 2; i++)
                #pragma unroll
                for (int q = 0; q < 4; q++) { coh_[i][q]=0.f; }
            #pragma unroll
            for (int ks = 0; ks < 4; ks++) {
                u32 ph_[4];
                ldA(ph_, su + O_PH, mt3*16, ks*8, 36, g, tg);
                #pragma unroll
                for (int nt = 0; nt < 2; nt++) {
                    u32 bh[2];
                    ldBf(bh, vh, (nb3+nt)*8, ks*8, 36, g, tg);
                    mma16(coh_[nt], ph_, bh);
                }
            }
            #pragma unroll
            for (int nt = 0; nt < 2; nt++) {
                int col = h*16 + (nb3+nt)*4 + tg, r0 = mt3*16 + g;
                su[O_AH + r0*P_X + col]     = pk2(coh_[nt][0], coh_[nt][1]);
                su[O_AH + (r0+8)*P_X + col] = pk2(coh_[nt][2], coh_[nt][3]);
            }
        }
        // no closing barrier: parity buffers + SYNC-A/B ordering make next
        // head's epilogue writes safe vs this head's GEMM2/GEMM3 readers.
    }
    __syncthreads();    // AH complete before GEMM4

    // ---- GEMM4: out = Wout @ att  (A = Wh from L2, B = att hi) ----
    {
        float c4[2][8][4];
        #pragma unroll
        for (int m = 0; m < 2; m++)
            #pragma unroll
            for (int nt = 0; nt < 8; nt++)
                c4[m][nt][0]=c4[m][nt][1]=c4[m][nt][2]=c4[m][nt][3]=0.f;

        #pragma unroll 2
        for (int ks = 0; ks < 16; ks++) {
            u32 ah[2][4];
            #pragma unroll
            for (int m = 0; m < 2; m++) {
                uint4 vh4 = *(const uint4*)&WA4h[(ks*16 + (w*2+m))*128 + lane*4];
                ah[m][0]=vh4.x; ah[m][1]=vh4.y; ah[m][2]=vh4.z; ah[m][3]=vh4.w;
            }
            #pragma unroll
            for (int nt = 0; nt < 8; nt++) {
                u32 bh[2];
                ldBf(bh, su + O_AH, nt*8, ks*8, P_X, g, tg);
                #pragma unroll
                for (int m = 0; m < 2; m++) {
                    mma16(c4[m][nt], ah[m], bh);
                }
            }
        }
        // all warps done reading AH before staging overwrites it
        __syncthreads();

        // C -> smem (pitch 66), +bias  (staging overlays XH+AH, offsets 0..16896)
        #pragma unroll
        for (int m = 0; m < 2; m++) {
            int o0 = (w*2 + m)*16 + g;
            float b0v = sf[O_BOUT + o0], b1v = sf[O_BOUT + o0 + 8];
            #pragma unroll
            for (int nt = 0; nt < 8; nt++) {
                int col = nt*8 + 2*tg;
                sf[o0*66 + col]       = c4[m][nt][0] + b0v;
                sf[o0*66 + col + 1]   = c4[m][nt][1] + b0v;
                sf[(o0+8)*66 + col]   = c4[m][nt][2] + b1v;
                sf[(o0+8)*66 + col+1] = c4[m][nt][3] + b1v;
            }
        }
        __syncthreads();
        // coalesced store
        float* ob = out + ((size_t)bb << 24) + (size_t)(wh*8)*256 + ww*8;
        #pragma unroll 4
        for (int i = 0; i < 32; i++) {
            int j = i*512 + t*2;
            int o = j >> 6, pix = j & 63;
            float2 v = *(float2*)&sf[o*66 + pix];
            *(float2*)&ob[(size_t)o*65536 + (size_t)(pix>>3)*256 + (pix&7)] = v;
        }
    }
}

// ---------------- launch ----------------
extern "C" void kernel_launch(void* const* d_in, const int* in_sizes, int n_in,
                              void* d_out, int out_size)
{
    (void)in_sizes; (void)n_in; (void)out_size;
    const float* x     = (const float*)d_in[0];
    const float* g     = (const float*)d_in[1];
    const float* b     = (const float*)d_in[2];
    const float* w_qkv = (const float*)d_in[3];
    const float* w_out = (const float*)d_in[4];
    const float* b_out = (const float*)d_in[5];

    cudaFuncSetAttribute(attn_kernel, cudaFuncAttributeMaxDynamicSharedMemorySize, SMEM_BYTES);

    dpb_kernel<<<289, 64>>>(
        (const float*)d_in[6],  (const float*)d_in[7],
        (const float*)d_in[8],  (const float*)d_in[9],
        (const float*)d_in[10], (const float*)d_in[11],
        (const float*)d_in[12], (const float*)d_in[13],
        (const float*)d_in[14], (const float*)d_in[15],
        (const float*)d_in[16], (const float*)d_in[17],
        (const float*)d_in[18], (const float*)d_in[19]);
    conv_b1<<<1024, 64>>>(w_qkv);
    conv_a1v<<<256, 128>>>(w_qkv);
    conv_a4<<<256, 128>>>(w_out);
    attn_kernel<<<4096, 256, SMEM_BYTES>>>(x, g, b, b_out, (float*)d_out);
}

// round 14
// speedup vs baseline: 6.8895x; 1.0529x over previous
#include <cuda_runtime.h>
#include <cuda_fp16.h>
#include <math.h>

#define EPS 1e-5f
#define QK_SCALE 0.17677669529663687f
typedef unsigned int u32;

__device__ float g_table[289];
// fragment-major weight arrays (fp16x2 pairs, hi only), written by conv kernels
__device__ u32 WB1h[65536];   // qk B-frags [h][ks16][nt8][lane32][2]
__device__ u32 WA1h[32768];   // v  A-frags [h][ks16][mt2][lane32][4]
__device__ u32 WA4h[32768];   // out A-frags [ks16][mt16][lane32][4]

// ---------------- compact smem layout (u32 offsets), 2 CTAs/SM ----------------
#define P_X    132
#define O_XH   0        /* 64 x 132 = 8448 */
#define O_AH   8448     /* 64 x 132 = 8448 */
#define O_QKH0 16896    /* 64 x 36  = 2304 */
#define O_QKH1 19200    /* 64 x 36  = 2304 */
#define O_VH0  21504    /* 32 x 36  = 1152 */
#define O_VH1  22656    /* 32 x 36  = 1152 */
#define O_PH   23808    /* 64 x 36  = 2304 */
#define O_TBL  26112    /* 320 */
#define O_BOUT 26432    /* 256 */
#define O_RED  26688    /* 512 */
#define O_MEAN 27200    /* 64  */
#define O_RSTD 27264    /* 64  */
#define O_GW   27328    /* 256 */
#define O_GB   27584    /* 256 */
#define SMEM_U32 27840
#define SMEM_BYTES (SMEM_U32*4)

// ---------------- helpers ----------------
__device__ __forceinline__ u32 pk2(float x0, float x1){
    __half2 h = __floats2half2_rn(x0, x1);   // x0 -> lower half
    return *(u32*)&h;
}
__device__ __forceinline__ void mma16(float* c, const u32* a, const u32* b){
    asm volatile("mma.sync.aligned.m16n8k16.row.col.f32.f16.f16.f32 "
        "{%0,%1,%2,%3},{%4,%5,%6,%7},{%8,%9},{%0,%1,%2,%3};"
        : "+f"(c[0]),"+f"(c[1]),"+f"(c[2]),"+f"(c[3])
        : "r"(a[0]),"r"(a[1]),"r"(a[2]),"r"(a[3]),"r"(b[0]),"r"(b[1]));
}
__device__ __forceinline__ void ldA(u32* a, const u32* s, int r0, int cp_, int pitch, int g, int tg){
    a[0]=s[(r0+g)*pitch+cp_+tg];   a[1]=s[(r0+g+8)*pitch+cp_+tg];
    a[2]=s[(r0+g)*pitch+cp_+tg+4]; a[3]=s[(r0+g+8)*pitch+cp_+tg+4];
}
__device__ __forceinline__ void ldBf(u32* b, const u32* s, int n0, int cp_, int pitch, int g, int tg){
    b[0]=s[(n0+g)*pitch+cp_+tg];   b[1]=s[(n0+g)*pitch+cp_+tg+4];
}

// ---------------- weight precompute: fragment-major fp16 hi layouts ----------------
__global__ void conv_b1(const float* __restrict__ w){
    int b = blockIdx.x;                  // (h*16+ks)*8+nt
    int h = b >> 7, ks = (b >> 3) & 15, nt = b & 7;
    int t = threadIdx.x;                 // lane*2 + j
    int lane = t >> 1, j = t & 1;
    int g = lane >> 2, tg = lane & 3;
    int r = nt*8 + g;
    int R = (r < 32) ? (h*32 + r) : (256 + h*32 + (r - 32));
    int p = ks*8 + tg + j*4;
    WB1h[b*64 + t] = pk2(w[R*256 + 2*p], w[R*256 + 2*p + 1]);
}
__global__ void conv_a1v(const float* __restrict__ w){
    int b = blockIdx.x;                  // (h*16+ks)*2+mt
    int h = b >> 5, mt = b & 1;
    int t = threadIdx.x;                 // lane*4 + j
    int lane = t >> 2, j = t & 3;
    int g = lane >> 2, tg = lane & 3;
    int vrow = mt*16 + g + (j & 1)*8;
    int R = 512 + h*32 + vrow;
    int ks = (b >> 1) & 15;
    int p = ks*8 + tg + (j >> 1)*4;
    WA1h[b*128 + t] = pk2(w[R*256 + 2*p], w[R*256 + 2*p + 1]);
}
__global__ void conv_a4(const float* __restrict__ w){
    int b = blockIdx.x;                  // ks*16 + mt
    int ks = b >> 4, mt = b & 15;
    int t = threadIdx.x;
    int lane = t >> 2, j = t & 3;
    int g = lane >> 2, tg = lane & 3;
    int R = mt*16 + g + (j & 1)*8;
    int p = ks*8 + tg + (j >> 1)*4;
    WA4h[b*128 + t] = pk2(w[R*256 + 2*p], w[R*256 + 2*p + 1]);
}

// ---------------- DPB MLP ----------------
__device__ __forceinline__ float blockreduce64(float v, float* red){
    #pragma unroll
    for (int o = 16; o > 0; o >>= 1) v += __shfl_xor_sync(0xffffffffu, v, o);
    int t = threadIdx.x;
    if ((t & 31) == 0) red[t >> 5] = v;
    __syncthreads();
    float r = red[0] + red[1];
    __syncthreads();
    return r;
}
__global__ void dpb_kernel(
    const float* __restrict__ w1, const float* __restrict__ b1,
    const float* __restrict__ g1, const float* __restrict__ bb1,
    const float* __restrict__ w2, const float* __restrict__ b2,
    const float* __restrict__ g2, const float* __restrict__ bb2,
    const float* __restrict__ w3, const float* __restrict__ b3,
    const float* __restrict__ g3, const float* __restrict__ bb3,
    const float* __restrict__ w4, const float* __restrict__ b4)
{
    __shared__ float hs[64];
    __shared__ float red[2];
    int r = blockIdx.x, j = threadIdx.x;
    float r0 = (float)(r / 17 - 8), r1 = (float)(r % 17 - 8);
    float v = r0 * w1[j] + r1 * w1[64 + j] + b1[j];
    float m = blockreduce64(v, red) * (1.f/64.f);
    float d = v - m;
    float var = blockreduce64(d*d, red) * (1.f/64.f);
    v = fmaxf(d * rsqrtf(var + EPS) * g1[j] + bb1[j], 0.f);
    hs[j] = v; __syncthreads();
    float a = b2[j];
    #pragma unroll 8
    for (int k = 0; k < 64; k++) a += hs[k] * w2[k*64 + j];
    m = blockreduce64(a, red) * (1.f/64.f);
    d = a - m;
    var = blockreduce64(d*d, red) * (1.f/64.f);
    a = fmaxf(d * rsqrtf(var + EPS) * g2[j] + bb2[j], 0.f);
    __syncthreads(); hs[j] = a; __syncthreads();
    a = b3[j];
    #pragma unroll 8
    for (int k = 0; k < 64; k++) a += hs[k] * w3[k*64 + j];
    m = blockreduce64(a, red) * (1.f/64.f);
    d = a - m;
    var = blockreduce64(d*d, red) * (1.f/64.f);
    a = fmaxf(d * rsqrtf(var + EPS) * g3[j] + bb3[j], 0.f);
    __syncthreads(); hs[j] = a; __syncthreads();
    float c = blockreduce64(hs[j] * w4[j], red);
    if (j == 0) g_table[r] = c + b4[0];
}

// ---------------- fused attention (2 CTAs/SM) ----------------
__global__ __launch_bounds__(256, 2) void attn_kernel(
    const float* __restrict__ x, const float* __restrict__ gw, const float* __restrict__ gb,
    const float* __restrict__ b_out, float* __restrict__ out)
{
    extern __shared__ u32 su[];
    float* sf = (float*)su;
    const int t = threadIdx.x, lane = t & 31, w = t >> 5;
    const int g = lane >> 2, tg = lane & 3;
    const int wid = blockIdx.x;
    const int bb = wid >> 10, wh = (wid >> 5) & 31, ww = wid & 31;
    const float* xb = x + ((size_t)bb << 24) + (size_t)(wh * 8) * 256 + ww * 8;

    if (t < 289) sf[O_TBL + t] = g_table[t];
    sf[O_BOUT + t] = b_out[t];
    sf[O_GW + t] = gw[t];
    sf[O_GB + t] = gb[t];

    // ---- LN pass 1: single global read; fp32 stats + pack raw fp16 pairs ----
    {
        int pix = t & 63, q4 = t >> 6;
        const float* xp = xb + (size_t)((pix >> 3) * 256 + (pix & 7))
                             + (size_t)(q4 * 64) * 65536;
        float s = 0.f, ss = 0.f;
        #pragma unroll 4
        for (int j = 0; j < 32; j++) {
            float v0 = xp[(size_t)(2*j)     * 65536];
            float v1 = xp[(size_t)(2*j + 1) * 65536];
            s += v0 + v1; ss += v0*v0 + v1*v1;
            su[O_XH + pix*P_X + q4*32 + j] = pk2(v0, v1);
        }
        sf[O_RED + t] = s; sf[O_RED + 256 + t] = ss;
        __syncthreads();
        if (t < 64) {
            float s0 = sf[O_RED+t] + sf[O_RED+64+t] + sf[O_RED+128+t] + sf[O_RED+192+t];
            float s1 = sf[O_RED+256+t] + sf[O_RED+320+t] + sf[O_RED+384+t] + sf[O_RED+448+t];
            float mn = s0 * (1.f/256.f);
            float vr = s1 * (1.f/256.f) - mn*mn;
            sf[O_MEAN + t] = mn;
            sf[O_RSTD + t] = rsqrtf(vr + EPS);
        }
        __syncthreads();
    }
    // ---- LN pass 2: normalize XH in place (thread-local read/write) ----
    {
        int pix = t & 63, q4 = t >> 6;
        float mn = sf[O_MEAN + pix], rs = sf[O_RSTD + pix];
        #pragma unroll 8
        for (int j = 0; j < 32; j++) {
            int c = q4*64 + 2*j;
            u32 hv = su[O_XH + pix*P_X + q4*32 + j];
            __half2 h2 = *(__half2*)&hv;
            float v0 = (__low2float(h2)  - mn)*rs*sf[O_GW+c]   + sf[O_GB+c];
            float v1 = (__high2float(h2) - mn)*rs*sf[O_GW+c+1] + sf[O_GB+c+1];
            su[O_XH + pix*P_X + q4*32 + j] = pk2(v0, v1);
        }
        __syncthreads();
    }

    const int mt  = w >> 1,  nb  = (w & 1) * 4;   // G1 qk tiles
    const int vmt = w & 1,   vnb = (w >> 1) * 2;  // G1 v tiles
    const int mt3 = w >> 1,  nb3 = (w & 1) * 2;   // GEMM3 tiles

    // ---- per-head ----
    for (int h = 0; h < 8; h++) {
        u32* qkh = su + ((h & 1) ? O_QKH1 : O_QKH0);
        u32* vh  = su + ((h & 1) ? O_VH1  : O_VH0);

        // GEMM1: all single-term fp16 hi (q/k/v)
        float cqh_[4][4], cvh_[2][4];
        #pragma unroll
        for (int i = 0; i < 4; i++)
            #pragma unroll
            for (int q = 0; q < 4; q++) { cqh_[i][q]=0.f; }
        #pragma unroll
        for (int i = 0; i < 2; i++)
            #pragma unroll
            for (int q = 0; q < 4; q++) { cvh_[i][q]=0.f; }

        #pragma unroll 4
        for (int ks = 0; ks < 16; ks++) {
            u32 axh[4];
            ldA(axh, su + O_XH, mt*16, ks*8, P_X, g, tg);
            uint4 awh4 = *(const uint4*)&WA1h[((h*16+ks)*2+vmt)*128 + lane*4];
            #pragma unroll
            for (int nt = 0; nt < 4; nt++) {
                uint2 b2h = *(const uint2*)&WB1h[((h*16+ks)*8+nb+nt)*64 + lane*2];
                u32 bh[2] = {b2h.x, b2h.y};
                mma16(cqh_[nt], axh, bh);   // Xh * Wh
            }
            u32 awh[4] = {awh4.x, awh4.y, awh4.z, awh4.w};
            #pragma unroll
            for (int vt = 0; vt < 2; vt++) {
                u32 bxh[2];
                ldBf(bxh, su + O_XH, (vnb+vt)*8, ks*8, P_X, g, tg);
                mma16(cvh_[vt], awh, bxh);  // Wh * Xh
            }
        }
        // epilogue: q/k transposed pairs (hi only) to parity buffer
        #pragma unroll
        for (int nt = 0; nt < 4; nt++) {
            int isq = (nb + nt) < 4;            // channels < 32 -> q
            float sc = isq ? QK_SCALE : 1.f;
            int col = (nb+nt)*4 + tg, p0 = mt*16 + g;
            qkh[p0*36 + col]     = pk2(cqh_[nt][0]*sc, cqh_[nt][1]*sc);
            qkh[(p0+8)*36 + col] = pk2(cqh_[nt][2]*sc, cqh_[nt][3]*sc);
        }
        #pragma unroll
        for (int vt = 0; vt < 2; vt++) {
            int col = (vnb+vt)*4 + tg, r0 = vmt*16 + g;
            vh[r0*36 + col]     = pk2(cvh_[vt][0], cvh_[vt][1]);
            vh[(r0+8)*36 + col] = pk2(cvh_[vt][2], cvh_[vt][3]);
        }
        __syncthreads();    // SYNC-A

        // GEMM2 + softmax (warps 0..3): single fp16 chain
        if (w < 4) {
            float cs[8][4];
            #pragma unroll
            for (int nt = 0; nt < 8; nt++) {
                int i0 = w*16 + g, i1 = i0 + 8;
                int j0 = nt*8 + 2*tg, j1 = j0 + 1;
                cs[nt][0] = sf[O_TBL + ((i0>>3)-(j0>>3)+7)*15 + (i0&7)-(j0&7)+7];
                cs[nt][1] = sf[O_TBL + ((i0>>3)-(j1>>3)+7)*15 + (i0&7)-(j1&7)+7];
                cs[nt][2] = sf[O_TBL + ((i1>>3)-(j0>>3)+7)*15 + (i1&7)-(j0&7)+7];
                cs[nt][3] = sf[O_TBL + ((i1>>3)-(j1>>3)+7)*15 + (i1&7)-(j1&7)+7];
            }
            #pragma unroll
            for (int ks = 0; ks < 2; ks++) {
                u32 qh[4];
                ldA(qh, qkh, w*16, ks*8, 36, g, tg);
                #pragma unroll
                for (int nt = 0; nt < 8; nt++) {
                    u32 bh[2];
                    ldBf(bh, qkh, nt*8, 16 + ks*8, 36, g, tg);
                    mma16(cs[nt], qh, bh);
                }
            }
            float mx0 = -1e30f, mx1 = -1e30f;
            #pragma unroll
            for (int nt = 0; nt < 8; nt++) {
                mx0 = fmaxf(mx0, fmaxf(cs[nt][0], cs[nt][1]));
                mx1 = fmaxf(mx1, fmaxf(cs[nt][2], cs[nt][3]));
            }
            mx0 = fmaxf(mx0, __shfl_xor_sync(0xffffffffu, mx0, 1));
            mx0 = fmaxf(mx0, __shfl_xor_sync(0xffffffffu, mx0, 2));
            mx1 = fmaxf(mx1, __shfl_xor_sync(0xffffffffu, mx1, 1));
            mx1 = fmaxf(mx1, __shfl_xor_sync(0xffffffffu, mx1, 2));
            float s0 = 0.f, s1 = 0.f;
            #pragma unroll
            for (int nt = 0; nt < 8; nt++) {
                cs[nt][0] = __expf(cs[nt][0] - mx0);
                cs[nt][1] = __expf(cs[nt][1] - mx0);
                cs[nt][2] = __expf(cs[nt][2] - mx1);
                cs[nt][3] = __expf(cs[nt][3] - mx1);
                s0 += cs[nt][0] + cs[nt][1];
                s1 += cs[nt][2] + cs[nt][3];
            }
            s0 += __shfl_xor_sync(0xffffffffu, s0, 1);
            s0 += __shfl_xor_sync(0xffffffffu, s0, 2);
            s1 += __shfl_xor_sync(0xffffffffu, s1, 1);
            s1 += __shfl_xor_sync(0xffffffffu, s1, 2);
            float i0 = 1.f / s0, i1 = 1.f / s1;
            int r0 = w*16 + g;
            #pragma unroll
            for (int nt = 0; nt < 8; nt++) {
                int col = nt*4 + tg;
                su[O_PH + r0*36 + col]     = pk2(cs[nt][0]*i0, cs[nt][1]*i0);
                su[O_PH + (r0+8)*36 + col] = pk2(cs[nt][2]*i1, cs[nt][3]*i1);
            }
        }
        __syncthreads();    // SYNC-B

        // GEMM3: out_h = P @ V  (A = P hi, B = V hi)
        {
            float coh_[2][4];
            #pragma unroll
            for (int i = 0; i < 2; i++)
                #pragma unroll
                for (int q = 0; q < 4; q++) { coh_[i][q]=0.f; }
            #pragma unroll
            for (int ks = 0; ks < 4; ks++) {
                u32 ph_[4];
                ldA(ph_, su + O_PH, mt3*16, ks*8, 36, g, tg);
                #pragma unroll
                for (int nt = 0; nt < 2; nt++) {
                    u32 bh[2];
                    ldBf(bh, vh, (nb3+nt)*8, ks*8, 36, g, tg);
                    mma16(coh_[nt], ph_, bh);
                }
            }
            #pragma unroll
            for (int nt = 0; nt < 2; nt++) {
                int col = h*16 + (nb3+nt)*4 + tg, r0 = mt3*16 + g;
                su[O_AH + r0*P_X + col]     = pk2(coh_[nt][0], coh_[nt][1]);
                su[O_AH + (r0+8)*P_X + col] = pk2(coh_[nt][2], coh_[nt][3]);
            }
        }
        // no closing barrier: parity buffers + SYNC-A/B ordering make next
        // head's epilogue writes safe vs this head's GEMM2/GEMM3 readers.
    }
    __syncthreads();    // AH complete before GEMM4

    // ---- GEMM4: out = Wout @ att  (A = Wh from L2, B = att hi) ----
    {
        float c4[2][8][4];
        #pragma unroll
        for (int m = 0; m < 2; m++)
            #pragma unroll
            for (int nt = 0; nt < 8; nt++)
                c4[m][nt][0]=c4[m][nt][1]=c4[m][nt][2]=c4[m][nt][3]=0.f;

        #pragma unroll 2
        for (int ks = 0; ks < 16; ks++) {
            u32 ah[2][4];
            #pragma unroll
            for (int m = 0; m < 2; m++) {
                uint4 vh4 = *(const uint4*)&WA4h[(ks*16 + (w*2+m))*128 + lane*4];
                ah[m][0]=vh4.x; ah[m][1]=vh4.y; ah[m][2]=vh4.z; ah[m][3]=vh4.w;
            }
            #pragma unroll
            for (int nt = 0; nt < 8; nt++) {
                u32 bh[2];
                ldBf(bh, su + O_AH, nt*8, ks*8, P_X, g, tg);
                #pragma unroll
                for (int m = 0; m < 2; m++) {
                    mma16(c4[m][nt], ah[m], bh);
                }
            }
        }
        // direct global stores: frag (m,nt) covers out rows o0,o0+8, pix nt*8+2tg..+1
        // addr(o,pix) = o*65536 + (pix>>3)*256 + (pix&7); pix>>3 = nt, pix&7 = 2tg
        float* ob = out + ((size_t)bb << 24) + (size_t)(wh*8)*256 + ww*8;
        #pragma unroll
        for (int m = 0; m < 2; m++) {
            int o0 = (w*2 + m)*16 + g;
            float b0v = sf[O_BOUT + o0], b1v = sf[O_BOUT + o0 + 8];
            #pragma unroll
            for (int nt = 0; nt < 8; nt++) {
                float2 v0 = make_float2(c4[m][nt][0] + b0v, c4[m][nt][1] + b0v);
                float2 v1 = make_float2(c4[m][nt][2] + b1v, c4[m][nt][3] + b1v);
                *(float2*)&ob[(size_t)o0*65536       + nt*256 + 2*tg] = v0;
                *(float2*)&ob[(size_t)(o0+8)*65536   + nt*256 + 2*tg] = v1;
            }
        }
    }
}

// ---------------- launch ----------------
extern "C" void kernel_launch(void* const* d_in, const int* in_sizes, int n_in,
                              void* d_out, int out_size)
{
    (void)in_sizes; (void)n_in; (void)out_size;
    const float* x     = (const float*)d_in[0];
    const float* g     = (const float*)d_in[1];
    const float* b     = (const float*)d_in[2];
    const float* w_qkv = (const float*)d_in[3];
    const float* w_out = (const float*)d_in[4];
    const float* b_out = (const float*)d_in[5];

    cudaFuncSetAttribute(attn_kernel, cudaFuncAttributeMaxDynamicSharedMemorySize, SMEM_BYTES);

    dpb_kernel<<<289, 64>>>(
        (const float*)d_in[6],  (const float*)d_in[7],
        (const float*)d_in[8],  (const float*)d_in[9],
        (const float*)d_in[10], (const float*)d_in[11],
        (const float*)d_in[12], (const float*)d_in[13],
        (const float*)d_in[14], (const float*)d_in[15],
        (const float*)d_in[16], (const float*)d_in[17],
        (const float*)d_in[18], (const float*)d_in[19]);
    conv_b1<<<1024, 64>>>(w_qkv);
    conv_a1v<<<256, 128>>>(w_qkv);
    conv_a4<<<256, 128>>>(w_out);
    attn_kernel<<<4096, 256, SMEM_BYTES>>>(x, g, b, b_out, (float*)d_out);
}